// round 1
// baseline (speedup 1.0000x reference)
#include <cuda_runtime.h>
#include <math.h>

#define Bn 2
#define Cn 8
#define Fn 256
#define Wn 512
#define Hn 8
#define HDn 32
#define En 4
#define NB (Bn*Cn*Fn*Wn)

// ---------------- scratch (device globals; no allocation allowed) ----------------
__device__ float g_h[NB];
__device__ float g_z[NB];
__device__ float g_lin[NB];
__device__ float g_q[NB];
__device__ float g_k[NB];
__device__ float g_v[NB];
__device__ float g_attn[NB];
__device__ float g_o[NB];
__device__ float g_t1[NB];
__device__ float g_ffn[Bn*Cn*En*Wn];

// ---------------- LayerNorm over features f (per b,c,w), per-channel affine ----------------
__global__ void ln_kernel(const float* __restrict__ X, const float* __restrict__ gam,
                          const float* __restrict__ bet, float* __restrict__ Y) {
    int w = blockIdx.x * 64 + threadIdx.x;
    int c = blockIdx.y, b = blockIdx.z;
    const float* xp = X + ((size_t)(b*Cn + c) * Fn) * Wn + w;
    float s = 0.f, s2 = 0.f;
#pragma unroll 4
    for (int f = 0; f < Fn; f++) {
        float v = xp[(size_t)f * Wn];
        s += v; s2 += v * v;
    }
    float m   = s * (1.0f / Fn);
    float var = s2 * (1.0f / Fn) - m * m;
    float inv = rsqrtf(var + 1e-5f);
    const float* gp = gam + c * Fn;
    const float* bp = bet + c * Fn;
    float* yp = Y + ((size_t)(b*Cn + c) * Fn) * Wn + w;
#pragma unroll 4
    for (int f = 0; f < Fn; f++) {
        yp[(size_t)f * Wn] = (xp[(size_t)f * Wn] - m) * inv * gp[f] + bp[f];
    }
}

// ---------------- per-channel GEMM: Y[bc] = W[c] (MxK) @ X[bc] (KxN), M=K=256, N=512 ----------------
template<bool ACC>
__global__ void __launch_bounds__(256) gemm_pc(const float* __restrict__ Wt,
                                               const float* __restrict__ Xin,
                                               float* __restrict__ Y) {
    __shared__ float As[64][17];
    __shared__ float Bs[16][64];
    int bc = blockIdx.z, c = bc % Cn;
    const float* A  = Wt  + (size_t)c  * Fn * Fn;   // (g,f) row-major, ld=Fn
    const float* Bm = Xin + (size_t)bc * Fn * Wn;   // (f,w) row-major, ld=Wn
    float*       Cm = Y   + (size_t)bc * Fn * Wn;
    int tx = threadIdx.x, ty = threadIdx.y;
    int tid = ty * 16 + tx;
    int m0 = tid >> 2, kq = (tid & 3) * 4;
    int kr = tid >> 4, nc = (tid & 15) * 4;
    int tileM = blockIdx.y * 64, tileN = blockIdx.x * 64;
    float acc[4][4] = {};
    for (int kt = 0; kt < Fn; kt += 16) {
        float4 av = *(const float4*)(A + (size_t)(tileM + m0) * Fn + kt + kq);
        As[m0][kq + 0] = av.x; As[m0][kq + 1] = av.y;
        As[m0][kq + 2] = av.z; As[m0][kq + 3] = av.w;
        *(float4*)&Bs[kr][nc] = *(const float4*)(Bm + (size_t)(kt + kr) * Wn + tileN + nc);
        __syncthreads();
#pragma unroll
        for (int k = 0; k < 16; k++) {
            float4 bv = *(const float4*)&Bs[k][tx * 4];
            float avv[4];
#pragma unroll
            for (int i = 0; i < 4; i++) avv[i] = As[ty * 4 + i][k];
#pragma unroll
            for (int i = 0; i < 4; i++) {
                acc[i][0] += avv[i] * bv.x;
                acc[i][1] += avv[i] * bv.y;
                acc[i][2] += avv[i] * bv.z;
                acc[i][3] += avv[i] * bv.w;
            }
        }
        __syncthreads();
    }
#pragma unroll
    for (int i = 0; i < 4; i++) {
        float* cp = Cm + (size_t)(tileM + ty * 4 + i) * Wn + tileN + tx * 4;
        float4 r = make_float4(acc[i][0], acc[i][1], acc[i][2], acc[i][3]);
        if (ACC) {
            float4 o = *(const float4*)cp;
            r.x += o.x; r.y += o.y; r.z += o.z; r.w += o.w;
        }
        *(float4*)cp = r;
    }
}

// ---------------- width-3 channel-mix conv + bias (+ optional interleaved RoPE) ----------------
// Input  Lin: (b,ci,f,w); Kc: (co,ci,3); Output Qout: head layout [(b*Cn+co)*Hn+h][n=w][d]
template<bool ROPE>
__global__ void conv_rope(const float* __restrict__ Lin, const float* __restrict__ Kc,
                          const float* __restrict__ bias, float* __restrict__ Qout) {
    __shared__ float ks[Cn * 3];
    int w  = blockIdx.x * 128 + threadIdx.x;
    int p  = blockIdx.y;            // feature-pair index 0..127  (f0=2p, f1=2p+1)
    int bz = blockIdx.z;            // b*Cn + co
    int co = bz % Cn;
    int b  = bz / Cn;
    if (threadIdx.x < Cn * 3) ks[threadIdx.x] = Kc[co * Cn * 3 + threadIdx.x];
    __syncthreads();
    int f0 = 2 * p;
    float acc0 = bias[co], acc1 = acc0;
#pragma unroll
    for (int ci = 0; ci < Cn; ci++) {
        const float* lp = Lin + ((size_t)(b*Cn + ci) * Fn + f0) * Wn;
        float k0 = ks[ci*3], k1 = ks[ci*3+1], k2 = ks[ci*3+2];
        float lm = (w > 0)      ? lp[w - 1] : 0.f;
        float lc = lp[w];
        float ln_ = (w < Wn-1)  ? lp[w + 1] : 0.f;
        acc0 += k0 * lm + k1 * lc + k2 * ln_;
        const float* lq = lp + Wn;
        lm  = (w > 0)     ? lq[w - 1] : 0.f;
        lc  = lq[w];
        ln_ = (w < Wn-1)  ? lq[w + 1] : 0.f;
        acc1 += k0 * lm + k1 * lc + k2 * ln_;
    }
    if (ROPE) {
        int j = p & 15;                                  // pair index within head dim
        float invf = exp10f(-0.25f * (float)j);          // 1/10000^(2j/32) = 10^(-j/4)
        float fr = (float)w * invf;
        float sn, cs;
        sincosf(fr, &sn, &cs);
        float o0 = acc0 * cs - acc1 * sn;
        float o1 = acc1 * cs + acc0 * sn;
        acc0 = o0; acc1 = o1;
    }
    int h  = p >> 4;
    int dj = (p & 15) * 2;
    float* qp = Qout + (((size_t)bz * Hn + h) * Wn + w) * HDn + dj;
    qp[0] = acc0;
    qp[1] = acc1;
}

// ---------------- attention: one block per head, one thread per query ----------------
// Q,K,V: [head][n][d] (head = (b*Cn+c)*Hn+h). Output written in (b,c,f,w) layout.
__global__ void __launch_bounds__(512) attn_kernel(const float* __restrict__ Q,
                                                   const float* __restrict__ Kt,
                                                   const float* __restrict__ Vt,
                                                   float* __restrict__ Out) {
    __shared__ float Ks[128][32];
    __shared__ float Vs[128][32];
    int head = blockIdx.x;
    const float* qp = Q  + ((size_t)head * Wn + threadIdx.x) * HDn;
    const float* kp = Kt + (size_t)head * Wn * HDn;
    const float* vp = Vt + (size_t)head * Wn * HDn;
    float4 q4[8];
#pragma unroll
    for (int i = 0; i < 8; i++) q4[i] = ((const float4*)qp)[i];
    float4 a4[8] = {};
    float mrun = -1e30f, l = 0.f;
    for (int t0 = 0; t0 < Wn; t0 += 128) {
        __syncthreads();
        const float4* kg = (const float4*)(kp + (size_t)t0 * HDn);
        const float4* vg = (const float4*)(vp + (size_t)t0 * HDn);
        float4* ksh = (float4*)&Ks[0][0];
        float4* vsh = (float4*)&Vs[0][0];
#pragma unroll
        for (int i = 0; i < 2; i++) {
            ksh[threadIdx.x + i * 512] = kg[threadIdx.x + i * 512];
            vsh[threadIdx.x + i * 512] = vg[threadIdx.x + i * 512];
        }
        __syncthreads();
        for (int mm = 0; mm < 128; mm++) {
            const float4* kr = (const float4*)Ks[mm];
            float s = 0.f;
#pragma unroll
            for (int dd = 0; dd < 8; dd++) {
                float4 kk = kr[dd];
                s += q4[dd].x * kk.x + q4[dd].y * kk.y + q4[dd].z * kk.z + q4[dd].w * kk.w;
            }
            s *= 0.0625f;   // / sqrt(F=256)
            if (s > mrun) {
                float corr = __expf(mrun - s);
                l *= corr;
#pragma unroll
                for (int dd = 0; dd < 8; dd++) {
                    a4[dd].x *= corr; a4[dd].y *= corr; a4[dd].z *= corr; a4[dd].w *= corr;
                }
                mrun = s;
            }
            float pp = __expf(s - mrun);
            l += pp;
            const float4* vr = (const float4*)Vs[mm];
#pragma unroll
            for (int dd = 0; dd < 8; dd++) {
                float4 vv = vr[dd];
                a4[dd].x += pp * vv.x; a4[dd].y += pp * vv.y;
                a4[dd].z += pp * vv.z; a4[dd].w += pp * vv.w;
            }
        }
    }
    float invl = 1.0f / l;
    int bc = head / Hn, hh = head % Hn;
    float* op = Out + ((size_t)bc * Fn + hh * HDn) * Wn + threadIdx.x;
#pragma unroll
    for (int dd = 0; dd < 8; dd++) {
        op[(size_t)(dd*4 + 0) * Wn] = a4[dd].x * invl;
        op[(size_t)(dd*4 + 1) * Wn] = a4[dd].y * invl;
        op[(size_t)(dd*4 + 2) * Wn] = a4[dd].z * invl;
        op[(size_t)(dd*4 + 3) * Wn] = a4[dd].w * invl;
    }
}

// ---------------- depthwise f-convs: za(sq_relu of k11) + zb(k7) ----------------
__global__ void frameconv_ab(const float* __restrict__ Z,
                             const float* __restrict__ k11, const float* __restrict__ b11,
                             const float* __restrict__ k7,  const float* __restrict__ b7,
                             float* __restrict__ Yo) {
    int idx = blockIdx.x * 256 + threadIdx.x;
    int w  = idx & (Wn - 1);
    int f  = (idx >> 9) & (Fn - 1);
    int bc = idx >> 17;
    int c  = bc & (Cn - 1);
    const float* zp = Z + (size_t)bc * Fn * Wn + w;
    float a = b11[c];
#pragma unroll
    for (int t = 0; t < 11; t++) {
        int ff = f - 5 + t;
        if (ff >= 0 && ff < Fn) a += zp[(size_t)ff * Wn] * k11[c * 11 + t];
    }
    a = fmaxf(a, 0.f); a = a * a;
    float bo = b7[c];
#pragma unroll
    for (int t = 0; t < 7; t++) {
        int ff = f - 3 + t;
        if (ff >= 0 && ff < Fn) bo += zp[(size_t)ff * Wn] * k7[c * 7 + t];
    }
    Yo[idx] = a + bo;
}

// ---------------- depthwise k7 conv + residual add into H ----------------
__global__ void frameconv2_add(const float* __restrict__ S,
                               const float* __restrict__ k7, const float* __restrict__ b7,
                               float* __restrict__ Hb) {
    int idx = blockIdx.x * 256 + threadIdx.x;
    int w  = idx & (Wn - 1);
    int f  = (idx >> 9) & (Fn - 1);
    int bc = idx >> 17;
    int c  = bc & (Cn - 1);
    const float* sp = S + (size_t)bc * Fn * Wn + w;
    float v = b7[c];
#pragma unroll
    for (int t = 0; t < 7; t++) {
        int ff = f - 3 + t;
        if (ff >= 0 && ff < Fn) v += sp[(size_t)ff * Wn] * k7[c * 7 + t];
    }
    Hb[idx] += v;
}

__global__ void add_xo(const float* __restrict__ X, const float* __restrict__ O,
                       float* __restrict__ Hb) {
    int idx = blockIdx.x * 256 + threadIdx.x;
    Hb[idx] = X[idx] + O[idx];
}

__global__ void add_inplace(float* __restrict__ Hb, const float* __restrict__ O) {
    int idx = blockIdx.x * 256 + threadIdx.x;
    Hb[idx] += O[idx];
}

// ---------------- FFN: t = sq_relu(z @ w3^T) (E=4), then h += t @ w4^T ----------------
__global__ void __launch_bounds__(512) ffn3(const float* __restrict__ Z,
                                            const float* __restrict__ w3,
                                            float* __restrict__ T) {
    __shared__ float ws[En * Fn];
    int bc = blockIdx.x;
    int c  = bc & (Cn - 1);
    for (int i = threadIdx.x; i < En * Fn; i += 512) ws[i] = w3[c * En * Fn + i];
    __syncthreads();
    const float* zp = Z + (size_t)bc * Fn * Wn + threadIdx.x;
    float acc[En] = {};
    for (int f = 0; f < Fn; f++) {
        float zv = zp[(size_t)f * Wn];
#pragma unroll
        for (int e = 0; e < En; e++) acc[e] += zv * ws[e * Fn + f];
    }
    float* tp = T + (size_t)bc * En * Wn + threadIdx.x;
#pragma unroll
    for (int e = 0; e < En; e++) {
        float v = fmaxf(acc[e], 0.f);
        tp[(size_t)e * Wn] = v * v;
    }
}

__global__ void ffn4_add(const float* __restrict__ T, const float* __restrict__ w4,
                         float* __restrict__ Hb) {
    int idx = blockIdx.x * 256 + threadIdx.x;
    int w  = idx & (Wn - 1);
    int f  = (idx >> 9) & (Fn - 1);
    int bc = idx >> 17;
    int c  = bc & (Cn - 1);
    const float* tp = T + (size_t)bc * En * Wn + w;
    const float* wp = w4 + ((size_t)c * Fn + f) * En;
    float v = tp[0] * wp[0] + tp[Wn] * wp[1] + tp[2 * Wn] * wp[2] + tp[3 * Wn] * wp[3];
    Hb[idx] += v;
}

// ---------------- final concat (x, h) along channels ----------------
__global__ void write_out(const float* __restrict__ X, const float* __restrict__ Hb,
                          float* __restrict__ O) {
    int idx = blockIdx.x * 256 + threadIdx.x;
    int b = idx / (Cn * Fn * Wn);
    int r = idx - b * (Cn * Fn * Wn);
    O[(size_t)b * 2 * Cn * Fn * Wn + r] = X[idx];
    O[(size_t)b * 2 * Cn * Fn * Wn + Cn * Fn * Wn + r] = Hb[idx];
}

// =====================================================================================

extern "C" void kernel_launch(void* const* d_in, const int* in_sizes, int n_in,
                              void* d_out, int out_size) {
    const float* x     = (const float*)d_in[0];
    const float* skip  = (const float*)d_in[1];
    const float* Wq    = (const float*)d_in[2];
    const float* Kq    = (const float*)d_in[3];
    const float* bq    = (const float*)d_in[4];
    const float* Wk    = (const float*)d_in[5];
    const float* Kk    = (const float*)d_in[6];
    const float* bk    = (const float*)d_in[7];
    const float* Wv    = (const float*)d_in[8];
    const float* Kv    = (const float*)d_in[9];
    const float* bv    = (const float*)d_in[10];
    const float* Wo    = (const float*)d_in[11];
    const float* ng    = (const float*)d_in[12];
    const float* nbet  = (const float*)d_in[13];
    const float* c1a_w = (const float*)d_in[14];
    const float* c1a_b = (const float*)d_in[15];
    const float* c1b_w = (const float*)d_in[16];
    const float* c1b_b = (const float*)d_in[17];
    const float* c2_w  = (const float*)d_in[18];
    const float* c2_b  = (const float*)d_in[19];
    const float* w3    = (const float*)d_in[20];
    const float* w4    = (const float*)d_in[21];
    float* out = (float*)d_out;

    float *hB, *zB, *linB, *qB, *kB, *vB, *attB, *oB, *t1B, *ffnB;
    cudaGetSymbolAddress((void**)&hB,   g_h);
    cudaGetSymbolAddress((void**)&zB,   g_z);
    cudaGetSymbolAddress((void**)&linB, g_lin);
    cudaGetSymbolAddress((void**)&qB,   g_q);
    cudaGetSymbolAddress((void**)&kB,   g_k);
    cudaGetSymbolAddress((void**)&vB,   g_v);
    cudaGetSymbolAddress((void**)&attB, g_attn);
    cudaGetSymbolAddress((void**)&oB,   g_o);
    cudaGetSymbolAddress((void**)&t1B,  g_t1);
    cudaGetSymbolAddress((void**)&ffnB, g_ffn);

    const dim3 gGemm(Wn / 64, Fn / 64, Bn * Cn);
    const dim3 bGemm(16, 16);
    const dim3 gConv(Wn / 128, Fn / 2, Bn * Cn);
    const int  nElemBlocks = NB / 256;

    auto run_ln = [&](const float* X, int gi, float* Yb) {
        ln_kernel<<<dim3(Wn / 64, Cn, Bn), 64>>>(X, ng + gi * Cn * Fn, nbet + gi * Cn * Fn, Yb);
    };

    auto run_attn = [&](int i, const float* t, const float* m, bool accO) {
        gemm_pc<false><<<gGemm, bGemm>>>(Wq + (size_t)i * Cn * Fn * Fn, t, linB);
        conv_rope<true><<<gConv, 128>>>(linB, Kq + (size_t)i * Cn * Cn * 3, bq + i * Cn, qB);
        gemm_pc<false><<<gGemm, bGemm>>>(Wk + (size_t)i * Cn * Fn * Fn, m, linB);
        conv_rope<true><<<gConv, 128>>>(linB, Kk + (size_t)i * Cn * Cn * 3, bk + i * Cn, kB);
        gemm_pc<false><<<gGemm, bGemm>>>(Wv + (size_t)i * Cn * Fn * Fn, m, linB);
        conv_rope<false><<<gConv, 128>>>(linB, Kv + (size_t)i * Cn * Cn * 3, bv + i * Cn, vB);
        attn_kernel<<<Bn * Cn * Hn, 512>>>(qB, kB, vB, attB);
        if (accO) gemm_pc<true><<<gGemm, bGemm>>>(Wo + (size_t)i * Cn * Fn * Fn, attB, oB);
        else      gemm_pc<false><<<gGemm, bGemm>>>(Wo + (size_t)i * Cn * Fn * Fn, attB, oB);
    };

    // h = x; z = LN0(h); h = h + att0(z,z) + att1(z,skip)
    run_ln(x, 0, zB);
    run_attn(0, zB, zB, false);
    run_attn(1, zB, skip, true);
    add_xo<<<nElemBlocks, 256>>>(x, oB, hB);

    // conv block
    run_ln(hB, 1, zB);
    frameconv_ab<<<nElemBlocks, 256>>>(zB, c1a_w, c1a_b, c1b_w, c1b_b, t1B);
    run_ln(t1B, 2, zB);
    frameconv2_add<<<nElemBlocks, 256>>>(zB, c2_w, c2_b, hB);

    // h = h + att2(LN3(h), same)
    run_ln(hB, 3, zB);
    run_attn(2, zB, zB, false);
    add_inplace<<<nElemBlocks, 256>>>(hB, oB);

    // h = h + att3(LN4(h), skip)
    run_ln(hB, 4, zB);
    run_attn(3, zB, skip, false);
    add_inplace<<<nElemBlocks, 256>>>(hB, oB);

    // FFN
    run_ln(hB, 5, zB);
    ffn3<<<Bn * Cn, 512>>>(zB, w3, ffnB);
    ffn4_add<<<nElemBlocks, 256>>>(ffnB, w4, hB);

    // concat(x, h)
    write_out<<<nElemBlocks, 256>>>(x, hB, out);
}

// round 3
// speedup vs baseline: 1.1808x; 1.1808x over previous
#include <cuda_runtime.h>
#include <cuda_bf16.h>
#include <math.h>
#include <stdint.h>

#define Bn 2
#define Cn 8
#define Fn 256
#define Wn 512
#define Hn 8
#define HDn 32
#define En 4
#define NB (Bn*Cn*Fn*Wn)
#define WOFF (Cn*Fn*Fn)

// ======================= warp-MMA helpers (baseline PTX, sm_80+) =======================
__device__ __forceinline__ uint32_t smem_u32(const void* p) {
    uint32_t a;
    asm("{ .reg .u64 t; cvta.to.shared.u64 t, %1; cvt.u32.u64 %0, t; }" : "=r"(a) : "l"(p));
    return a;
}
__device__ __forceinline__ void ldm_x4(uint32_t& r0, uint32_t& r1, uint32_t& r2, uint32_t& r3,
                                       uint32_t addr) {
    asm volatile("ldmatrix.sync.aligned.m8n8.x4.shared.b16 {%0,%1,%2,%3}, [%4];"
                 : "=r"(r0), "=r"(r1), "=r"(r2), "=r"(r3) : "r"(addr));
}
__device__ __forceinline__ void mma_bf16(float* d, const uint32_t* a, const uint32_t* b) {
    asm volatile("mma.sync.aligned.m16n8k16.row.col.f32.bf16.bf16.f32 "
                 "{%0,%1,%2,%3}, {%4,%5,%6,%7}, {%8,%9}, {%0,%1,%2,%3};"
                 : "+f"(d[0]), "+f"(d[1]), "+f"(d[2]), "+f"(d[3])
                 : "r"(a[0]), "r"(a[1]), "r"(a[2]), "r"(a[3]), "r"(b[0]), "r"(b[1]));
}

__device__ __forceinline__ uint32_t pack_split(float a, float b, uint32_t& lo) {
    __nv_bfloat16 ha = __float2bfloat16(a), hb = __float2bfloat16(b);
    __nv_bfloat16 la = __float2bfloat16(a - __bfloat162float(ha));
    __nv_bfloat16 lb = __float2bfloat16(b - __bfloat162float(hb));
    lo = (uint32_t)__bfloat16_as_ushort(la) | ((uint32_t)__bfloat16_as_ushort(lb) << 16);
    return (uint32_t)__bfloat16_as_ushort(ha) | ((uint32_t)__bfloat16_as_ushort(hb) << 16);
}

// ======================= scratch (device globals) =======================
__device__ float g_h[NB];
__device__ float g_z[NB];
__device__ float g_lin[NB];
__device__ float g_q[NB];
__device__ float g_k[NB];
__device__ float g_v[NB];
__device__ float g_o[NB];
__device__ float g_t1[NB];
__device__ float g_ffn[Bn*Cn*En*Wn];
__device__ __nv_bfloat16 g_zTh[Bn*Cn*Wn*Fn];
__device__ __nv_bfloat16 g_zTl[Bn*Cn*Wn*Fn];
__device__ __nv_bfloat16 g_skTh[Bn*Cn*Wn*Fn];
__device__ __nv_bfloat16 g_skTl[Bn*Cn*Wn*Fn];
__device__ __nv_bfloat16 g_atTh[Bn*Cn*Wn*Fn];
__device__ __nv_bfloat16 g_atTl[Bn*Cn*Wn*Fn];
__device__ __nv_bfloat16 g_WqH[4*WOFF]; __device__ __nv_bfloat16 g_WqL[4*WOFF];
__device__ __nv_bfloat16 g_WkH[4*WOFF]; __device__ __nv_bfloat16 g_WkL[4*WOFF];
__device__ __nv_bfloat16 g_WvH[4*WOFF]; __device__ __nv_bfloat16 g_WvL[4*WOFF];
__device__ __nv_bfloat16 g_WoH[4*WOFF]; __device__ __nv_bfloat16 g_WoL[4*WOFF];

// ======================= fp32 LayerNorm (conv/FFN path) =======================
__global__ void ln_kernel(const float* __restrict__ X, const float* __restrict__ gam,
                          const float* __restrict__ bet, float* __restrict__ Y) {
    int w = blockIdx.x * 64 + threadIdx.x;
    int c = blockIdx.y, b = blockIdx.z;
    const float* xp = X + ((size_t)(b*Cn + c) * Fn) * Wn + w;
    float s = 0.f, s2 = 0.f;
#pragma unroll 4
    for (int f = 0; f < Fn; f++) { float v = xp[(size_t)f * Wn]; s += v; s2 += v * v; }
    float m = s * (1.0f / Fn);
    float inv = rsqrtf(s2 * (1.0f / Fn) - m * m + 1e-5f);
    const float* gp = gam + c * Fn;
    const float* bp = bet + c * Fn;
    float* yp = Y + ((size_t)(b*Cn + c) * Fn) * Wn + w;
#pragma unroll 4
    for (int f = 0; f < Fn; f++)
        yp[(size_t)f * Wn] = (xp[(size_t)f * Wn] - m) * inv * gp[f] + bp[f];
}

// ============ LayerNorm -> transposed bf16 hi/lo ([bc][w][f]) for GEMM B ============
__global__ void ln_t_kernel(const float* __restrict__ X, const float* __restrict__ gam,
                            const float* __restrict__ bet,
                            __nv_bfloat16* __restrict__ Zh, __nv_bfloat16* __restrict__ Zl) {
    int w = blockIdx.x * 64 + threadIdx.x;
    int c = blockIdx.y, b = blockIdx.z;
    int bc = b * Cn + c;
    const float* xp = X + ((size_t)bc * Fn) * Wn + w;
    float s = 0.f, s2 = 0.f;
#pragma unroll 4
    for (int f = 0; f < Fn; f++) { float v = xp[(size_t)f * Wn]; s += v; s2 += v * v; }
    float m = s * (1.0f / Fn);
    float inv = rsqrtf(s2 * (1.0f / Fn) - m * m + 1e-5f);
    const float* gp = gam + c * Fn;
    const float* bp = bet + c * Fn;
    __nv_bfloat16* th = Zh + ((size_t)bc * Wn + w) * Fn;
    __nv_bfloat16* tl = Zl + ((size_t)bc * Wn + w) * Fn;
    for (int f0 = 0; f0 < Fn; f0 += 8) {
        uint32_t ph[4], pl[4];
#pragma unroll
        for (int j = 0; j < 4; j++) {
            int f = f0 + 2 * j;
            float v0 = (xp[(size_t)f * Wn]     - m) * inv * gp[f]   + bp[f];
            float v1 = (xp[(size_t)(f+1) * Wn] - m) * inv * gp[f+1] + bp[f+1];
            ph[j] = pack_split(v0, v1, pl[j]);
        }
        *(uint4*)(th + f0) = make_uint4(ph[0], ph[1], ph[2], ph[3]);
        *(uint4*)(tl + f0) = make_uint4(pl[0], pl[1], pl[2], pl[3]);
    }
}

// ============ transpose + split: (b,c,f,w) fp32 -> [bc][w][f] bf16 hi/lo ============
__global__ void tsplit_kernel(const float* __restrict__ X,
                              __nv_bfloat16* __restrict__ Th, __nv_bfloat16* __restrict__ Tl) {
    __shared__ float t[32][33];
    int bc = blockIdx.z;
    int w0 = blockIdx.x * 32, f0 = blockIdx.y * 32;
    const float* xp = X + ((size_t)bc * Fn + f0) * Wn + w0;
#pragma unroll
    for (int i = 0; i < 4; i++) {
        int fr = threadIdx.y + i * 8;
        t[fr][threadIdx.x] = xp[(size_t)fr * Wn + threadIdx.x];
    }
    __syncthreads();
#pragma unroll
    for (int i = 0; i < 4; i++) {
        int wr = threadIdx.y + i * 8;
        float v = t[threadIdx.x][wr];
        __nv_bfloat16 h = __float2bfloat16(v);
        __nv_bfloat16 l = __float2bfloat16(v - __bfloat162float(h));
        size_t idx = ((size_t)bc * Wn + w0 + wr) * Fn + f0 + threadIdx.x;
        Th[idx] = h; Tl[idx] = l;
    }
}

// ============ weight split: fp32 -> bf16 hi/lo (K-major layout preserved) ============
__global__ void wsplit_kernel(const float* __restrict__ X,
                              __nv_bfloat16* __restrict__ H, __nv_bfloat16* __restrict__ L) {
    int i = (blockIdx.x * 256 + threadIdx.x) * 4;
    float4 v = *(const float4*)(X + i);
    uint32_t l0, l1;
    uint32_t h0 = pack_split(v.x, v.y, l0);
    uint32_t h1 = pack_split(v.z, v.w, l1);
    *(uint2*)((unsigned short*)H + i) = make_uint2(h0, h1);
    *(uint2*)((unsigned short*)L + i) = make_uint2(l0, l1);
}

// ======================= mma.sync 3xBF16 per-channel GEMM =======================
// Y[bc](256x512) = W[c](256x256, K-major rows) @ X[bc]^T, X given as [bc][w][f]
// CTA tile 128x128, K-chunk 64 in smem; 8 warps, warp tile 64x32.
#define KCn 64
#define LDT 72
#define TELEM (128 * LDT)

template<bool ACC>
__global__ void __launch_bounds__(256) gemm_mma(const __nv_bfloat16* __restrict__ AhG,
                                                const __nv_bfloat16* __restrict__ AlG,
                                                const __nv_bfloat16* __restrict__ BhG,
                                                const __nv_bfloat16* __restrict__ BlG,
                                                float* __restrict__ Y) {
    extern __shared__ __nv_bfloat16 sm[];
    __nv_bfloat16* sAh = sm;
    __nv_bfloat16* sAl = sm + TELEM;
    __nv_bfloat16* sBh = sm + 2 * TELEM;
    __nv_bfloat16* sBl = sm + 3 * TELEM;
    int tid = threadIdx.x, lane = tid & 31, wid = tid >> 5;
    int wm = wid >> 2, wn = wid & 3;
    int bc = blockIdx.z, c = bc & (Cn - 1);
    int tileM = blockIdx.y * 128, tileN = blockIdx.x * 128;
    const __nv_bfloat16* gAh = AhG + ((size_t)c * Fn + tileM) * Fn;
    const __nv_bfloat16* gAl = AlG + ((size_t)c * Fn + tileM) * Fn;
    const __nv_bfloat16* gBh = BhG + ((size_t)bc * Wn + tileN) * Fn;
    const __nv_bfloat16* gBl = BlG + ((size_t)bc * Wn + tileN) * Fn;

    float acc[4][4][4] = {};
    int lrow = tid >> 1;            // 0..127
    int lq   = (tid & 1) * 4;       // uint4 index base within row

    uint32_t sb = smem_u32(sm);
    int grp = lane >> 3, lr = lane & 7;
    // ldmatrix base offsets (elements) for this lane
    int aRow = wm * 64 + (grp & 1) * 8 + lr;      // + mi*16
    int aCol = (grp >> 1) * 8;                    // + k0
    int bRow = wn * 32 + (grp >> 1) * 8 + lr;     // + nb*16
    int bCol = (grp & 1) * 8;                     // + k0

    for (int kc = 0; kc < 4; kc++) {
        if (kc) __syncthreads();
        const uint4* pa = (const uint4*)(gAh + (size_t)lrow * Fn + kc * KCn);
        const uint4* pb = (const uint4*)(gAl + (size_t)lrow * Fn + kc * KCn);
        const uint4* pc = (const uint4*)(gBh + (size_t)lrow * Fn + kc * KCn);
        const uint4* pd = (const uint4*)(gBl + (size_t)lrow * Fn + kc * KCn);
        uint4* qa = (uint4*)(sAh + lrow * LDT);
        uint4* qb = (uint4*)(sAl + lrow * LDT);
        uint4* qc = (uint4*)(sBh + lrow * LDT);
        uint4* qd = (uint4*)(sBl + lrow * LDT);
#pragma unroll
        for (int j = 0; j < 4; j++) {
            qa[lq + j] = pa[lq + j];
            qb[lq + j] = pb[lq + j];
            qc[lq + j] = pc[lq + j];
            qd[lq + j] = pd[lq + j];
        }
        __syncthreads();
#pragma unroll
        for (int ks = 0; ks < 4; ks++) {
            int k0 = ks * 16;
            uint32_t ah[4][4], al[4][4], bh[2][4], bl[2][4];
#pragma unroll
            for (int mi = 0; mi < 4; mi++) {
                uint32_t off = ((aRow + mi * 16) * LDT + aCol + k0) * 2;
                ldm_x4(ah[mi][0], ah[mi][1], ah[mi][2], ah[mi][3], sb + off);
                ldm_x4(al[mi][0], al[mi][1], al[mi][2], al[mi][3], sb + TELEM * 2 + off);
            }
#pragma unroll
            for (int nb = 0; nb < 2; nb++) {
                uint32_t off = ((bRow + nb * 16) * LDT + bCol + k0) * 2;
                ldm_x4(bh[nb][0], bh[nb][1], bh[nb][2], bh[nb][3], sb + TELEM * 4 + off);
                ldm_x4(bl[nb][0], bl[nb][1], bl[nb][2], bl[nb][3], sb + TELEM * 6 + off);
            }
#pragma unroll
            for (int mi = 0; mi < 4; mi++) {
#pragma unroll
                for (int nb = 0; nb < 2; nb++) {
                    mma_bf16(acc[mi][2*nb],   ah[mi], &bh[nb][0]);
                    mma_bf16(acc[mi][2*nb+1], ah[mi], &bh[nb][2]);
                    mma_bf16(acc[mi][2*nb],   ah[mi], &bl[nb][0]);
                    mma_bf16(acc[mi][2*nb+1], ah[mi], &bl[nb][2]);
                    mma_bf16(acc[mi][2*nb],   al[mi], &bh[nb][0]);
                    mma_bf16(acc[mi][2*nb+1], al[mi], &bh[nb][2]);
                }
            }
        }
    }

#pragma unroll
    for (int mi = 0; mi < 4; mi++) {
        int row = tileM + wm * 64 + mi * 16 + (lane >> 2);
#pragma unroll
        for (int ni = 0; ni < 4; ni++) {
            int col = tileN + wn * 32 + ni * 8 + (lane & 3) * 2;
            float* p0 = Y + ((size_t)bc * Fn + row) * Wn + col;
            float* p1 = p0 + 8 * Wn;
            float2 v0 = make_float2(acc[mi][ni][0], acc[mi][ni][1]);
            float2 v1 = make_float2(acc[mi][ni][2], acc[mi][ni][3]);
            if (ACC) {
                float2 o0 = *(const float2*)p0, o1 = *(const float2*)p1;
                v0.x += o0.x; v0.y += o0.y; v1.x += o1.x; v1.y += o1.y;
            }
            *(float2*)p0 = v0;
            *(float2*)p1 = v1;
        }
    }
}

// ======================= conv3 + bias (+ RoPE) -> head layout =======================
template<bool ROPE>
__global__ void conv_rope(const float* __restrict__ Lin, const float* __restrict__ Kc,
                          const float* __restrict__ bias, float* __restrict__ Qout) {
    __shared__ float ks[Cn * 3];
    int w  = blockIdx.x * 128 + threadIdx.x;
    int p  = blockIdx.y;
    int bz = blockIdx.z;
    int co = bz % Cn;
    int b  = bz / Cn;
    if (threadIdx.x < Cn * 3) ks[threadIdx.x] = Kc[co * Cn * 3 + threadIdx.x];
    __syncthreads();
    int f0 = 2 * p;
    float acc0 = bias[co], acc1 = acc0;
#pragma unroll
    for (int ci = 0; ci < Cn; ci++) {
        const float* lp = Lin + ((size_t)(b*Cn + ci) * Fn + f0) * Wn;
        float k0 = ks[ci*3], k1 = ks[ci*3+1], k2 = ks[ci*3+2];
        float lm = (w > 0)     ? lp[w - 1] : 0.f;
        float lc = lp[w];
        float ln_ = (w < Wn-1) ? lp[w + 1] : 0.f;
        acc0 += k0 * lm + k1 * lc + k2 * ln_;
        const float* lq = lp + Wn;
        lm  = (w > 0)     ? lq[w - 1] : 0.f;
        lc  = lq[w];
        ln_ = (w < Wn-1)  ? lq[w + 1] : 0.f;
        acc1 += k0 * lm + k1 * lc + k2 * ln_;
    }
    if (ROPE) {
        int j = p & 15;
        float invf = exp10f(-0.25f * (float)j);
        float fr = (float)w * invf;
        float sn, cs;
        sincosf(fr, &sn, &cs);
        float o0 = acc0 * cs - acc1 * sn;
        float o1 = acc1 * cs + acc0 * sn;
        acc0 = o0; acc1 = o1;
    }
    int h  = p >> 4;
    int dj = (p & 15) * 2;
    float* qp = Qout + (((size_t)bz * Hn + h) * Wn + w) * HDn + dj;
    qp[0] = acc0;
    qp[1] = acc1;
}

// ======================= attention (flash-style, 1 thread/query) =======================
__global__ void __launch_bounds__(512) attn_kernel(const float* __restrict__ Q,
                                                   const float* __restrict__ Kt,
                                                   const float* __restrict__ Vt,
                                                   __nv_bfloat16* __restrict__ AttH,
                                                   __nv_bfloat16* __restrict__ AttL) {
    __shared__ float Ks[128][32];
    __shared__ float Vs[128][32];
    int head = blockIdx.x;
    const float* qp = Q  + ((size_t)head * Wn + threadIdx.x) * HDn;
    const float* kp = Kt + (size_t)head * Wn * HDn;
    const float* vp = Vt + (size_t)head * Wn * HDn;
    float4 q4[8];
#pragma unroll
    for (int i = 0; i < 8; i++) q4[i] = ((const float4*)qp)[i];
    float4 a4[8] = {};
    float mrun = -1e30f, l = 0.f;
    for (int t0 = 0; t0 < Wn; t0 += 128) {
        __syncthreads();
        const float4* kg = (const float4*)(kp + (size_t)t0 * HDn);
        const float4* vg = (const float4*)(vp + (size_t)t0 * HDn);
        float4* ksh = (float4*)&Ks[0][0];
        float4* vsh = (float4*)&Vs[0][0];
#pragma unroll
        for (int i = 0; i < 2; i++) {
            ksh[threadIdx.x + i * 512] = kg[threadIdx.x + i * 512];
            vsh[threadIdx.x + i * 512] = vg[threadIdx.x + i * 512];
        }
        __syncthreads();
        for (int mm = 0; mm < 128; mm++) {
            const float4* kr = (const float4*)Ks[mm];
            float s = 0.f;
#pragma unroll
            for (int dd = 0; dd < 8; dd++) {
                float4 kk = kr[dd];
                s += q4[dd].x * kk.x + q4[dd].y * kk.y + q4[dd].z * kk.z + q4[dd].w * kk.w;
            }
            s *= 0.0625f;
            if (s > mrun) {
                float corr = __expf(mrun - s);
                l *= corr;
#pragma unroll
                for (int dd = 0; dd < 8; dd++) {
                    a4[dd].x *= corr; a4[dd].y *= corr; a4[dd].z *= corr; a4[dd].w *= corr;
                }
                mrun = s;
            }
            float pp = __expf(s - mrun);
            l += pp;
            const float4* vr = (const float4*)Vs[mm];
#pragma unroll
            for (int dd = 0; dd < 8; dd++) {
                float4 vv = vr[dd];
                a4[dd].x += pp * vv.x; a4[dd].y += pp * vv.y;
                a4[dd].z += pp * vv.z; a4[dd].w += pp * vv.w;
            }
        }
    }
    float invl = 1.0f / l;
    int bc = head / Hn, hh = head % Hn;
    __nv_bfloat16* oh = AttH + ((size_t)bc * Wn + threadIdx.x) * Fn + hh * HDn;
    __nv_bfloat16* ol = AttL + ((size_t)bc * Wn + threadIdx.x) * Fn + hh * HDn;
#pragma unroll
    for (int g = 0; g < 4; g++) {
        float4 u = a4[2*g], vv = a4[2*g+1];
        uint32_t ph[4], pl[4];
        ph[0] = pack_split(u.x * invl,  u.y * invl,  pl[0]);
        ph[1] = pack_split(u.z * invl,  u.w * invl,  pl[1]);
        ph[2] = pack_split(vv.x * invl, vv.y * invl, pl[2]);
        ph[3] = pack_split(vv.z * invl, vv.w * invl, pl[3]);
        *(uint4*)(oh + g * 8) = make_uint4(ph[0], ph[1], ph[2], ph[3]);
        *(uint4*)(ol + g * 8) = make_uint4(pl[0], pl[1], pl[2], pl[3]);
    }
}

// ======================= depthwise convs / FFN / elementwise =======================
__global__ void frameconv_ab(const float* __restrict__ Z,
                             const float* __restrict__ k11, const float* __restrict__ b11,
                             const float* __restrict__ k7,  const float* __restrict__ b7,
                             float* __restrict__ Yo) {
    int idx = blockIdx.x * 256 + threadIdx.x;
    int w  = idx & (Wn - 1);
    int f  = (idx >> 9) & (Fn - 1);
    int bc = idx >> 17;
    int c  = bc & (Cn - 1);
    const float* zp = Z + (size_t)bc * Fn * Wn + w;
    float a = b11[c];
#pragma unroll
    for (int t = 0; t < 11; t++) {
        int ff = f - 5 + t;
        if (ff >= 0 && ff < Fn) a += zp[(size_t)ff * Wn] * k11[c * 11 + t];
    }
    a = fmaxf(a, 0.f); a = a * a;
    float bo = b7[c];
#pragma unroll
    for (int t = 0; t < 7; t++) {
        int ff = f - 3 + t;
        if (ff >= 0 && ff < Fn) bo += zp[(size_t)ff * Wn] * k7[c * 7 + t];
    }
    Yo[idx] = a + bo;
}

__global__ void frameconv2_add(const float* __restrict__ S,
                               const float* __restrict__ k7, const float* __restrict__ b7,
                               float* __restrict__ Hb) {
    int idx = blockIdx.x * 256 + threadIdx.x;
    int w  = idx & (Wn - 1);
    int f  = (idx >> 9) & (Fn - 1);
    int bc = idx >> 17;
    int c  = bc & (Cn - 1);
    const float* sp = S + (size_t)bc * Fn * Wn + w;
    float v = b7[c];
#pragma unroll
    for (int t = 0; t < 7; t++) {
        int ff = f - 3 + t;
        if (ff >= 0 && ff < Fn) v += sp[(size_t)ff * Wn] * k7[c * 7 + t];
    }
    Hb[idx] += v;
}

__global__ void add_xo(const float* __restrict__ X, const float* __restrict__ O,
                       float* __restrict__ Hb) {
    int idx = blockIdx.x * 256 + threadIdx.x;
    Hb[idx] = X[idx] + O[idx];
}

__global__ void add_inplace(float* __restrict__ Hb, const float* __restrict__ O) {
    int idx = blockIdx.x * 256 + threadIdx.x;
    Hb[idx] += O[idx];
}

__global__ void __launch_bounds__(512) ffn3(const float* __restrict__ Z,
                                            const float* __restrict__ w3,
                                            float* __restrict__ T) {
    __shared__ float ws[En * Fn];
    int bc = blockIdx.x;
    int c  = bc & (Cn - 1);
    for (int i = threadIdx.x; i < En * Fn; i += 512) ws[i] = w3[c * En * Fn + i];
    __syncthreads();
    const float* zp = Z + (size_t)bc * Fn * Wn + threadIdx.x;
    float acc[En] = {};
    for (int f = 0; f < Fn; f++) {
        float zv = zp[(size_t)f * Wn];
#pragma unroll
        for (int e = 0; e < En; e++) acc[e] += zv * ws[e * Fn + f];
    }
    float* tp = T + (size_t)bc * En * Wn + threadIdx.x;
#pragma unroll
    for (int e = 0; e < En; e++) {
        float v = fmaxf(acc[e], 0.f);
        tp[(size_t)e * Wn] = v * v;
    }
}

__global__ void ffn4_add(const float* __restrict__ T, const float* __restrict__ w4,
                         float* __restrict__ Hb) {
    int idx = blockIdx.x * 256 + threadIdx.x;
    int w  = idx & (Wn - 1);
    int f  = (idx >> 9) & (Fn - 1);
    int bc = idx >> 17;
    int c  = bc & (Cn - 1);
    const float* tp = T + (size_t)bc * En * Wn + w;
    const float* wp = w4 + ((size_t)c * Fn + f) * En;
    float v = tp[0] * wp[0] + tp[Wn] * wp[1] + tp[2 * Wn] * wp[2] + tp[3 * Wn] * wp[3];
    Hb[idx] += v;
}

__global__ void write_out(const float* __restrict__ X, const float* __restrict__ Hb,
                          float* __restrict__ O) {
    int idx = blockIdx.x * 256 + threadIdx.x;
    int b = idx / (Cn * Fn * Wn);
    int r = idx - b * (Cn * Fn * Wn);
    O[(size_t)b * 2 * Cn * Fn * Wn + r] = X[idx];
    O[(size_t)b * 2 * Cn * Fn * Wn + Cn * Fn * Wn + r] = Hb[idx];
}

// =====================================================================================

extern "C" void kernel_launch(void* const* d_in, const int* in_sizes, int n_in,
                              void* d_out, int out_size) {
    const float* x     = (const float*)d_in[0];
    const float* skip  = (const float*)d_in[1];
    const float* Wq    = (const float*)d_in[2];
    const float* Kq    = (const float*)d_in[3];
    const float* bq    = (const float*)d_in[4];
    const float* Wk    = (const float*)d_in[5];
    const float* Kk    = (const float*)d_in[6];
    const float* bk    = (const float*)d_in[7];
    const float* Wv    = (const float*)d_in[8];
    const float* Kv    = (const float*)d_in[9];
    const float* bv    = (const float*)d_in[10];
    const float* Wo    = (const float*)d_in[11];
    const float* ng    = (const float*)d_in[12];
    const float* nbet  = (const float*)d_in[13];
    const float* c1a_w = (const float*)d_in[14];
    const float* c1a_b = (const float*)d_in[15];
    const float* c1b_w = (const float*)d_in[16];
    const float* c1b_b = (const float*)d_in[17];
    const float* c2_w  = (const float*)d_in[18];
    const float* c2_b  = (const float*)d_in[19];
    const float* w3    = (const float*)d_in[20];
    const float* w4    = (const float*)d_in[21];
    float* out = (float*)d_out;

    float *hB, *zB, *linB, *qB, *kB, *vB, *oB, *t1B, *ffnB;
    cudaGetSymbolAddress((void**)&hB,   g_h);
    cudaGetSymbolAddress((void**)&zB,   g_z);
    cudaGetSymbolAddress((void**)&linB, g_lin);
    cudaGetSymbolAddress((void**)&qB,   g_q);
    cudaGetSymbolAddress((void**)&kB,   g_k);
    cudaGetSymbolAddress((void**)&vB,   g_v);
    cudaGetSymbolAddress((void**)&oB,   g_o);
    cudaGetSymbolAddress((void**)&t1B,  g_t1);
    cudaGetSymbolAddress((void**)&ffnB, g_ffn);
    __nv_bfloat16 *zTh, *zTl, *skTh, *skTl, *atTh, *atTl;
    __nv_bfloat16 *WqH, *WqL, *WkH, *WkL, *WvH, *WvL, *WoH, *WoL;
    cudaGetSymbolAddress((void**)&zTh,  g_zTh);  cudaGetSymbolAddress((void**)&zTl,  g_zTl);
    cudaGetSymbolAddress((void**)&skTh, g_skTh); cudaGetSymbolAddress((void**)&skTl, g_skTl);
    cudaGetSymbolAddress((void**)&atTh, g_atTh); cudaGetSymbolAddress((void**)&atTl, g_atTl);
    cudaGetSymbolAddress((void**)&WqH, g_WqH); cudaGetSymbolAddress((void**)&WqL, g_WqL);
    cudaGetSymbolAddress((void**)&WkH, g_WkH); cudaGetSymbolAddress((void**)&WkL, g_WkL);
    cudaGetSymbolAddress((void**)&WvH, g_WvH); cudaGetSymbolAddress((void**)&WvL, g_WvL);
    cudaGetSymbolAddress((void**)&WoH, g_WoH); cudaGetSymbolAddress((void**)&WoL, g_WoL);

    const int GSM = 4 * TELEM * 2;   // 73728 bytes
    cudaFuncSetAttribute(gemm_mma<false>, cudaFuncAttributeMaxDynamicSharedMemorySize, GSM);
    cudaFuncSetAttribute(gemm_mma<true>,  cudaFuncAttributeMaxDynamicSharedMemorySize, GSM);

    const dim3 gGemm(Wn / 128, Fn / 128, Bn * Cn);   // (4, 2, 16)
    const dim3 gConv(Wn / 128, Fn / 2, Bn * Cn);
    const int  nElemBlocks = NB / 256;
    const int  wBlocks = (4 * WOFF) / 1024;

    // one-time conversions
    wsplit_kernel<<<wBlocks, 256>>>(Wq, WqH, WqL);
    wsplit_kernel<<<wBlocks, 256>>>(Wk, WkH, WkL);
    wsplit_kernel<<<wBlocks, 256>>>(Wv, WvH, WvL);
    wsplit_kernel<<<wBlocks, 256>>>(Wo, WoH, WoL);
    tsplit_kernel<<<dim3(Wn/32, Fn/32, Bn*Cn), dim3(32, 8)>>>(skip, skTh, skTl);

    auto run_ln = [&](const float* X, int gi, float* Yb) {
        ln_kernel<<<dim3(Wn / 64, Cn, Bn), 64>>>(X, ng + gi * Cn * Fn, nbet + gi * Cn * Fn, Yb);
    };
    auto run_ln_t = [&](const float* X, int gi) {
        ln_t_kernel<<<dim3(Wn / 64, Cn, Bn), 64>>>(X, ng + gi * Cn * Fn, nbet + gi * Cn * Fn, zTh, zTl);
    };

    auto run_attn = [&](int i, const __nv_bfloat16* th, const __nv_bfloat16* tl,
                        const __nv_bfloat16* mh, const __nv_bfloat16* ml, bool accO) {
        size_t wo = (size_t)i * WOFF;
        gemm_mma<false><<<gGemm, 256, GSM>>>(WqH + wo, WqL + wo, th, tl, linB);
        conv_rope<true><<<gConv, 128>>>(linB, Kq + (size_t)i * Cn * Cn * 3, bq + i * Cn, qB);
        gemm_mma<false><<<gGemm, 256, GSM>>>(WkH + wo, WkL + wo, mh, ml, linB);
        conv_rope<true><<<gConv, 128>>>(linB, Kk + (size_t)i * Cn * Cn * 3, bk + i * Cn, kB);
        gemm_mma<false><<<gGemm, 256, GSM>>>(WvH + wo, WvL + wo, mh, ml, linB);
        conv_rope<false><<<gConv, 128>>>(linB, Kv + (size_t)i * Cn * Cn * 3, bv + i * Cn, vB);
        attn_kernel<<<Bn * Cn * Hn, 512>>>(qB, kB, vB, atTh, atTl);
        if (accO) gemm_mma<true><<<gGemm, 256, GSM>>>(WoH + wo, WoL + wo, atTh, atTl, oB);
        else      gemm_mma<false><<<gGemm, 256, GSM>>>(WoH + wo, WoL + wo, atTh, atTl, oB);
    };

    // h = x; z = LN0(h); h = h + att0(z,z) + att1(z,skip)
    run_ln_t(x, 0);
    run_attn(0, zTh, zTl, zTh, zTl, false);
    run_attn(1, zTh, zTl, skTh, skTl, true);
    add_xo<<<nElemBlocks, 256>>>(x, oB, hB);

    // conv block
    run_ln(hB, 1, zB);
    frameconv_ab<<<nElemBlocks, 256>>>(zB, c1a_w, c1a_b, c1b_w, c1b_b, t1B);
    run_ln(t1B, 2, zB);
    frameconv2_add<<<nElemBlocks, 256>>>(zB, c2_w, c2_b, hB);

    // h = h + att2(LN3(h), same)
    run_ln_t(hB, 3);
    run_attn(2, zTh, zTl, zTh, zTl, false);
    add_inplace<<<nElemBlocks, 256>>>(hB, oB);

    // h = h + att3(LN4(h), skip)
    run_ln_t(hB, 4);
    run_attn(3, zTh, zTl, skTh, skTl, false);
    add_inplace<<<nElemBlocks, 256>>>(hB, oB);

    // FFN
    run_ln(hB, 5, zB);
    ffn3<<<Bn * Cn, 512>>>(zB, w3, ffnB);
    ffn4_add<<<nElemBlocks, 256>>>(ffnB, w4, hB);

    // concat(x, h)
    write_out<<<nElemBlocks, 256>>>(x, hB, out);
}

// round 5
// speedup vs baseline: 1.9665x; 1.6655x over previous
#include <cuda_runtime.h>
#include <cuda_bf16.h>
#include <math.h>
#include <stdint.h>

#define Bn 2
#define Cn 8
#define Fn 256
#define Wn 512
#define Hn 8
#define HDn 32
#define En 4
#define NB (Bn*Cn*Fn*Wn)
#define WOFF (Cn*Fn*Fn)
#define NHEAD (Bn*Cn*Hn)

// ======================= warp-MMA helpers (baseline PTX, sm_80+) =======================
__device__ __forceinline__ uint32_t smem_u32(const void* p) {
    uint32_t a;
    asm("{ .reg .u64 t; cvta.to.shared.u64 t, %1; cvt.u32.u64 %0, t; }" : "=r"(a) : "l"(p));
    return a;
}
__device__ __forceinline__ void ldm_x4(uint32_t& r0, uint32_t& r1, uint32_t& r2, uint32_t& r3,
                                       uint32_t addr) {
    asm volatile("ldmatrix.sync.aligned.m8n8.x4.shared.b16 {%0,%1,%2,%3}, [%4];"
                 : "=r"(r0), "=r"(r1), "=r"(r2), "=r"(r3) : "r"(addr));
}
__device__ __forceinline__ void ldm_x2_trans(uint32_t& r0, uint32_t& r1, uint32_t addr) {
    asm volatile("ldmatrix.sync.aligned.m8n8.x2.trans.shared.b16 {%0,%1}, [%2];"
                 : "=r"(r0), "=r"(r1) : "r"(addr));
}
__device__ __forceinline__ void mma_bf16(float* d, const uint32_t* a, const uint32_t* b) {
    asm volatile("mma.sync.aligned.m16n8k16.row.col.f32.bf16.bf16.f32 "
                 "{%0,%1,%2,%3}, {%4,%5,%6,%7}, {%8,%9}, {%0,%1,%2,%3};"
                 : "+f"(d[0]), "+f"(d[1]), "+f"(d[2]), "+f"(d[3])
                 : "r"(a[0]), "r"(a[1]), "r"(a[2]), "r"(a[3]), "r"(b[0]), "r"(b[1]));
}
__device__ __forceinline__ uint32_t pack_split(float a, float b, uint32_t& lo) {
    __nv_bfloat16 ha = __float2bfloat16(a), hb = __float2bfloat16(b);
    __nv_bfloat16 la = __float2bfloat16(a - __bfloat162float(ha));
    __nv_bfloat16 lb = __float2bfloat16(b - __bfloat162float(hb));
    lo = (uint32_t)__bfloat16_as_ushort(la) | ((uint32_t)__bfloat16_as_ushort(lb) << 16);
    return (uint32_t)__bfloat16_as_ushort(ha) | ((uint32_t)__bfloat16_as_ushort(hb) << 16);
}
__device__ __forceinline__ uint32_t packbf(float a, float b) {
    __nv_bfloat162 v = __floats2bfloat162_rn(a, b);
    return *(uint32_t*)&v;
}

// ======================= scratch (device globals) =======================
__device__ float g_h[NB];
__device__ float g_z[NB];
__device__ float g_lin[NB];
__device__ float g_t1[NB];
__device__ float g_o[NB];
__device__ float g_ffn[Bn*Cn*En*Wn];
__device__ uint2 g_qI[NHEAD*Wn*16];                 // Q interleaved hi/lo bf16x2
__device__ uint2 g_kI[NHEAD*Wn*16];                 // K interleaved hi/lo bf16x2
__device__ __nv_bfloat16 g_vbf[NHEAD*Wn*HDn];       // V bf16 [head][m][d]
__device__ __nv_bfloat16 g_zTh[Bn*Cn*Wn*Fn];
__device__ __nv_bfloat16 g_zTl[Bn*Cn*Wn*Fn];
__device__ __nv_bfloat16 g_skTh[Bn*Cn*Wn*Fn];
__device__ __nv_bfloat16 g_skTl[Bn*Cn*Wn*Fn];
__device__ __nv_bfloat16 g_atTh[Bn*Cn*Wn*Fn];
__device__ __nv_bfloat16 g_atTl[Bn*Cn*Wn*Fn];
__device__ __nv_bfloat16 g_WqH[4*WOFF]; __device__ __nv_bfloat16 g_WqL[4*WOFF];
__device__ __nv_bfloat16 g_WkH[4*WOFF]; __device__ __nv_bfloat16 g_WkL[4*WOFF];
__device__ __nv_bfloat16 g_WvH[4*WOFF]; __device__ __nv_bfloat16 g_WvL[4*WOFF];
__device__ __nv_bfloat16 g_WoH[4*WOFF]; __device__ __nv_bfloat16 g_WoL[4*WOFF];

// ======================= fp32 LayerNorm (conv/FFN path) =======================
__global__ void ln_kernel(const float* __restrict__ X, const float* __restrict__ gam,
                          const float* __restrict__ bet, float* __restrict__ Y) {
    int w = blockIdx.x * 64 + threadIdx.x;
    int c = blockIdx.y, b = blockIdx.z;
    const float* xp = X + ((size_t)(b*Cn + c) * Fn) * Wn + w;
    float s = 0.f, s2 = 0.f;
#pragma unroll 4
    for (int f = 0; f < Fn; f++) { float v = xp[(size_t)f * Wn]; s += v; s2 += v * v; }
    float m = s * (1.0f / Fn);
    float inv = rsqrtf(s2 * (1.0f / Fn) - m * m + 1e-5f);
    const float* gp = gam + c * Fn;
    const float* bp = bet + c * Fn;
    float* yp = Y + ((size_t)(b*Cn + c) * Fn) * Wn + w;
#pragma unroll 4
    for (int f = 0; f < Fn; f++)
        yp[(size_t)f * Wn] = (xp[(size_t)f * Wn] - m) * inv * gp[f] + bp[f];
}

// ============ LayerNorm -> transposed bf16 hi/lo ([bc][w][f]) for GEMM B ============
__global__ void ln_t_kernel(const float* __restrict__ X, const float* __restrict__ gam,
                            const float* __restrict__ bet,
                            __nv_bfloat16* __restrict__ Zh, __nv_bfloat16* __restrict__ Zl) {
    int w = blockIdx.x * 64 + threadIdx.x;
    int c = blockIdx.y, b = blockIdx.z;
    int bc = b * Cn + c;
    const float* xp = X + ((size_t)bc * Fn) * Wn + w;
    float s = 0.f, s2 = 0.f;
#pragma unroll 4
    for (int f = 0; f < Fn; f++) { float v = xp[(size_t)f * Wn]; s += v; s2 += v * v; }
    float m = s * (1.0f / Fn);
    float inv = rsqrtf(s2 * (1.0f / Fn) - m * m + 1e-5f);
    const float* gp = gam + c * Fn;
    const float* bp = bet + c * Fn;
    __nv_bfloat16* th = Zh + ((size_t)bc * Wn + w) * Fn;
    __nv_bfloat16* tl = Zl + ((size_t)bc * Wn + w) * Fn;
    for (int f0 = 0; f0 < Fn; f0 += 8) {
        uint32_t ph[4], pl[4];
#pragma unroll
        for (int j = 0; j < 4; j++) {
            int f = f0 + 2 * j;
            float v0 = (xp[(size_t)f * Wn]     - m) * inv * gp[f]   + bp[f];
            float v1 = (xp[(size_t)(f+1) * Wn] - m) * inv * gp[f+1] + bp[f+1];
            ph[j] = pack_split(v0, v1, pl[j]);
        }
        *(uint4*)(th + f0) = make_uint4(ph[0], ph[1], ph[2], ph[3]);
        *(uint4*)(tl + f0) = make_uint4(pl[0], pl[1], pl[2], pl[3]);
    }
}

// ============ transpose + split: (b,c,f,w) fp32 -> [bc][w][f] bf16 hi/lo ============
__global__ void tsplit_kernel(const float* __restrict__ X,
                              __nv_bfloat16* __restrict__ Th, __nv_bfloat16* __restrict__ Tl) {
    __shared__ float t[32][33];
    int bc = blockIdx.z;
    int w0 = blockIdx.x * 32, f0 = blockIdx.y * 32;
    const float* xp = X + ((size_t)bc * Fn + f0) * Wn + w0;
#pragma unroll
    for (int i = 0; i < 4; i++) {
        int fr = threadIdx.y + i * 8;
        t[fr][threadIdx.x] = xp[(size_t)fr * Wn + threadIdx.x];
    }
    __syncthreads();
#pragma unroll
    for (int i = 0; i < 4; i++) {
        int wr = threadIdx.y + i * 8;
        float v = t[threadIdx.x][wr];
        __nv_bfloat16 h = __float2bfloat16(v);
        __nv_bfloat16 l = __float2bfloat16(v - __bfloat162float(h));
        size_t idx = ((size_t)bc * Wn + w0 + wr) * Fn + f0 + threadIdx.x;
        Th[idx] = h; Tl[idx] = l;
    }
}

// ============ weight split: fp32 -> bf16 hi/lo (K-major layout preserved) ============
__global__ void wsplit_kernel(const float* __restrict__ X,
                              __nv_bfloat16* __restrict__ H, __nv_bfloat16* __restrict__ L) {
    int i = (blockIdx.x * 256 + threadIdx.x) * 4;
    float4 v = *(const float4*)(X + i);
    uint32_t l0, l1;
    uint32_t h0 = pack_split(v.x, v.y, l0);
    uint32_t h1 = pack_split(v.z, v.w, l1);
    *(uint2*)((unsigned short*)H + i) = make_uint2(h0, h1);
    *(uint2*)((unsigned short*)L + i) = make_uint2(l0, l1);
}

// ======================= mma.sync 3xBF16 per-channel GEMM (verified round 3) =======================
#define KCn 64
#define LDT 72
#define TELEM (128 * LDT)

template<bool ACC>
__global__ void __launch_bounds__(256) gemm_mma(const __nv_bfloat16* __restrict__ AhG,
                                                const __nv_bfloat16* __restrict__ AlG,
                                                const __nv_bfloat16* __restrict__ BhG,
                                                const __nv_bfloat16* __restrict__ BlG,
                                                float* __restrict__ Y) {
    extern __shared__ __nv_bfloat16 sm[];
    __nv_bfloat16* sAh = sm;
    __nv_bfloat16* sAl = sm + TELEM;
    __nv_bfloat16* sBh = sm + 2 * TELEM;
    __nv_bfloat16* sBl = sm + 3 * TELEM;
    int tid = threadIdx.x, lane = tid & 31, wid = tid >> 5;
    int wm = wid >> 2, wn = wid & 3;
    int bc = blockIdx.z, c = bc & (Cn - 1);
    int tileM = blockIdx.y * 128, tileN = blockIdx.x * 128;
    const __nv_bfloat16* gAh = AhG + ((size_t)c * Fn + tileM) * Fn;
    const __nv_bfloat16* gAl = AlG + ((size_t)c * Fn + tileM) * Fn;
    const __nv_bfloat16* gBh = BhG + ((size_t)bc * Wn + tileN) * Fn;
    const __nv_bfloat16* gBl = BlG + ((size_t)bc * Wn + tileN) * Fn;

    float acc[4][4][4] = {};
    int lrow = tid >> 1;
    int lq   = (tid & 1) * 4;

    uint32_t sb = smem_u32(sm);
    int grp = lane >> 3, lr = lane & 7;
    int aRow = wm * 64 + (grp & 1) * 8 + lr;
    int aCol = (grp >> 1) * 8;
    int bRow = wn * 32 + (grp >> 1) * 8 + lr;
    int bCol = (grp & 1) * 8;

    for (int kc = 0; kc < 4; kc++) {
        if (kc) __syncthreads();
        const uint4* pa = (const uint4*)(gAh + (size_t)lrow * Fn + kc * KCn);
        const uint4* pb = (const uint4*)(gAl + (size_t)lrow * Fn + kc * KCn);
        const uint4* pc = (const uint4*)(gBh + (size_t)lrow * Fn + kc * KCn);
        const uint4* pd = (const uint4*)(gBl + (size_t)lrow * Fn + kc * KCn);
        uint4* qa = (uint4*)(sAh + lrow * LDT);
        uint4* qb = (uint4*)(sAl + lrow * LDT);
        uint4* qc = (uint4*)(sBh + lrow * LDT);
        uint4* qd = (uint4*)(sBl + lrow * LDT);
#pragma unroll
        for (int j = 0; j < 4; j++) {
            qa[lq + j] = pa[lq + j];
            qb[lq + j] = pb[lq + j];
            qc[lq + j] = pc[lq + j];
            qd[lq + j] = pd[lq + j];
        }
        __syncthreads();
#pragma unroll
        for (int ks = 0; ks < 4; ks++) {
            int k0 = ks * 16;
            uint32_t ah[4][4], al[4][4], bh[2][4], bl[2][4];
#pragma unroll
            for (int mi = 0; mi < 4; mi++) {
                uint32_t off = ((aRow + mi * 16) * LDT + aCol + k0) * 2;
                ldm_x4(ah[mi][0], ah[mi][1], ah[mi][2], ah[mi][3], sb + off);
                ldm_x4(al[mi][0], al[mi][1], al[mi][2], al[mi][3], sb + TELEM * 2 + off);
            }
#pragma unroll
            for (int nb = 0; nb < 2; nb++) {
                uint32_t off = ((bRow + nb * 16) * LDT + bCol + k0) * 2;
                ldm_x4(bh[nb][0], bh[nb][1], bh[nb][2], bh[nb][3], sb + TELEM * 4 + off);
                ldm_x4(bl[nb][0], bl[nb][1], bl[nb][2], bl[nb][3], sb + TELEM * 6 + off);
            }
#pragma unroll
            for (int mi = 0; mi < 4; mi++) {
#pragma unroll
                for (int nb = 0; nb < 2; nb++) {
                    mma_bf16(acc[mi][2*nb],   ah[mi], &bh[nb][0]);
                    mma_bf16(acc[mi][2*nb+1], ah[mi], &bh[nb][2]);
                    mma_bf16(acc[mi][2*nb],   ah[mi], &bl[nb][0]);
                    mma_bf16(acc[mi][2*nb+1], ah[mi], &bl[nb][2]);
                    mma_bf16(acc[mi][2*nb],   al[mi], &bh[nb][0]);
                    mma_bf16(acc[mi][2*nb+1], al[mi], &bh[nb][2]);
                }
            }
        }
    }

#pragma unroll
    for (int mi = 0; mi < 4; mi++) {
        int row = tileM + wm * 64 + mi * 16 + (lane >> 2);
#pragma unroll
        for (int ni = 0; ni < 4; ni++) {
            int col = tileN + wn * 32 + ni * 8 + (lane & 3) * 2;
            float* p0 = Y + ((size_t)bc * Fn + row) * Wn + col;
            float* p1 = p0 + 8 * Wn;
            float2 v0 = make_float2(acc[mi][ni][0], acc[mi][ni][1]);
            float2 v1 = make_float2(acc[mi][ni][2], acc[mi][ni][3]);
            if (ACC) {
                float2 o0 = *(const float2*)p0, o1 = *(const float2*)p1;
                v0.x += o0.x; v0.y += o0.y; v1.x += o1.x; v1.y += o1.y;
            }
            *(float2*)p0 = v0;
            *(float2*)p1 = v1;
        }
    }
}

// ======= conv3 + bias (+RoPE): all 8 output channels per block, smem input tile =======
// MODE 0: Q/K path -> uint2 interleaved bf16x2 hi/lo, with RoPE
// MODE 1: V path   -> __nv_bfloat162 plain, no RoPE
template<int MODE>
__global__ void __launch_bounds__(128) conv_fuse(const float* __restrict__ Lin,
                                                 const float* __restrict__ Kc,
                                                 const float* __restrict__ bias,
                                                 void* __restrict__ Out) {
    __shared__ float sIn[Cn][2][132];
    __shared__ float ks[Cn * Cn * 3];
    int tid = threadIdx.x;
    int w0 = blockIdx.x * 128;
    int p  = blockIdx.y;              // feature-pair 0..127
    int b  = blockIdx.z;
    int f0 = 2 * p;
    for (int t = tid; t < Cn * 2 * 130; t += 128) {
        int ci = t / 260, r = t % 260;
        int fi = r / 130, wo = r % 130;
        int gw = w0 + wo - 1;
        float v = (gw >= 0 && gw < Wn) ? Lin[((size_t)(b*Cn + ci) * Fn + f0 + fi) * Wn + gw] : 0.f;
        sIn[ci][fi][wo] = v;
    }
    for (int t = tid; t < Cn * Cn * 3; t += 128) ks[t] = Kc[t];   // FIX: strided (192 > 128)
    __syncthreads();

    int w = w0 + tid;
    float cs = 1.f, sn = 0.f;
    if (MODE == 0) {
        int j = p & 15;
        float invf = exp10f(-0.25f * (float)j);
        sincosf((float)w * invf, &sn, &cs);
    }
    int h  = p >> 4;
    int jj = p & 15;
#pragma unroll
    for (int co = 0; co < Cn; co++) {
        float acc0 = bias[co], acc1 = acc0;
#pragma unroll
        for (int ci = 0; ci < Cn; ci++) {
            float k0 = ks[co*24 + ci*3], k1 = ks[co*24 + ci*3 + 1], k2 = ks[co*24 + ci*3 + 2];
            acc0 += k0 * sIn[ci][0][tid] + k1 * sIn[ci][0][tid+1] + k2 * sIn[ci][0][tid+2];
            acc1 += k0 * sIn[ci][1][tid] + k1 * sIn[ci][1][tid+1] + k2 * sIn[ci][1][tid+2];
        }
        size_t head = (size_t)(b*Cn + co) * Hn + h;
        size_t idx = (head * Wn + w) * 16 + jj;
        if (MODE == 0) {
            float o0 = acc0 * cs - acc1 * sn;
            float o1 = acc1 * cs + acc0 * sn;
            uint32_t lo, hi = pack_split(o0, o1, lo);
            ((uint2*)Out)[idx] = make_uint2(hi, lo);
        } else {
            ((__nv_bfloat162*)Out)[idx] = __floats2bfloat162_rn(acc0, acc1);
        }
    }
}

// ======================= tensor-core flash attention =======================
// Qi/Ki: [head][n][16][2] u32 (hi,lo bf16x2). V: [head][m][32] bf16.
// Block: 256 thr, 8 warps x 32 queries = 256 q; grid = head*2 (query halves).
__global__ void __launch_bounds__(256, 1) attn_mma(const uint2* __restrict__ Qi,
                                                   const uint2* __restrict__ Ki,
                                                   const __nv_bfloat16* __restrict__ Vg,
                                                   __nv_bfloat16* __restrict__ AttH,
                                                   __nv_bfloat16* __restrict__ AttL) {
    __shared__ __nv_bfloat16 Kh[64][40];
    __shared__ __nv_bfloat16 Kl[64][40];
    __shared__ __nv_bfloat16 Vs[64][40];
    int head = blockIdx.x >> 1, half = blockIdx.x & 1;
    int tid = threadIdx.x, lane = tid & 31, wid = tid >> 5;
    int qb = half * 256 + wid * 32;
    size_t hbase = (size_t)head * Wn;

    // load Q fragments (hi/lo) directly from gmem
    uint32_t qh[2][2][4], ql[2][2][4];
#pragma unroll
    for (int mi = 0; mi < 2; mi++) {
        int r0 = qb + mi * 16 + (lane >> 2);
#pragma unroll
        for (int kk = 0; kk < 2; kk++) {
            int jp = kk * 8 + (lane & 3);
            uint2 t0 = Qi[(hbase + r0) * 16 + jp];
            uint2 t1 = Qi[(hbase + r0 + 8) * 16 + jp];
            uint2 t2 = Qi[(hbase + r0) * 16 + jp + 4];
            uint2 t3 = Qi[(hbase + r0 + 8) * 16 + jp + 4];
            qh[mi][kk][0] = t0.x; qh[mi][kk][1] = t1.x; qh[mi][kk][2] = t2.x; qh[mi][kk][3] = t3.x;
            ql[mi][kk][0] = t0.y; ql[mi][kk][1] = t1.y; ql[mi][kk][2] = t2.y; ql[mi][kk][3] = t3.y;
        }
    }
    float m_[4] = {-1e30f, -1e30f, -1e30f, -1e30f};
    float l_[4] = {0.f, 0.f, 0.f, 0.f};
    float o[2][4][4] = {};
    uint32_t sbK = smem_u32(Kh), sbKl = smem_u32(Kl), sbV = smem_u32(Vs);
    int grp = lane >> 3, lr = lane & 7;

    for (int kt = 0; kt < 8; kt++) {
        int kb = kt * 64;
        __syncthreads();
        // stage K interleaved -> Kh/Kl
#pragma unroll
        for (int it = 0; it < 4; it++) {
            int idx = tid + it * 256;
            int row = idx >> 4, j = idx & 15;
            uint2 v = Ki[(hbase + kb + row) * 16 + j];
            ((uint32_t*)&Kh[row][0])[j] = v.x;
            ((uint32_t*)&Kl[row][0])[j] = v.y;
        }
        // stage V
        {
            int row = tid >> 2, q = tid & 3;
            uint4 v = ((const uint4*)(Vg + (hbase + kb + row) * HDn))[q];
            *((uint4*)&Vs[row][q * 8]) = v;
        }
        __syncthreads();

        // ---- scores: 3-term bf16 QK^T ----
        float s[2][8][4] = {};
#pragma unroll
        for (int kk = 0; kk < 2; kk++) {
#pragma unroll
            for (int nb = 0; nb < 4; nb++) {
                uint32_t kh4[4], kl4[4];
                uint32_t off = ((nb * 16 + (grp >> 1) * 8 + lr) * 40 + (grp & 1) * 8 + kk * 16) * 2;
                ldm_x4(kh4[0], kh4[1], kh4[2], kh4[3], sbK + off);
                ldm_x4(kl4[0], kl4[1], kl4[2], kl4[3], sbKl + off);
#pragma unroll
                for (int mi = 0; mi < 2; mi++) {
                    mma_bf16(s[mi][2*nb],   qh[mi][kk], &kh4[0]);
                    mma_bf16(s[mi][2*nb+1], qh[mi][kk], &kh4[2]);
                    mma_bf16(s[mi][2*nb],   qh[mi][kk], &kl4[0]);
                    mma_bf16(s[mi][2*nb+1], qh[mi][kk], &kl4[2]);
                    mma_bf16(s[mi][2*nb],   ql[mi][kk], &kh4[0]);
                    mma_bf16(s[mi][2*nb+1], ql[mi][kk], &kh4[2]);
                }
            }
        }

        // ---- online softmax + P (bf16) ----
        uint32_t pa[2][4][4];
#pragma unroll
        for (int mi = 0; mi < 2; mi++) {
            float mx0 = -1e30f, mx1 = -1e30f;
#pragma unroll
            for (int n = 0; n < 8; n++) {
#pragma unroll
                for (int q = 0; q < 4; q++) s[mi][n][q] *= 0.0625f;
                mx0 = fmaxf(mx0, fmaxf(s[mi][n][0], s[mi][n][1]));
                mx1 = fmaxf(mx1, fmaxf(s[mi][n][2], s[mi][n][3]));
            }
            mx0 = fmaxf(mx0, __shfl_xor_sync(0xffffffffu, mx0, 1));
            mx0 = fmaxf(mx0, __shfl_xor_sync(0xffffffffu, mx0, 2));
            mx1 = fmaxf(mx1, __shfl_xor_sync(0xffffffffu, mx1, 1));
            mx1 = fmaxf(mx1, __shfl_xor_sync(0xffffffffu, mx1, 2));
            int si = mi * 2;
            float mn0 = fmaxf(m_[si], mx0), mn1 = fmaxf(m_[si+1], mx1);
            float c0 = __expf(m_[si] - mn0), c1 = __expf(m_[si+1] - mn1);
            m_[si] = mn0; m_[si+1] = mn1;
            float ls0 = 0.f, ls1 = 0.f;
#pragma unroll
            for (int n = 0; n < 8; n++) {
                float p0 = __expf(s[mi][n][0] - mn0);
                float p1 = __expf(s[mi][n][1] - mn0);
                float p2 = __expf(s[mi][n][2] - mn1);
                float p3 = __expf(s[mi][n][3] - mn1);
                ls0 += p0 + p1; ls1 += p2 + p3;
                s[mi][n][0] = p0; s[mi][n][1] = p1; s[mi][n][2] = p2; s[mi][n][3] = p3;
            }
            ls0 += __shfl_xor_sync(0xffffffffu, ls0, 1);
            ls0 += __shfl_xor_sync(0xffffffffu, ls0, 2);
            ls1 += __shfl_xor_sync(0xffffffffu, ls1, 1);
            ls1 += __shfl_xor_sync(0xffffffffu, ls1, 2);
            l_[si]   = l_[si]   * c0 + ls0;
            l_[si+1] = l_[si+1] * c1 + ls1;
#pragma unroll
            for (int dn = 0; dn < 4; dn++) {
                o[mi][dn][0] *= c0; o[mi][dn][1] *= c0;
                o[mi][dn][2] *= c1; o[mi][dn][3] *= c1;
            }
#pragma unroll
            for (int t = 0; t < 4; t++) {
                pa[mi][t][0] = packbf(s[mi][2*t][0],   s[mi][2*t][1]);
                pa[mi][t][1] = packbf(s[mi][2*t][2],   s[mi][2*t][3]);
                pa[mi][t][2] = packbf(s[mi][2*t+1][0], s[mi][2*t+1][1]);
                pa[mi][t][3] = packbf(s[mi][2*t+1][2], s[mi][2*t+1][3]);
            }
        }

        // ---- P @ V ----
#pragma unroll
        for (int dn = 0; dn < 4; dn++) {
            uint32_t vb[4][2];
#pragma unroll
            for (int t = 0; t < 4; t++) {
                uint32_t off = ((t * 16 + (lane & 15)) * 40 + dn * 8) * 2;
                ldm_x2_trans(vb[t][0], vb[t][1], sbV + off);
            }
#pragma unroll
            for (int mi = 0; mi < 2; mi++)
#pragma unroll
                for (int t = 0; t < 4; t++)
                    mma_bf16(o[mi][dn], pa[mi][t], vb[t]);
        }
    }

    // ---- epilogue: O/l -> bf16 hi/lo at [bc][w][f] ----
    int bc = head >> 3, hh = head & 7;
#pragma unroll
    for (int mi = 0; mi < 2; mi++) {
        int r0 = qb + mi * 16 + (lane >> 2);
        float i0 = 1.0f / l_[mi*2], i1 = 1.0f / l_[mi*2 + 1];
#pragma unroll
        for (int dn = 0; dn < 4; dn++) {
            int d0 = dn * 8 + (lane & 3) * 2;
            size_t a0 = ((size_t)bc * Wn + r0) * Fn + hh * HDn + d0;
            size_t a1 = ((size_t)bc * Wn + r0 + 8) * Fn + hh * HDn + d0;
            uint32_t lo0, hi0 = pack_split(o[mi][dn][0] * i0, o[mi][dn][1] * i0, lo0);
            uint32_t lo1, hi1 = pack_split(o[mi][dn][2] * i1, o[mi][dn][3] * i1, lo1);
            *(uint32_t*)(AttH + a0) = hi0;
            *(uint32_t*)(AttL + a0) = lo0;
            *(uint32_t*)(AttH + a1) = hi1;
            *(uint32_t*)(AttL + a1) = lo1;
        }
    }
}

// ======================= depthwise convs / FFN / elementwise =======================
__global__ void frameconv_ab(const float* __restrict__ Z,
                             const float* __restrict__ k11, const float* __restrict__ b11,
                             const float* __restrict__ k7,  const float* __restrict__ b7,
                             float* __restrict__ Yo) {
    int idx = blockIdx.x * 256 + threadIdx.x;
    int w  = idx & (Wn - 1);
    int f  = (idx >> 9) & (Fn - 1);
    int bc = idx >> 17;
    int c  = bc & (Cn - 1);
    const float* zp = Z + (size_t)bc * Fn * Wn + w;
    float a = b11[c];
#pragma unroll
    for (int t = 0; t < 11; t++) {
        int ff = f - 5 + t;
        if (ff >= 0 && ff < Fn) a += zp[(size_t)ff * Wn] * k11[c * 11 + t];
    }
    a = fmaxf(a, 0.f); a = a * a;
    float bo = b7[c];
#pragma unroll
    for (int t = 0; t < 7; t++) {
        int ff = f - 3 + t;
        if (ff >= 0 && ff < Fn) bo += zp[(size_t)ff * Wn] * k7[c * 7 + t];
    }
    Yo[idx] = a + bo;
}

__global__ void frameconv2_add(const float* __restrict__ S,
                               const float* __restrict__ k7, const float* __restrict__ b7,
                               float* __restrict__ Hb) {
    int idx = blockIdx.x * 256 + threadIdx.x;
    int w  = idx & (Wn - 1);
    int f  = (idx >> 9) & (Fn - 1);
    int bc = idx >> 17;
    int c  = bc & (Cn - 1);
    const float* sp = S + (size_t)bc * Fn * Wn + w;
    float v = b7[c];
#pragma unroll
    for (int t = 0; t < 7; t++) {
        int ff = f - 3 + t;
        if (ff >= 0 && ff < Fn) v += sp[(size_t)ff * Wn] * k7[c * 7 + t];
    }
    Hb[idx] += v;
}

__global__ void add_xo(const float* __restrict__ X, const float* __restrict__ O,
                       float* __restrict__ Hb) {
    int idx = blockIdx.x * 256 + threadIdx.x;
    Hb[idx] = X[idx] + O[idx];
}

__global__ void add_inplace(float* __restrict__ Hb, const float* __restrict__ O) {
    int idx = blockIdx.x * 256 + threadIdx.x;
    Hb[idx] += O[idx];
}

__global__ void __launch_bounds__(512) ffn3(const float* __restrict__ Z,
                                            const float* __restrict__ w3,
                                            float* __restrict__ T) {
    __shared__ float ws[En * Fn];
    int bc = blockIdx.x;
    int c  = bc & (Cn - 1);
    for (int i = threadIdx.x; i < En * Fn; i += 512) ws[i] = w3[c * En * Fn + i];
    __syncthreads();
    const float* zp = Z + (size_t)bc * Fn * Wn + threadIdx.x;
    float acc[En] = {};
    for (int f = 0; f < Fn; f++) {
        float zv = zp[(size_t)f * Wn];
#pragma unroll
        for (int e = 0; e < En; e++) acc[e] += zv * ws[e * Fn + f];
    }
    float* tp = T + (size_t)bc * En * Wn + threadIdx.x;
#pragma unroll
    for (int e = 0; e < En; e++) {
        float v = fmaxf(acc[e], 0.f);
        tp[(size_t)e * Wn] = v * v;
    }
}

__global__ void ffn4_add(const float* __restrict__ T, const float* __restrict__ w4,
                         float* __restrict__ Hb) {
    int idx = blockIdx.x * 256 + threadIdx.x;
    int w  = idx & (Wn - 1);
    int f  = (idx >> 9) & (Fn - 1);
    int bc = idx >> 17;
    int c  = bc & (Cn - 1);
    const float* tp = T + (size_t)bc * En * Wn + w;
    const float* wp = w4 + ((size_t)c * Fn + f) * En;
    float v = tp[0] * wp[0] + tp[Wn] * wp[1] + tp[2 * Wn] * wp[2] + tp[3 * Wn] * wp[3];
    Hb[idx] += v;
}

__global__ void write_out(const float* __restrict__ X, const float* __restrict__ Hb,
                          float* __restrict__ O) {
    int idx = blockIdx.x * 256 + threadIdx.x;
    int b = idx / (Cn * Fn * Wn);
    int r = idx - b * (Cn * Fn * Wn);
    O[(size_t)b * 2 * Cn * Fn * Wn + r] = X[idx];
    O[(size_t)b * 2 * Cn * Fn * Wn + Cn * Fn * Wn + r] = Hb[idx];
}

// =====================================================================================

extern "C" void kernel_launch(void* const* d_in, const int* in_sizes, int n_in,
                              void* d_out, int out_size) {
    const float* x     = (const float*)d_in[0];
    const float* skip  = (const float*)d_in[1];
    const float* Wq    = (const float*)d_in[2];
    const float* Kq    = (const float*)d_in[3];
    const float* bq    = (const float*)d_in[4];
    const float* Wk    = (const float*)d_in[5];
    const float* Kk    = (const float*)d_in[6];
    const float* bk    = (const float*)d_in[7];
    const float* Wv    = (const float*)d_in[8];
    const float* Kv    = (const float*)d_in[9];
    const float* bv    = (const float*)d_in[10];
    const float* Wo    = (const float*)d_in[11];
    const float* ng    = (const float*)d_in[12];
    const float* nbet  = (const float*)d_in[13];
    const float* c1a_w = (const float*)d_in[14];
    const float* c1a_b = (const float*)d_in[15];
    const float* c1b_w = (const float*)d_in[16];
    const float* c1b_b = (const float*)d_in[17];
    const float* c2_w  = (const float*)d_in[18];
    const float* c2_b  = (const float*)d_in[19];
    const float* w3    = (const float*)d_in[20];
    const float* w4    = (const float*)d_in[21];
    float* out = (float*)d_out;

    float *hB, *zB, *linB, *oB, *t1B, *ffnB;
    cudaGetSymbolAddress((void**)&hB,   g_h);
    cudaGetSymbolAddress((void**)&zB,   g_z);
    cudaGetSymbolAddress((void**)&linB, g_lin);
    cudaGetSymbolAddress((void**)&oB,   g_o);
    cudaGetSymbolAddress((void**)&t1B,  g_t1);
    cudaGetSymbolAddress((void**)&ffnB, g_ffn);
    uint2 *qI, *kI;
    __nv_bfloat16 *vBf;
    cudaGetSymbolAddress((void**)&qI,  g_qI);
    cudaGetSymbolAddress((void**)&kI,  g_kI);
    cudaGetSymbolAddress((void**)&vBf, g_vbf);
    __nv_bfloat16 *zTh, *zTl, *skTh, *skTl, *atTh, *atTl;
    __nv_bfloat16 *WqH, *WqL, *WkH, *WkL, *WvH, *WvL, *WoH, *WoL;
    cudaGetSymbolAddress((void**)&zTh,  g_zTh);  cudaGetSymbolAddress((void**)&zTl,  g_zTl);
    cudaGetSymbolAddress((void**)&skTh, g_skTh); cudaGetSymbolAddress((void**)&skTl, g_skTl);
    cudaGetSymbolAddress((void**)&atTh, g_atTh); cudaGetSymbolAddress((void**)&atTl, g_atTl);
    cudaGetSymbolAddress((void**)&WqH, g_WqH); cudaGetSymbolAddress((void**)&WqL, g_WqL);
    cudaGetSymbolAddress((void**)&WkH, g_WkH); cudaGetSymbolAddress((void**)&WkL, g_WkL);
    cudaGetSymbolAddress((void**)&WvH, g_WvH); cudaGetSymbolAddress((void**)&WvL, g_WvL);
    cudaGetSymbolAddress((void**)&WoH, g_WoH); cudaGetSymbolAddress((void**)&WoL, g_WoL);

    const int GSM = 4 * TELEM * 2;
    cudaFuncSetAttribute(gemm_mma<false>, cudaFuncAttributeMaxDynamicSharedMemorySize, GSM);
    cudaFuncSetAttribute(gemm_mma<true>,  cudaFuncAttributeMaxDynamicSharedMemorySize, GSM);

    const dim3 gGemm(Wn / 128, Fn / 128, Bn * Cn);
    const dim3 gConv(Wn / 128, Fn / 2, Bn);
    const int  nElemBlocks = NB / 256;
    const int  wBlocks = (4 * WOFF) / 1024;

    wsplit_kernel<<<wBlocks, 256>>>(Wq, WqH, WqL);
    wsplit_kernel<<<wBlocks, 256>>>(Wk, WkH, WkL);
    wsplit_kernel<<<wBlocks, 256>>>(Wv, WvH, WvL);
    wsplit_kernel<<<wBlocks, 256>>>(Wo, WoH, WoL);
    tsplit_kernel<<<dim3(Wn/32, Fn/32, Bn*Cn), dim3(32, 8)>>>(skip, skTh, skTl);

    auto run_ln = [&](const float* X, int gi, float* Yb) {
        ln_kernel<<<dim3(Wn / 64, Cn, Bn), 64>>>(X, ng + gi * Cn * Fn, nbet + gi * Cn * Fn, Yb);
    };
    auto run_ln_t = [&](const float* X, int gi) {
        ln_t_kernel<<<dim3(Wn / 64, Cn, Bn), 64>>>(X, ng + gi * Cn * Fn, nbet + gi * Cn * Fn, zTh, zTl);
    };

    auto run_attn = [&](int i, const __nv_bfloat16* th, const __nv_bfloat16* tl,
                        const __nv_bfloat16* mh, const __nv_bfloat16* ml, bool accO) {
        size_t wo = (size_t)i * WOFF;
        gemm_mma<false><<<gGemm, 256, GSM>>>(WqH + wo, WqL + wo, th, tl, linB);
        conv_fuse<0><<<gConv, 128>>>(linB, Kq + (size_t)i * Cn * Cn * 3, bq + i * Cn, qI);
        gemm_mma<false><<<gGemm, 256, GSM>>>(WkH + wo, WkL + wo, mh, ml, linB);
        conv_fuse<0><<<gConv, 128>>>(linB, Kk + (size_t)i * Cn * Cn * 3, bk + i * Cn, kI);
        gemm_mma<false><<<gGemm, 256, GSM>>>(WvH + wo, WvL + wo, mh, ml, linB);
        conv_fuse<1><<<gConv, 128>>>(linB, Kv + (size_t)i * Cn * Cn * 3, bv + i * Cn, vBf);
        attn_mma<<<NHEAD * 2, 256>>>(qI, kI, vBf, atTh, atTl);
        if (accO) gemm_mma<true><<<gGemm, 256, GSM>>>(WoH + wo, WoL + wo, atTh, atTl, oB);
        else      gemm_mma<false><<<gGemm, 256, GSM>>>(WoH + wo, WoL + wo, atTh, atTl, oB);
    };

    // h = x; z = LN0(h); h = h + att0(z,z) + att1(z,skip)
    run_ln_t(x, 0);
    run_attn(0, zTh, zTl, zTh, zTl, false);
    run_attn(1, zTh, zTl, skTh, skTl, true);
    add_xo<<<nElemBlocks, 256>>>(x, oB, hB);

    // conv block
    run_ln(hB, 1, zB);
    frameconv_ab<<<nElemBlocks, 256>>>(zB, c1a_w, c1a_b, c1b_w, c1b_b, t1B);
    run_ln(t1B, 2, zB);
    frameconv2_add<<<nElemBlocks, 256>>>(zB, c2_w, c2_b, hB);

    // h = h + att2(LN3(h), same)
    run_ln_t(hB, 3);
    run_attn(2, zTh, zTl, zTh, zTl, false);
    add_inplace<<<nElemBlocks, 256>>>(hB, oB);

    // h = h + att3(LN4(h), skip)
    run_ln_t(hB, 4);
    run_attn(3, zTh, zTl, skTh, skTl, false);
    add_inplace<<<nElemBlocks, 256>>>(hB, oB);

    // FFN
    run_ln(hB, 5, zB);
    ffn3<<<Bn * Cn, 512>>>(zB, w3, ffnB);
    ffn4_add<<<nElemBlocks, 256>>>(ffnB, w4, hB);

    // concat(x, h)
    write_out<<<nElemBlocks, 256>>>(x, hB, out);
}

// round 8
// speedup vs baseline: 2.3091x; 1.1742x over previous
#include <cuda_runtime.h>
#include <cuda_bf16.h>
#include <math.h>
#include <stdint.h>

#define Bn 2
#define Cn 8
#define Fn 256
#define Wn 512
#define Hn 8
#define HDn 32
#define En 4
#define NB (Bn*Cn*Fn*Wn)
#define WOFF (Cn*Fn*Fn)
#define NHEAD (Bn*Cn*Hn)

// ======================= warp-MMA helpers (baseline PTX, sm_80+) =======================
__device__ __forceinline__ uint32_t smem_u32(const void* p) {
    uint32_t a;
    asm("{ .reg .u64 t; cvta.to.shared.u64 t, %1; cvt.u32.u64 %0, t; }" : "=r"(a) : "l"(p));
    return a;
}
__device__ __forceinline__ void ldm_x4(uint32_t& r0, uint32_t& r1, uint32_t& r2, uint32_t& r3,
                                       uint32_t addr) {
    asm volatile("ldmatrix.sync.aligned.m8n8.x4.shared.b16 {%0,%1,%2,%3}, [%4];"
                 : "=r"(r0), "=r"(r1), "=r"(r2), "=r"(r3) : "r"(addr));
}
__device__ __forceinline__ void ldm_x2_trans(uint32_t& r0, uint32_t& r1, uint32_t addr) {
    asm volatile("ldmatrix.sync.aligned.m8n8.x2.trans.shared.b16 {%0,%1}, [%2];"
                 : "=r"(r0), "=r"(r1) : "r"(addr));
}
__device__ __forceinline__ void mma_bf16(float* d, const uint32_t* a, const uint32_t* b) {
    asm volatile("mma.sync.aligned.m16n8k16.row.col.f32.bf16.bf16.f32 "
                 "{%0,%1,%2,%3}, {%4,%5,%6,%7}, {%8,%9}, {%0,%1,%2,%3};"
                 : "+f"(d[0]), "+f"(d[1]), "+f"(d[2]), "+f"(d[3])
                 : "r"(a[0]), "r"(a[1]), "r"(a[2]), "r"(a[3]), "r"(b[0]), "r"(b[1]));
}
__device__ __forceinline__ uint32_t pack_split(float a, float b, uint32_t& lo) {
    __nv_bfloat16 ha = __float2bfloat16(a), hb = __float2bfloat16(b);
    __nv_bfloat16 la = __float2bfloat16(a - __bfloat162float(ha));
    __nv_bfloat16 lb = __float2bfloat16(b - __bfloat162float(hb));
    lo = (uint32_t)__bfloat16_as_ushort(la) | ((uint32_t)__bfloat16_as_ushort(lb) << 16);
    return (uint32_t)__bfloat16_as_ushort(ha) | ((uint32_t)__bfloat16_as_ushort(hb) << 16);
}
__device__ __forceinline__ uint32_t packbf(float a, float b) {
    __nv_bfloat162 v = __floats2bfloat162_rn(a, b);
    return *(uint32_t*)&v;
}

// ======================= scratch (device globals) =======================
__device__ float g_h[NB];
__device__ float g_z[NB];
__device__ float g_lin3[3*NB];
__device__ float g_t1[NB];
__device__ float g_ffn[Bn*Cn*En*Wn];
__device__ uint2 g_qI[NHEAD*Wn*16];
__device__ uint2 g_kI[NHEAD*Wn*16];
__device__ __nv_bfloat16 g_vbf[NHEAD*Wn*HDn];
__device__ __nv_bfloat16 g_zTh[Bn*Cn*Wn*Fn];
__device__ __nv_bfloat16 g_zTl[Bn*Cn*Wn*Fn];
__device__ __nv_bfloat16 g_skTh[Bn*Cn*Wn*Fn];
__device__ __nv_bfloat16 g_skTl[Bn*Cn*Wn*Fn];
__device__ __nv_bfloat16 g_atTh[Bn*Cn*Wn*Fn];
__device__ __nv_bfloat16 g_atTl[Bn*Cn*Wn*Fn];
__device__ __nv_bfloat16 g_WqH[4*WOFF]; __device__ __nv_bfloat16 g_WqL[4*WOFF];
__device__ __nv_bfloat16 g_WkH[4*WOFF]; __device__ __nv_bfloat16 g_WkL[4*WOFF];
__device__ __nv_bfloat16 g_WvH[4*WOFF]; __device__ __nv_bfloat16 g_WvL[4*WOFF];
__device__ __nv_bfloat16 g_WoH[4*WOFF]; __device__ __nv_bfloat16 g_WoL[4*WOFF];

// ======================= fp32 LayerNorm (conv/FFN path) =======================
__global__ void ln_kernel(const float* __restrict__ X, const float* __restrict__ gam,
                          const float* __restrict__ bet, float* __restrict__ Y) {
    int w = blockIdx.x * 64 + threadIdx.x;
    int c = blockIdx.y, b = blockIdx.z;
    const float* xp = X + ((size_t)(b*Cn + c) * Fn) * Wn + w;
    float s = 0.f, s2 = 0.f;
#pragma unroll 4
    for (int f = 0; f < Fn; f++) { float v = xp[(size_t)f * Wn]; s += v; s2 += v * v; }
    float m = s * (1.0f / Fn);
    float inv = rsqrtf(s2 * (1.0f / Fn) - m * m + 1e-5f);
    const float* gp = gam + c * Fn;
    const float* bp = bet + c * Fn;
    float* yp = Y + ((size_t)(b*Cn + c) * Fn) * Wn + w;
#pragma unroll 4
    for (int f = 0; f < Fn; f++)
        yp[(size_t)f * Wn] = (xp[(size_t)f * Wn] - m) * inv * gp[f] + bp[f];
}

// ============ LayerNorm -> transposed bf16 hi/lo ([bc][w][f]) ============
__global__ void ln_t_kernel(const float* __restrict__ X, const float* __restrict__ gam,
                            const float* __restrict__ bet,
                            __nv_bfloat16* __restrict__ Zh, __nv_bfloat16* __restrict__ Zl) {
    int w = blockIdx.x * 64 + threadIdx.x;
    int c = blockIdx.y, b = blockIdx.z;
    int bc = b * Cn + c;
    const float* xp = X + ((size_t)bc * Fn) * Wn + w;
    float s = 0.f, s2 = 0.f;
#pragma unroll 4
    for (int f = 0; f < Fn; f++) { float v = xp[(size_t)f * Wn]; s += v; s2 += v * v; }
    float m = s * (1.0f / Fn);
    float inv = rsqrtf(s2 * (1.0f / Fn) - m * m + 1e-5f);
    const float* gp = gam + c * Fn;
    const float* bp = bet + c * Fn;
    __nv_bfloat16* th = Zh + ((size_t)bc * Wn + w) * Fn;
    __nv_bfloat16* tl = Zl + ((size_t)bc * Wn + w) * Fn;
    for (int f0 = 0; f0 < Fn; f0 += 8) {
        uint32_t ph[4], pl[4];
#pragma unroll
        for (int j = 0; j < 4; j++) {
            int f = f0 + 2 * j;
            float v0 = (xp[(size_t)f * Wn]     - m) * inv * gp[f]   + bp[f];
            float v1 = (xp[(size_t)(f+1) * Wn] - m) * inv * gp[f+1] + bp[f+1];
            ph[j] = pack_split(v0, v1, pl[j]);
        }
        *(uint4*)(th + f0) = make_uint4(ph[0], ph[1], ph[2], ph[3]);
        *(uint4*)(tl + f0) = make_uint4(pl[0], pl[1], pl[2], pl[3]);
    }
}

// ============ transpose + split: (b,c,f,w) fp32 -> [bc][w][f] bf16 hi/lo ============
__global__ void tsplit_kernel(const float* __restrict__ X,
                              __nv_bfloat16* __restrict__ Th, __nv_bfloat16* __restrict__ Tl) {
    __shared__ float t[32][33];
    int bc = blockIdx.z;
    int w0 = blockIdx.x * 32, f0 = blockIdx.y * 32;
    const float* xp = X + ((size_t)bc * Fn + f0) * Wn + w0;
#pragma unroll
    for (int i = 0; i < 4; i++) {
        int fr = threadIdx.y + i * 8;
        t[fr][threadIdx.x] = xp[(size_t)fr * Wn + threadIdx.x];
    }
    __syncthreads();
#pragma unroll
    for (int i = 0; i < 4; i++) {
        int wr = threadIdx.y + i * 8;
        float v = t[threadIdx.x][wr];
        __nv_bfloat16 h = __float2bfloat16(v);
        __nv_bfloat16 l = __float2bfloat16(v - __bfloat162float(h));
        size_t idx = ((size_t)bc * Wn + w0 + wr) * Fn + f0 + threadIdx.x;
        Th[idx] = h; Tl[idx] = l;
    }
}

// ============ weight split: all four weight tensors in one launch ============
__global__ void wsplit_all(const float* __restrict__ S0, const float* __restrict__ S1,
                           const float* __restrict__ S2, const float* __restrict__ S3,
                           __nv_bfloat16* H0, __nv_bfloat16* L0,
                           __nv_bfloat16* H1, __nv_bfloat16* L1,
                           __nv_bfloat16* H2, __nv_bfloat16* L2,
                           __nv_bfloat16* H3, __nv_bfloat16* L3) {
    int which = blockIdx.y;
    const float* X = which == 0 ? S0 : which == 1 ? S1 : which == 2 ? S2 : S3;
    __nv_bfloat16* H = which == 0 ? H0 : which == 1 ? H1 : which == 2 ? H2 : H3;
    __nv_bfloat16* L = which == 0 ? L0 : which == 1 ? L1 : which == 2 ? L2 : L3;
    int i = (blockIdx.x * 256 + threadIdx.x) * 4;
    float4 v = *(const float4*)(X + i);
    uint32_t l0, l1;
    uint32_t h0 = pack_split(v.x, v.y, l0);
    uint32_t h1 = pack_split(v.z, v.w, l1);
    *(uint2*)((unsigned short*)H + i) = make_uint2(h0, h1);
    *(uint2*)((unsigned short*)L + i) = make_uint2(l0, l1);
}

// ======================= synchronous-staging 3xBF16 GEMM body (round-5 proven) =======================
#define KCn 64
#define LDT 72
#define TELEM (128 * LDT)
#define GSM (4 * TELEM * 2)          // 73728 bytes

template<bool ACC>
__device__ __forceinline__ void gemm_body(const __nv_bfloat16* __restrict__ gAh,
                                          const __nv_bfloat16* __restrict__ gAl,
                                          const __nv_bfloat16* __restrict__ gBh,
                                          const __nv_bfloat16* __restrict__ gBl,
                                          float* __restrict__ Yrow) {
    extern __shared__ __nv_bfloat16 sm[];
    __nv_bfloat16* sAh = sm;
    __nv_bfloat16* sAl = sm + TELEM;
    __nv_bfloat16* sBh = sm + 2 * TELEM;
    __nv_bfloat16* sBl = sm + 3 * TELEM;
    int tid = threadIdx.x, lane = tid & 31, wid = tid >> 5;
    int wm = wid >> 2, wn = wid & 3;

    float acc[4][4][4] = {};
    int lrow = tid >> 1;
    int lq   = (tid & 1) * 4;

    uint32_t sb = smem_u32(sm);
    int grp = lane >> 3, lr = lane & 7;
    int aRow = wm * 64 + (grp & 1) * 8 + lr;
    int aCol = (grp >> 1) * 8;
    int bRow = wn * 32 + (grp >> 1) * 8 + lr;
    int bCol = (grp & 1) * 8;

    for (int kc = 0; kc < 4; kc++) {
        if (kc) __syncthreads();
        const uint4* pa = (const uint4*)(gAh + (size_t)lrow * Fn + kc * KCn);
        const uint4* pb = (const uint4*)(gAl + (size_t)lrow * Fn + kc * KCn);
        const uint4* pc = (const uint4*)(gBh + (size_t)lrow * Fn + kc * KCn);
        const uint4* pd = (const uint4*)(gBl + (size_t)lrow * Fn + kc * KCn);
        uint4* qa = (uint4*)(sAh + lrow * LDT);
        uint4* qb = (uint4*)(sAl + lrow * LDT);
        uint4* qc = (uint4*)(sBh + lrow * LDT);
        uint4* qd = (uint4*)(sBl + lrow * LDT);
#pragma unroll
        for (int j = 0; j < 4; j++) {
            qa[lq + j] = pa[lq + j];
            qb[lq + j] = pb[lq + j];
            qc[lq + j] = pc[lq + j];
            qd[lq + j] = pd[lq + j];
        }
        __syncthreads();
#pragma unroll
        for (int ks = 0; ks < 4; ks++) {
            int k0 = ks * 16;
            uint32_t ah[4][4], al[4][4], bh[2][4], bl[2][4];
#pragma unroll
            for (int mi = 0; mi < 4; mi++) {
                uint32_t off = ((aRow + mi * 16) * LDT + aCol + k0) * 2;
                ldm_x4(ah[mi][0], ah[mi][1], ah[mi][2], ah[mi][3], sb + off);
                ldm_x4(al[mi][0], al[mi][1], al[mi][2], al[mi][3], sb + TELEM * 2 + off);
            }
#pragma unroll
            for (int nb = 0; nb < 2; nb++) {
                uint32_t off = ((bRow + nb * 16) * LDT + bCol + k0) * 2;
                ldm_x4(bh[nb][0], bh[nb][1], bh[nb][2], bh[nb][3], sb + TELEM * 4 + off);
                ldm_x4(bl[nb][0], bl[nb][1], bl[nb][2], bl[nb][3], sb + TELEM * 6 + off);
            }
#pragma unroll
            for (int mi = 0; mi < 4; mi++) {
#pragma unroll
                for (int nb = 0; nb < 2; nb++) {
                    mma_bf16(acc[mi][2*nb],   ah[mi], &bh[nb][0]);
                    mma_bf16(acc[mi][2*nb+1], ah[mi], &bh[nb][2]);
                    mma_bf16(acc[mi][2*nb],   ah[mi], &bl[nb][0]);
                    mma_bf16(acc[mi][2*nb+1], ah[mi], &bl[nb][2]);
                    mma_bf16(acc[mi][2*nb],   al[mi], &bh[nb][0]);
                    mma_bf16(acc[mi][2*nb+1], al[mi], &bh[nb][2]);
                }
            }
        }
    }

#pragma unroll
    for (int mi = 0; mi < 4; mi++) {
        int row = wm * 64 + mi * 16 + (lane >> 2);
#pragma unroll
        for (int ni = 0; ni < 4; ni++) {
            int col = wn * 32 + ni * 8 + (lane & 3) * 2;
            float* p0 = Yrow + (size_t)row * Wn + col;
            float* p1 = p0 + 8 * Wn;
            float2 v0 = make_float2(acc[mi][ni][0], acc[mi][ni][1]);
            float2 v1 = make_float2(acc[mi][ni][2], acc[mi][ni][3]);
            if (ACC) {
                float2 o0 = *(const float2*)p0, o1 = *(const float2*)p1;
                v0.x += o0.x; v0.y += o0.y; v1.x += o1.x; v1.y += o1.y;
            }
            *(float2*)p0 = v0;
            *(float2*)p1 = v1;
        }
    }
}

// batched Q/K/V projection GEMM: grid (4, 2, 48); z = which*16 + bc
__global__ void __launch_bounds__(256) gemm_qkv(
        const __nv_bfloat16* __restrict__ WqH_, const __nv_bfloat16* __restrict__ WqL_,
        const __nv_bfloat16* __restrict__ WkH_, const __nv_bfloat16* __restrict__ WkL_,
        const __nv_bfloat16* __restrict__ WvH_, const __nv_bfloat16* __restrict__ WvL_,
        const __nv_bfloat16* __restrict__ th, const __nv_bfloat16* __restrict__ tl,
        const __nv_bfloat16* __restrict__ mh, const __nv_bfloat16* __restrict__ ml,
        float* __restrict__ dst3) {
    int z = blockIdx.z;
    int which = z >> 4, bc = z & 15, c = bc & (Cn - 1);
    int tileM = blockIdx.y * 128, tileN = blockIdx.x * 128;
    const __nv_bfloat16* Ah = (which == 0 ? WqH_ : which == 1 ? WkH_ : WvH_) + ((size_t)c * Fn + tileM) * Fn;
    const __nv_bfloat16* Al = (which == 0 ? WqL_ : which == 1 ? WkL_ : WvL_) + ((size_t)c * Fn + tileM) * Fn;
    const __nv_bfloat16* Bh = (which == 0 ? th : mh) + ((size_t)bc * Wn + tileN) * Fn;
    const __nv_bfloat16* Bl = (which == 0 ? tl : ml) + ((size_t)bc * Wn + tileN) * Fn;
    float* Y = dst3 + (size_t)which * NB + ((size_t)bc * Fn + tileM) * Wn + tileN;
    gemm_body<false>(Ah, Al, Bh, Bl, Y);
}

// Wo GEMM, accumulating into h: grid (4, 2, 16)
__global__ void __launch_bounds__(256) gemm_wo(
        const __nv_bfloat16* __restrict__ AhG, const __nv_bfloat16* __restrict__ AlG,
        const __nv_bfloat16* __restrict__ BhG, const __nv_bfloat16* __restrict__ BlG,
        float* __restrict__ Y) {
    int bc = blockIdx.z, c = bc & (Cn - 1);
    int tileM = blockIdx.y * 128, tileN = blockIdx.x * 128;
    gemm_body<true>(AhG + ((size_t)c * Fn + tileM) * Fn,
                    AlG + ((size_t)c * Fn + tileM) * Fn,
                    BhG + ((size_t)bc * Wn + tileN) * Fn,
                    BlG + ((size_t)bc * Wn + tileN) * Fn,
                    Y + ((size_t)bc * Fn + tileM) * Wn + tileN);
}

// ======= batched conv3+bias (+RoPE) for Q/K/V: grid (4, 128, 6); z = which*2 + b =======
__global__ void __launch_bounds__(128) conv_qkv(const float* __restrict__ lin3,
                                                const float* __restrict__ Kcq, const float* __restrict__ bq,
                                                const float* __restrict__ Kck, const float* __restrict__ bk,
                                                const float* __restrict__ Kcv, const float* __restrict__ bv,
                                                uint2* __restrict__ qI, uint2* __restrict__ kI,
                                                __nv_bfloat16* __restrict__ vbf) {
    __shared__ float sIn[Cn][2][132];
    __shared__ float ks[Cn * Cn * 3];
    int tid = threadIdx.x;
    int zz = blockIdx.z;
    int which = zz >> 1, b = zz & 1;
    const float* Lin = lin3 + (size_t)which * NB;
    const float* Kc  = which == 0 ? Kcq : which == 1 ? Kck : Kcv;
    const float* bias = which == 0 ? bq : which == 1 ? bk : bv;
    int w0 = blockIdx.x * 128;
    int p  = blockIdx.y;
    int f0 = 2 * p;
    for (int t = tid; t < Cn * 2 * 130; t += 128) {
        int ci = t / 260, r = t % 260;
        int fi = r / 130, wo = r % 130;
        int gw = w0 + wo - 1;
        float v = (gw >= 0 && gw < Wn) ? Lin[((size_t)(b*Cn + ci) * Fn + f0 + fi) * Wn + gw] : 0.f;
        sIn[ci][fi][wo] = v;
    }
    for (int t = tid; t < Cn * Cn * 3; t += 128) ks[t] = Kc[t];
    __syncthreads();

    int w = w0 + tid;
    float cs = 1.f, sn = 0.f;
    if (which < 2) {
        int j = p & 15;
        float invf = exp10f(-0.25f * (float)j);
        sincosf((float)w * invf, &sn, &cs);
    }
    int h  = p >> 4;
    int jj = p & 15;
#pragma unroll
    for (int co = 0; co < Cn; co++) {
        float acc0 = bias[co], acc1 = acc0;
#pragma unroll
        for (int ci = 0; ci < Cn; ci++) {
            float k0 = ks[co*24 + ci*3], k1 = ks[co*24 + ci*3 + 1], k2 = ks[co*24 + ci*3 + 2];
            acc0 += k0 * sIn[ci][0][tid] + k1 * sIn[ci][0][tid+1] + k2 * sIn[ci][0][tid+2];
            acc1 += k0 * sIn[ci][1][tid] + k1 * sIn[ci][1][tid+1] + k2 * sIn[ci][1][tid+2];
        }
        size_t head = (size_t)(b*Cn + co) * Hn + h;
        size_t idx = (head * Wn + w) * 16 + jj;
        if (which < 2) {
            float o0 = acc0 * cs - acc1 * sn;
            float o1 = acc1 * cs + acc0 * sn;
            uint32_t lo, hi = pack_split(o0, o1, lo);
            (which == 0 ? qI : kI)[idx] = make_uint2(hi, lo);
        } else {
            ((__nv_bfloat162*)vbf)[idx] = __floats2bfloat162_rn(acc0, acc1);
        }
    }
}

// ======================= tensor-core flash attention (2-term QK) =======================
__global__ void __launch_bounds__(256, 1) attn_mma(const uint2* __restrict__ Qi,
                                                   const uint2* __restrict__ Ki,
                                                   const __nv_bfloat16* __restrict__ Vg,
                                                   __nv_bfloat16* __restrict__ AttH,
                                                   __nv_bfloat16* __restrict__ AttL) {
    __shared__ __nv_bfloat16 Kh[64][40];
    __shared__ __nv_bfloat16 Kl[64][40];
    __shared__ __nv_bfloat16 Vs[64][40];
    int head = blockIdx.x >> 1, half = blockIdx.x & 1;
    int tid = threadIdx.x, lane = tid & 31, wid = tid >> 5;
    int qb = half * 256 + wid * 32;
    size_t hbase = (size_t)head * Wn;

    uint32_t qh[2][2][4];
#pragma unroll
    for (int mi = 0; mi < 2; mi++) {
        int r0 = qb + mi * 16 + (lane >> 2);
#pragma unroll
        for (int kk = 0; kk < 2; kk++) {
            int jp = kk * 8 + (lane & 3);
            qh[mi][kk][0] = Qi[(hbase + r0) * 16 + jp].x;
            qh[mi][kk][1] = Qi[(hbase + r0 + 8) * 16 + jp].x;
            qh[mi][kk][2] = Qi[(hbase + r0) * 16 + jp + 4].x;
            qh[mi][kk][3] = Qi[(hbase + r0 + 8) * 16 + jp + 4].x;
        }
    }
    float m_[4] = {-1e30f, -1e30f, -1e30f, -1e30f};
    float l_[4] = {0.f, 0.f, 0.f, 0.f};
    float o[2][4][4] = {};
    uint32_t sbK = smem_u32(Kh), sbKl = smem_u32(Kl), sbV = smem_u32(Vs);
    int grp = lane >> 3, lr = lane & 7;

    for (int kt = 0; kt < 8; kt++) {
        int kb = kt * 64;
        __syncthreads();
#pragma unroll
        for (int it = 0; it < 4; it++) {
            int idx = tid + it * 256;
            int row = idx >> 4, j = idx & 15;
            uint2 v = Ki[(hbase + kb + row) * 16 + j];
            ((uint32_t*)&Kh[row][0])[j] = v.x;
            ((uint32_t*)&Kl[row][0])[j] = v.y;
        }
        {
            int row = tid >> 2, q = tid & 3;
            uint4 v = ((const uint4*)(Vg + (hbase + kb + row) * HDn))[q];
            *((uint4*)&Vs[row][q * 8]) = v;
        }
        __syncthreads();

        float s[2][8][4] = {};
#pragma unroll
        for (int kk = 0; kk < 2; kk++) {
#pragma unroll
            for (int nb = 0; nb < 4; nb++) {
                uint32_t kh4[4], kl4[4];
                uint32_t off = ((nb * 16 + (grp >> 1) * 8 + lr) * 40 + (grp & 1) * 8 + kk * 16) * 2;
                ldm_x4(kh4[0], kh4[1], kh4[2], kh4[3], sbK + off);
                ldm_x4(kl4[0], kl4[1], kl4[2], kl4[3], sbKl + off);
#pragma unroll
                for (int mi = 0; mi < 2; mi++) {
                    mma_bf16(s[mi][2*nb],   qh[mi][kk], &kh4[0]);
                    mma_bf16(s[mi][2*nb+1], qh[mi][kk], &kh4[2]);
                    mma_bf16(s[mi][2*nb],   qh[mi][kk], &kl4[0]);
                    mma_bf16(s[mi][2*nb+1], qh[mi][kk], &kl4[2]);
                }
            }
        }

        uint32_t pa[2][4][4];
#pragma unroll
        for (int mi = 0; mi < 2; mi++) {
            float mx0 = -1e30f, mx1 = -1e30f;
#pragma unroll
            for (int n = 0; n < 8; n++) {
#pragma unroll
                for (int q = 0; q < 4; q++) s[mi][n][q] *= 0.0625f;
                mx0 = fmaxf(mx0, fmaxf(s[mi][n][0], s[mi][n][1]));
                mx1 = fmaxf(mx1, fmaxf(s[mi][n][2], s[mi][n][3]));
            }
            mx0 = fmaxf(mx0, __shfl_xor_sync(0xffffffffu, mx0, 1));
            mx0 = fmaxf(mx0, __shfl_xor_sync(0xffffffffu, mx0, 2));
            mx1 = fmaxf(mx1, __shfl_xor_sync(0xffffffffu, mx1, 1));
            mx1 = fmaxf(mx1, __shfl_xor_sync(0xffffffffu, mx1, 2));
            int si = mi * 2;
            float mn0 = fmaxf(m_[si], mx0), mn1 = fmaxf(m_[si+1], mx1);
            float c0 = __expf(m_[si] - mn0), c1 = __expf(m_[si+1] - mn1);
            m_[si] = mn0; m_[si+1] = mn1;
            float ls0 = 0.f, ls1 = 0.f;
#pragma unroll
            for (int n = 0; n < 8; n++) {
                float p0 = __expf(s[mi][n][0] - mn0);
                float p1 = __expf(s[mi][n][1] - mn0);
                float p2 = __expf(s[mi][n][2] - mn1);
                float p3 = __expf(s[mi][n][3] - mn1);
                ls0 += p0 + p1; ls1 += p2 + p3;
                s[mi][n][0] = p0; s[mi][n][1] = p1; s[mi][n][2] = p2; s[mi][n][3] = p3;
            }
            ls0 += __shfl_xor_sync(0xffffffffu, ls0, 1);
            ls0 += __shfl_xor_sync(0xffffffffu, ls0, 2);
            ls1 += __shfl_xor_sync(0xffffffffu, ls1, 1);
            ls1 += __shfl_xor_sync(0xffffffffu, ls1, 2);
            l_[si]   = l_[si]   * c0 + ls0;
            l_[si+1] = l_[si+1] * c1 + ls1;
#pragma unroll
            for (int dn = 0; dn < 4; dn++) {
                o[mi][dn][0] *= c0; o[mi][dn][1] *= c0;
                o[mi][dn][2] *= c1; o[mi][dn][3] *= c1;
            }
#pragma unroll
            for (int t = 0; t < 4; t++) {
                pa[mi][t][0] = packbf(s[mi][2*t][0],   s[mi][2*t][1]);
                pa[mi][t][1] = packbf(s[mi][2*t][2],   s[mi][2*t][3]);
                pa[mi][t][2] = packbf(s[mi][2*t+1][0], s[mi][2*t+1][1]);
                pa[mi][t][3] = packbf(s[mi][2*t+1][2], s[mi][2*t+1][3]);
            }
        }

#pragma unroll
        for (int dn = 0; dn < 4; dn++) {
            uint32_t vb[4][2];
#pragma unroll
            for (int t = 0; t < 4; t++) {
                uint32_t off = ((t * 16 + (lane & 15)) * 40 + dn * 8) * 2;
                ldm_x2_trans(vb[t][0], vb[t][1], sbV + off);
            }
#pragma unroll
            for (int mi = 0; mi < 2; mi++)
#pragma unroll
                for (int t = 0; t < 4; t++)
                    mma_bf16(o[mi][dn], pa[mi][t], vb[t]);
        }
    }

    int bc = head >> 3, hh = head & 7;
#pragma unroll
    for (int mi = 0; mi < 2; mi++) {
        int r0 = qb + mi * 16 + (lane >> 2);
        float i0 = 1.0f / l_[mi*2], i1 = 1.0f / l_[mi*2 + 1];
#pragma unroll
        for (int dn = 0; dn < 4; dn++) {
            int d0 = dn * 8 + (lane & 3) * 2;
            size_t a0 = ((size_t)bc * Wn + r0) * Fn + hh * HDn + d0;
            size_t a1 = ((size_t)bc * Wn + r0 + 8) * Fn + hh * HDn + d0;
            uint32_t lo0, hi0 = pack_split(o[mi][dn][0] * i0, o[mi][dn][1] * i0, lo0);
            uint32_t lo1, hi1 = pack_split(o[mi][dn][2] * i1, o[mi][dn][3] * i1, lo1);
            *(uint32_t*)(AttH + a0) = hi0;
            *(uint32_t*)(AttL + a0) = lo0;
            *(uint32_t*)(AttH + a1) = hi1;
            *(uint32_t*)(AttL + a1) = lo1;
        }
    }
}

// ======================= smem-tiled depthwise convs =======================
__global__ void __launch_bounds__(256) frameconv_ab_t(const float* __restrict__ Z,
                                                      const float* __restrict__ k11, const float* __restrict__ b11,
                                                      const float* __restrict__ k7,  const float* __restrict__ b7,
                                                      float* __restrict__ Yo) {
    extern __shared__ float sZ[];
    int tid = threadIdx.x;
    int bc = blockIdx.y, c = bc & (Cn - 1);
    int w0 = blockIdx.x * 64;
    const float* zp = Z + (size_t)bc * Fn * Wn + w0;
    for (int i = tid; i < Fn * 64; i += 256)
        sZ[i] = zp[(size_t)(i >> 6) * Wn + (i & 63)];
    __syncthreads();
    float wk11[11], wk7[7];
#pragma unroll
    for (int t = 0; t < 11; t++) wk11[t] = k11[c * 11 + t];
#pragma unroll
    for (int t = 0; t < 7; t++)  wk7[t]  = k7[c * 7 + t];
    float bb11 = b11[c], bb7 = b7[c];
    int w = tid & 63, fg = tid >> 6;
    float* yo = Yo + (size_t)bc * Fn * Wn + w0 + w;
    for (int f = fg * 64; f < fg * 64 + 64; f++) {
        float a = bb11;
#pragma unroll
        for (int t = 0; t < 11; t++) {
            int ff = f - 5 + t;
            if (ff >= 0 && ff < Fn) a += sZ[ff * 64 + w] * wk11[t];
        }
        a = fmaxf(a, 0.f); a = a * a;
        float bo = bb7;
#pragma unroll
        for (int t = 0; t < 7; t++) {
            int ff = f - 3 + t;
            if (ff >= 0 && ff < Fn) bo += sZ[ff * 64 + w] * wk7[t];
        }
        yo[(size_t)f * Wn] = a + bo;
    }
}

__global__ void __launch_bounds__(256) frameconv2_t(const float* __restrict__ S,
                                                    const float* __restrict__ k7, const float* __restrict__ b7,
                                                    float* __restrict__ Hb) {
    extern __shared__ float sZ[];
    int tid = threadIdx.x;
    int bc = blockIdx.y, c = bc & (Cn - 1);
    int w0 = blockIdx.x * 64;
    const float* sp = S + (size_t)bc * Fn * Wn + w0;
    for (int i = tid; i < Fn * 64; i += 256)
        sZ[i] = sp[(size_t)(i >> 6) * Wn + (i & 63)];
    __syncthreads();
    float wk7[7];
#pragma unroll
    for (int t = 0; t < 7; t++) wk7[t] = k7[c * 7 + t];
    float bb7 = b7[c];
    int w = tid & 63, fg = tid >> 6;
    float* hb = Hb + (size_t)bc * Fn * Wn + w0 + w;
    for (int f = fg * 64; f < fg * 64 + 64; f++) {
        float v = bb7;
#pragma unroll
        for (int t = 0; t < 7; t++) {
            int ff = f - 3 + t;
            if (ff >= 0 && ff < Fn) v += sZ[ff * 64 + w] * wk7[t];
        }
        hb[(size_t)f * Wn] += v;
    }
}

// ======================= misc / FFN / output =======================
__global__ void copy_x(const float* __restrict__ X, float* __restrict__ Hb) {
    int i = blockIdx.x * 256 + threadIdx.x;
    ((float4*)Hb)[i] = ((const float4*)X)[i];
}

__global__ void __launch_bounds__(512) ffn3(const float* __restrict__ Z,
                                            const float* __restrict__ w3,
                                            float* __restrict__ T) {
    __shared__ float ws[En * Fn];
    int bc = blockIdx.x;
    int c  = bc & (Cn - 1);
    for (int i = threadIdx.x; i < En * Fn; i += 512) ws[i] = w3[c * En * Fn + i];
    __syncthreads();
    const float* zp = Z + (size_t)bc * Fn * Wn + threadIdx.x;
    float acc[En] = {};
    for (int f = 0; f < Fn; f++) {
        float zv = zp[(size_t)f * Wn];
#pragma unroll
        for (int e = 0; e < En; e++) acc[e] += zv * ws[e * Fn + f];
    }
    float* tp = T + (size_t)bc * En * Wn + threadIdx.x;
#pragma unroll
    for (int e = 0; e < En; e++) {
        float v = fmaxf(acc[e], 0.f);
        tp[(size_t)e * Wn] = v * v;
    }
}

__global__ void ffn4_add(const float* __restrict__ T, const float* __restrict__ w4,
                         float* __restrict__ Hb) {
    int idx = blockIdx.x * 256 + threadIdx.x;
    int w  = idx & (Wn - 1);
    int f  = (idx >> 9) & (Fn - 1);
    int bc = idx >> 17;
    int c  = bc & (Cn - 1);
    const float* tp = T + (size_t)bc * En * Wn + w;
    const float* wp = w4 + ((size_t)c * Fn + f) * En;
    float v = tp[0] * wp[0] + tp[Wn] * wp[1] + tp[2 * Wn] * wp[2] + tp[3 * Wn] * wp[3];
    Hb[idx] += v;
}

__global__ void write_out(const float* __restrict__ X, const float* __restrict__ Hb,
                          float* __restrict__ O) {
    int idx = blockIdx.x * 256 + threadIdx.x;
    int b = idx / (Cn * Fn * Wn);
    int r = idx - b * (Cn * Fn * Wn);
    O[(size_t)b * 2 * Cn * Fn * Wn + r] = X[idx];
    O[(size_t)b * 2 * Cn * Fn * Wn + Cn * Fn * Wn + r] = Hb[idx];
}

// =====================================================================================

extern "C" void kernel_launch(void* const* d_in, const int* in_sizes, int n_in,
                              void* d_out, int out_size) {
    const float* x     = (const float*)d_in[0];
    const float* skip  = (const float*)d_in[1];
    const float* Wq    = (const float*)d_in[2];
    const float* Kq    = (const float*)d_in[3];
    const float* bq    = (const float*)d_in[4];
    const float* Wk    = (const float*)d_in[5];
    const float* Kk    = (const float*)d_in[6];
    const float* bk    = (const float*)d_in[7];
    const float* Wv    = (const float*)d_in[8];
    const float* Kv    = (const float*)d_in[9];
    const float* bv    = (const float*)d_in[10];
    const float* Wo    = (const float*)d_in[11];
    const float* ng    = (const float*)d_in[12];
    const float* nbet  = (const float*)d_in[13];
    const float* c1a_w = (const float*)d_in[14];
    const float* c1a_b = (const float*)d_in[15];
    const float* c1b_w = (const float*)d_in[16];
    const float* c1b_b = (const float*)d_in[17];
    const float* c2_w  = (const float*)d_in[18];
    const float* c2_b  = (const float*)d_in[19];
    const float* w3    = (const float*)d_in[20];
    const float* w4    = (const float*)d_in[21];
    float* out = (float*)d_out;

    float *hB, *zB, *lin3B, *t1B, *ffnB;
    cudaGetSymbolAddress((void**)&hB,    g_h);
    cudaGetSymbolAddress((void**)&zB,    g_z);
    cudaGetSymbolAddress((void**)&lin3B, g_lin3);
    cudaGetSymbolAddress((void**)&t1B,   g_t1);
    cudaGetSymbolAddress((void**)&ffnB,  g_ffn);
    uint2 *qI, *kI;
    __nv_bfloat16 *vBf;
    cudaGetSymbolAddress((void**)&qI,  g_qI);
    cudaGetSymbolAddress((void**)&kI,  g_kI);
    cudaGetSymbolAddress((void**)&vBf, g_vbf);
    __nv_bfloat16 *zTh, *zTl, *skTh, *skTl, *atTh, *atTl;
    __nv_bfloat16 *WqH, *WqL, *WkH, *WkL, *WvH, *WvL, *WoH, *WoL;
    cudaGetSymbolAddress((void**)&zTh,  g_zTh);  cudaGetSymbolAddress((void**)&zTl,  g_zTl);
    cudaGetSymbolAddress((void**)&skTh, g_skTh); cudaGetSymbolAddress((void**)&skTl, g_skTl);
    cudaGetSymbolAddress((void**)&atTh, g_atTh); cudaGetSymbolAddress((void**)&atTl, g_atTl);
    cudaGetSymbolAddress((void**)&WqH, g_WqH); cudaGetSymbolAddress((void**)&WqL, g_WqL);
    cudaGetSymbolAddress((void**)&WkH, g_WkH); cudaGetSymbolAddress((void**)&WkL, g_WkL);
    cudaGetSymbolAddress((void**)&WvH, g_WvH); cudaGetSymbolAddress((void**)&WvL, g_WvL);
    cudaGetSymbolAddress((void**)&WoH, g_WoH); cudaGetSymbolAddress((void**)&WoL, g_WoL);

    cudaFuncSetAttribute(gemm_qkv, cudaFuncAttributeMaxDynamicSharedMemorySize, GSM);
    cudaFuncSetAttribute(gemm_wo,  cudaFuncAttributeMaxDynamicSharedMemorySize, GSM);
    cudaFuncSetAttribute(frameconv_ab_t, cudaFuncAttributeMaxDynamicSharedMemorySize, Fn*64*4);
    cudaFuncSetAttribute(frameconv2_t,   cudaFuncAttributeMaxDynamicSharedMemorySize, Fn*64*4);

    const int nElemBlocks = NB / 256;
    const int wBlocks = (4 * WOFF) / 1024;

    wsplit_all<<<dim3(wBlocks, 4), 256>>>(Wq, Wk, Wv, Wo,
                                          WqH, WqL, WkH, WkL, WvH, WvL, WoH, WoL);
    tsplit_kernel<<<dim3(Wn/32, Fn/32, Bn*Cn), dim3(32, 8)>>>(skip, skTh, skTl);
    copy_x<<<NB / 1024, 256>>>(x, hB);

    auto run_ln = [&](const float* X, int gi, float* Yb) {
        ln_kernel<<<dim3(Wn / 64, Cn, Bn), 64>>>(X, ng + gi * Cn * Fn, nbet + gi * Cn * Fn, Yb);
    };
    auto run_ln_t = [&](const float* X, int gi) {
        ln_t_kernel<<<dim3(Wn / 64, Cn, Bn), 64>>>(X, ng + gi * Cn * Fn, nbet + gi * Cn * Fn, zTh, zTl);
    };

    auto run_attn = [&](int i, const __nv_bfloat16* th, const __nv_bfloat16* tl,
                        const __nv_bfloat16* mh, const __nv_bfloat16* ml) {
        size_t wo = (size_t)i * WOFF;
        size_t ko = (size_t)i * Cn * Cn * 3;
        gemm_qkv<<<dim3(4, 2, 48), 256, GSM>>>(WqH + wo, WqL + wo, WkH + wo, WkL + wo,
                                               WvH + wo, WvL + wo, th, tl, mh, ml, lin3B);
        conv_qkv<<<dim3(4, 128, 6), 128>>>(lin3B, Kq + ko, bq + i * Cn,
                                           Kk + ko, bk + i * Cn, Kv + ko, bv + i * Cn,
                                           qI, kI, vBf);
        attn_mma<<<NHEAD * 2, 256>>>(qI, kI, vBf, atTh, atTl);
        gemm_wo<<<dim3(4, 2, 16), 256, GSM>>>(WoH + wo, WoL + wo, atTh, atTl, hB);
    };

    // h = x + att0(z,z) + att1(z,skip), z = LN0(x)
    run_ln_t(x, 0);
    run_attn(0, zTh, zTl, zTh, zTl);
    run_attn(1, zTh, zTl, skTh, skTl);

    // conv block
    run_ln(hB, 1, zB);
    frameconv_ab_t<<<dim3(Wn/64, Bn*Cn), 256, Fn*64*4>>>(zB, c1a_w, c1a_b, c1b_w, c1b_b, t1B);
    run_ln(t1B, 2, zB);
    frameconv2_t<<<dim3(Wn/64, Bn*Cn), 256, Fn*64*4>>>(zB, c2_w, c2_b, hB);

    // h += att2(LN3(h), same)
    run_ln_t(hB, 3);
    run_attn(2, zTh, zTl, zTh, zTl);

    // h += att3(LN4(h), skip)
    run_ln_t(hB, 4);
    run_attn(3, zTh, zTl, skTh, skTl);

    // FFN
    run_ln(hB, 5, zB);
    ffn3<<<Bn * Cn, 512>>>(zB, w3, ffnB);
    ffn4_add<<<nElemBlocks, 256>>>(ffnB, w4, hB);

    // concat(x, h)
    write_out<<<nElemBlocks, 256>>>(x, hB, out);
}

// round 9
// speedup vs baseline: 2.7054x; 1.1716x over previous
#include <cuda_runtime.h>
#include <cuda_bf16.h>
#include <math.h>
#include <stdint.h>

#define Bn 2
#define Cn 8
#define Fn 256
#define Wn 512
#define Hn 8
#define HDn 32
#define En 4
#define NB (Bn*Cn*Fn*Wn)
#define WOFF (Cn*Fn*Fn)
#define NHEAD (Bn*Cn*Hn)

// ======================= warp-MMA helpers (baseline PTX, sm_80+) =======================
__device__ __forceinline__ uint32_t smem_u32(const void* p) {
    uint32_t a;
    asm("{ .reg .u64 t; cvta.to.shared.u64 t, %1; cvt.u32.u64 %0, t; }" : "=r"(a) : "l"(p));
    return a;
}
__device__ __forceinline__ void ldm_x4(uint32_t& r0, uint32_t& r1, uint32_t& r2, uint32_t& r3,
                                       uint32_t addr) {
    asm volatile("ldmatrix.sync.aligned.m8n8.x4.shared.b16 {%0,%1,%2,%3}, [%4];"
                 : "=r"(r0), "=r"(r1), "=r"(r2), "=r"(r3) : "r"(addr));
}
__device__ __forceinline__ void ldm_x2_trans(uint32_t& r0, uint32_t& r1, uint32_t addr) {
    asm volatile("ldmatrix.sync.aligned.m8n8.x2.trans.shared.b16 {%0,%1}, [%2];"
                 : "=r"(r0), "=r"(r1) : "r"(addr));
}
__device__ __forceinline__ void mma_bf16(float* d, const uint32_t* a, const uint32_t* b) {
    asm volatile("mma.sync.aligned.m16n8k16.row.col.f32.bf16.bf16.f32 "
                 "{%0,%1,%2,%3}, {%4,%5,%6,%7}, {%8,%9}, {%0,%1,%2,%3};"
                 : "+f"(d[0]), "+f"(d[1]), "+f"(d[2]), "+f"(d[3])
                 : "r"(a[0]), "r"(a[1]), "r"(a[2]), "r"(a[3]), "r"(b[0]), "r"(b[1]));
}
__device__ __forceinline__ uint32_t pack_split(float a, float b, uint32_t& lo) {
    __nv_bfloat16 ha = __float2bfloat16(a), hb = __float2bfloat16(b);
    __nv_bfloat16 la = __float2bfloat16(a - __bfloat162float(ha));
    __nv_bfloat16 lb = __float2bfloat16(b - __bfloat162float(hb));
    lo = (uint32_t)__bfloat16_as_ushort(la) | ((uint32_t)__bfloat16_as_ushort(lb) << 16);
    return (uint32_t)__bfloat16_as_ushort(ha) | ((uint32_t)__bfloat16_as_ushort(hb) << 16);
}
__device__ __forceinline__ uint32_t packbf(float a, float b) {
    __nv_bfloat162 v = __floats2bfloat162_rn(a, b);
    return *(uint32_t*)&v;
}

// ======================= scratch (device globals) =======================
__device__ float g_h[NB];
__device__ float g_z[NB];
__device__ float g_lin3[3*NB];
__device__ float g_t1[NB];
__device__ float g_ffn[Bn*Cn*En*Wn];
__device__ uint2 g_qI[NHEAD*Wn*16];
__device__ uint2 g_kI[NHEAD*Wn*16];
__device__ __nv_bfloat16 g_vbf[NHEAD*Wn*HDn];
__device__ __nv_bfloat16 g_zTh[Bn*Cn*Wn*Fn];
__device__ __nv_bfloat16 g_zTl[Bn*Cn*Wn*Fn];
__device__ __nv_bfloat16 g_skTh[Bn*Cn*Wn*Fn];
__device__ __nv_bfloat16 g_skTl[Bn*Cn*Wn*Fn];
__device__ __nv_bfloat16 g_atTh[Bn*Cn*Wn*Fn];
__device__ __nv_bfloat16 g_atTl[Bn*Cn*Wn*Fn];
__device__ __nv_bfloat16 g_WqH[4*WOFF]; __device__ __nv_bfloat16 g_WqL[4*WOFF];
__device__ __nv_bfloat16 g_WkH[4*WOFF]; __device__ __nv_bfloat16 g_WkL[4*WOFF];
__device__ __nv_bfloat16 g_WvH[4*WOFF]; __device__ __nv_bfloat16 g_WvL[4*WOFF];
__device__ __nv_bfloat16 g_WoH[4*WOFF]; __device__ __nv_bfloat16 g_WoL[4*WOFF];

// ======================= high-occupancy LayerNorm (fp32 out) =======================
// grid (Wn/64, Bn*Cn), block 256 = (64 w, 4 f-groups)
__global__ void __launch_bounds__(256) ln_v2(const float* __restrict__ X,
                                             const float* __restrict__ gam,
                                             const float* __restrict__ bet,
                                             float* __restrict__ Y) {
    __shared__ float ps[4][64], ps2[4][64], mb[64], ib[64];
    int tid = threadIdx.x, w = tid & 63, fg = tid >> 6;
    int bc = blockIdx.y, c = bc & (Cn - 1);
    int w0 = blockIdx.x * 64;
    const float* xp = X + (size_t)bc * Fn * Wn + w0 + w;
    float s = 0.f, s2 = 0.f;
#pragma unroll 4
    for (int f = fg * 64; f < fg * 64 + 64; f++) {
        float v = xp[(size_t)f * Wn];
        s += v; s2 += v * v;
    }
    ps[fg][w] = s; ps2[fg][w] = s2;
    __syncthreads();
    if (fg == 0) {
        float S  = ps[0][w]  + ps[1][w]  + ps[2][w]  + ps[3][w];
        float S2 = ps2[0][w] + ps2[1][w] + ps2[2][w] + ps2[3][w];
        float m = S * (1.0f / Fn);
        mb[w] = m;
        ib[w] = rsqrtf(S2 * (1.0f / Fn) - m * m + 1e-5f);
    }
    __syncthreads();
    float m = mb[w], inv = ib[w];
    const float* gp = gam + c * Fn;
    const float* bp = bet + c * Fn;
    float* yp = Y + (size_t)bc * Fn * Wn + w0 + w;
#pragma unroll 4
    for (int f = fg * 64; f < fg * 64 + 64; f++)
        yp[(size_t)f * Wn] = (xp[(size_t)f * Wn] - m) * inv * gp[f] + bp[f];
}

// ============ high-occupancy LayerNorm -> transposed bf16 hi/lo ([bc][w][f]) ============
__global__ void __launch_bounds__(256) ln_t_v2(const float* __restrict__ X,
                                               const float* __restrict__ gam,
                                               const float* __restrict__ bet,
                                               __nv_bfloat16* __restrict__ Zh,
                                               __nv_bfloat16* __restrict__ Zl) {
    __shared__ float ps[4][64], ps2[4][64], mb[64], ib[64];
    int tid = threadIdx.x, w = tid & 63, fg = tid >> 6;
    int bc = blockIdx.y, c = bc & (Cn - 1);
    int w0 = blockIdx.x * 64;
    const float* xp = X + (size_t)bc * Fn * Wn + w0 + w;
    float s = 0.f, s2 = 0.f;
#pragma unroll 4
    for (int f = fg * 64; f < fg * 64 + 64; f++) {
        float v = xp[(size_t)f * Wn];
        s += v; s2 += v * v;
    }
    ps[fg][w] = s; ps2[fg][w] = s2;
    __syncthreads();
    if (fg == 0) {
        float S  = ps[0][w]  + ps[1][w]  + ps[2][w]  + ps[3][w];
        float S2 = ps2[0][w] + ps2[1][w] + ps2[2][w] + ps2[3][w];
        float m = S * (1.0f / Fn);
        mb[w] = m;
        ib[w] = rsqrtf(S2 * (1.0f / Fn) - m * m + 1e-5f);
    }
    __syncthreads();
    float m = mb[w], inv = ib[w];
    const float* gp = gam + c * Fn;
    const float* bp = bet + c * Fn;
    __nv_bfloat16* th = Zh + ((size_t)bc * Wn + w0 + w) * Fn;
    __nv_bfloat16* tl = Zl + ((size_t)bc * Wn + w0 + w) * Fn;
    for (int f0 = fg * 64; f0 < fg * 64 + 64; f0 += 8) {
        uint32_t ph[4], pl[4];
#pragma unroll
        for (int j = 0; j < 4; j++) {
            int f = f0 + 2 * j;
            float v0 = (xp[(size_t)f * Wn]     - m) * inv * gp[f]   + bp[f];
            float v1 = (xp[(size_t)(f+1) * Wn] - m) * inv * gp[f+1] + bp[f+1];
            ph[j] = pack_split(v0, v1, pl[j]);
        }
        *(uint4*)(th + f0) = make_uint4(ph[0], ph[1], ph[2], ph[3]);
        *(uint4*)(tl + f0) = make_uint4(pl[0], pl[1], pl[2], pl[3]);
    }
}

// ============ transpose + split: (b,c,f,w) fp32 -> [bc][w][f] bf16 hi/lo ============
__global__ void tsplit_kernel(const float* __restrict__ X,
                              __nv_bfloat16* __restrict__ Th, __nv_bfloat16* __restrict__ Tl) {
    __shared__ float t[32][33];
    int bc = blockIdx.z;
    int w0 = blockIdx.x * 32, f0 = blockIdx.y * 32;
    const float* xp = X + ((size_t)bc * Fn + f0) * Wn + w0;
#pragma unroll
    for (int i = 0; i < 4; i++) {
        int fr = threadIdx.y + i * 8;
        t[fr][threadIdx.x] = xp[(size_t)fr * Wn + threadIdx.x];
    }
    __syncthreads();
#pragma unroll
    for (int i = 0; i < 4; i++) {
        int wr = threadIdx.y + i * 8;
        float v = t[threadIdx.x][wr];
        __nv_bfloat16 h = __float2bfloat16(v);
        __nv_bfloat16 l = __float2bfloat16(v - __bfloat162float(h));
        size_t idx = ((size_t)bc * Wn + w0 + wr) * Fn + f0 + threadIdx.x;
        Th[idx] = h; Tl[idx] = l;
    }
}

// ============ weight split: all four weight tensors in one launch ============
__global__ void wsplit_all(const float* __restrict__ S0, const float* __restrict__ S1,
                           const float* __restrict__ S2, const float* __restrict__ S3,
                           __nv_bfloat16* H0, __nv_bfloat16* L0,
                           __nv_bfloat16* H1, __nv_bfloat16* L1,
                           __nv_bfloat16* H2, __nv_bfloat16* L2,
                           __nv_bfloat16* H3, __nv_bfloat16* L3) {
    int which = blockIdx.y;
    const float* X = which == 0 ? S0 : which == 1 ? S1 : which == 2 ? S2 : S3;
    __nv_bfloat16* H = which == 0 ? H0 : which == 1 ? H1 : which == 2 ? H2 : H3;
    __nv_bfloat16* L = which == 0 ? L0 : which == 1 ? L1 : which == 2 ? L2 : L3;
    int i = (blockIdx.x * 256 + threadIdx.x) * 4;
    float4 v = *(const float4*)(X + i);
    uint32_t l0, l1;
    uint32_t h0 = pack_split(v.x, v.y, l0);
    uint32_t h1 = pack_split(v.z, v.w, l1);
    *(uint2*)((unsigned short*)H + i) = make_uint2(h0, h1);
    *(uint2*)((unsigned short*)L + i) = make_uint2(l0, l1);
}

// ======================= synchronous-staging 3xBF16 GEMM body (round-5/8 proven) =======================
#define KCn 64
#define LDT 72
#define TELEM (128 * LDT)
#define GSM (4 * TELEM * 2)          // 73728 bytes

template<bool ACC>
__device__ __forceinline__ void gemm_body(const __nv_bfloat16* __restrict__ gAh,
                                          const __nv_bfloat16* __restrict__ gAl,
                                          const __nv_bfloat16* __restrict__ gBh,
                                          const __nv_bfloat16* __restrict__ gBl,
                                          float* __restrict__ Yrow) {
    extern __shared__ __nv_bfloat16 sm[];
    __nv_bfloat16* sAh = sm;
    __nv_bfloat16* sAl = sm + TELEM;
    __nv_bfloat16* sBh = sm + 2 * TELEM;
    __nv_bfloat16* sBl = sm + 3 * TELEM;
    int tid = threadIdx.x, lane = tid & 31, wid = tid >> 5;
    int wm = wid >> 2, wn = wid & 3;

    float acc[4][4][4] = {};
    int lrow = tid >> 1;
    int lq   = (tid & 1) * 4;

    uint32_t sb = smem_u32(sm);
    int grp = lane >> 3, lr = lane & 7;
    int aRow = wm * 64 + (grp & 1) * 8 + lr;
    int aCol = (grp >> 1) * 8;
    int bRow = wn * 32 + (grp >> 1) * 8 + lr;
    int bCol = (grp & 1) * 8;

    for (int kc = 0; kc < 4; kc++) {
        if (kc) __syncthreads();
        const uint4* pa = (const uint4*)(gAh + (size_t)lrow * Fn + kc * KCn);
        const uint4* pb = (const uint4*)(gAl + (size_t)lrow * Fn + kc * KCn);
        const uint4* pc = (const uint4*)(gBh + (size_t)lrow * Fn + kc * KCn);
        const uint4* pd = (const uint4*)(gBl + (size_t)lrow * Fn + kc * KCn);
        uint4* qa = (uint4*)(sAh + lrow * LDT);
        uint4* qb = (uint4*)(sAl + lrow * LDT);
        uint4* qc = (uint4*)(sBh + lrow * LDT);
        uint4* qd = (uint4*)(sBl + lrow * LDT);
#pragma unroll
        for (int j = 0; j < 4; j++) {
            qa[lq + j] = pa[lq + j];
            qb[lq + j] = pb[lq + j];
            qc[lq + j] = pc[lq + j];
            qd[lq + j] = pd[lq + j];
        }
        __syncthreads();
#pragma unroll
        for (int ks = 0; ks < 4; ks++) {
            int k0 = ks * 16;
            uint32_t ah[4][4], al[4][4], bh[2][4], bl[2][4];
#pragma unroll
            for (int mi = 0; mi < 4; mi++) {
                uint32_t off = ((aRow + mi * 16) * LDT + aCol + k0) * 2;
                ldm_x4(ah[mi][0], ah[mi][1], ah[mi][2], ah[mi][3], sb + off);
                ldm_x4(al[mi][0], al[mi][1], al[mi][2], al[mi][3], sb + TELEM * 2 + off);
            }
#pragma unroll
            for (int nb = 0; nb < 2; nb++) {
                uint32_t off = ((bRow + nb * 16) * LDT + bCol + k0) * 2;
                ldm_x4(bh[nb][0], bh[nb][1], bh[nb][2], bh[nb][3], sb + TELEM * 4 + off);
                ldm_x4(bl[nb][0], bl[nb][1], bl[nb][2], bl[nb][3], sb + TELEM * 6 + off);
            }
#pragma unroll
            for (int mi = 0; mi < 4; mi++) {
#pragma unroll
                for (int nb = 0; nb < 2; nb++) {
                    mma_bf16(acc[mi][2*nb],   ah[mi], &bh[nb][0]);
                    mma_bf16(acc[mi][2*nb+1], ah[mi], &bh[nb][2]);
                    mma_bf16(acc[mi][2*nb],   ah[mi], &bl[nb][0]);
                    mma_bf16(acc[mi][2*nb+1], ah[mi], &bl[nb][2]);
                    mma_bf16(acc[mi][2*nb],   al[mi], &bh[nb][0]);
                    mma_bf16(acc[mi][2*nb+1], al[mi], &bh[nb][2]);
                }
            }
        }
    }

#pragma unroll
    for (int mi = 0; mi < 4; mi++) {
        int row = wm * 64 + mi * 16 + (lane >> 2);
#pragma unroll
        for (int ni = 0; ni < 4; ni++) {
            int col = wn * 32 + ni * 8 + (lane & 3) * 2;
            float* p0 = Yrow + (size_t)row * Wn + col;
            float* p1 = p0 + 8 * Wn;
            float2 v0 = make_float2(acc[mi][ni][0], acc[mi][ni][1]);
            float2 v1 = make_float2(acc[mi][ni][2], acc[mi][ni][3]);
            if (ACC) {
                float2 o0 = *(const float2*)p0, o1 = *(const float2*)p1;
                v0.x += o0.x; v0.y += o0.y; v1.x += o1.x; v1.y += o1.y;
            }
            *(float2*)p0 = v0;
            *(float2*)p1 = v1;
        }
    }
}

// batched Q/K/V projection GEMM: grid (4, 2, 48); z = which*16 + bc
__global__ void __launch_bounds__(256) gemm_qkv(
        const __nv_bfloat16* __restrict__ WqH_, const __nv_bfloat16* __restrict__ WqL_,
        const __nv_bfloat16* __restrict__ WkH_, const __nv_bfloat16* __restrict__ WkL_,
        const __nv_bfloat16* __restrict__ WvH_, const __nv_bfloat16* __restrict__ WvL_,
        const __nv_bfloat16* __restrict__ th, const __nv_bfloat16* __restrict__ tl,
        const __nv_bfloat16* __restrict__ mh, const __nv_bfloat16* __restrict__ ml,
        float* __restrict__ dst3) {
    int z = blockIdx.z;
    int which = z >> 4, bc = z & 15, c = bc & (Cn - 1);
    int tileM = blockIdx.y * 128, tileN = blockIdx.x * 128;
    const __nv_bfloat16* Ah = (which == 0 ? WqH_ : which == 1 ? WkH_ : WvH_) + ((size_t)c * Fn + tileM) * Fn;
    const __nv_bfloat16* Al = (which == 0 ? WqL_ : which == 1 ? WkL_ : WvL_) + ((size_t)c * Fn + tileM) * Fn;
    const __nv_bfloat16* Bh = (which == 0 ? th : mh) + ((size_t)bc * Wn + tileN) * Fn;
    const __nv_bfloat16* Bl = (which == 0 ? tl : ml) + ((size_t)bc * Wn + tileN) * Fn;
    float* Y = dst3 + (size_t)which * NB + ((size_t)bc * Fn + tileM) * Wn + tileN;
    gemm_body<false>(Ah, Al, Bh, Bl, Y);
}

// Wo GEMM, accumulating into h: grid (4, 2, 16)
__global__ void __launch_bounds__(256) gemm_wo(
        const __nv_bfloat16* __restrict__ AhG, const __nv_bfloat16* __restrict__ AlG,
        const __nv_bfloat16* __restrict__ BhG, const __nv_bfloat16* __restrict__ BlG,
        float* __restrict__ Y) {
    int bc = blockIdx.z, c = bc & (Cn - 1);
    int tileM = blockIdx.y * 128, tileN = blockIdx.x * 128;
    gemm_body<true>(AhG + ((size_t)c * Fn + tileM) * Fn,
                    AlG + ((size_t)c * Fn + tileM) * Fn,
                    BhG + ((size_t)bc * Wn + tileN) * Fn,
                    BlG + ((size_t)bc * Wn + tileN) * Fn,
                    Y + ((size_t)bc * Fn + tileM) * Wn + tileN);
}

// ======= batched conv3+bias (+RoPE) for Q/K/V: grid (4, 128, 6); z = which*2 + b =======
__global__ void __launch_bounds__(128) conv_qkv(const float* __restrict__ lin3,
                                                const float* __restrict__ Kcq, const float* __restrict__ bq,
                                                const float* __restrict__ Kck, const float* __restrict__ bk,
                                                const float* __restrict__ Kcv, const float* __restrict__ bv,
                                                uint2* __restrict__ qI, uint2* __restrict__ kI,
                                                __nv_bfloat16* __restrict__ vbf) {
    __shared__ float sIn[Cn][2][132];
    __shared__ float ks[Cn * Cn * 3];
    int tid = threadIdx.x;
    int zz = blockIdx.z;
    int which = zz >> 1, b = zz & 1;
    const float* Lin = lin3 + (size_t)which * NB;
    const float* Kc  = which == 0 ? Kcq : which == 1 ? Kck : Kcv;
    const float* bias = which == 0 ? bq : which == 1 ? bk : bv;
    int w0 = blockIdx.x * 128;
    int p  = blockIdx.y;
    int f0 = 2 * p;
    for (int t = tid; t < Cn * 2 * 130; t += 128) {
        int ci = t / 260, r = t % 260;
        int fi = r / 130, wo = r % 130;
        int gw = w0 + wo - 1;
        float v = (gw >= 0 && gw < Wn) ? Lin[((size_t)(b*Cn + ci) * Fn + f0 + fi) * Wn + gw] : 0.f;
        sIn[ci][fi][wo] = v;
    }
    for (int t = tid; t < Cn * Cn * 3; t += 128) ks[t] = Kc[t];
    __syncthreads();

    int w = w0 + tid;
    float cs = 1.f, sn = 0.f;
    if (which < 2) {
        int j = p & 15;
        float invf = exp10f(-0.25f * (float)j);
        sincosf((float)w * invf, &sn, &cs);
    }
    int h  = p >> 4;
    int jj = p & 15;
#pragma unroll
    for (int co = 0; co < Cn; co++) {
        float acc0 = bias[co], acc1 = acc0;
#pragma unroll
        for (int ci = 0; ci < Cn; ci++) {
            float k0 = ks[co*24 + ci*3], k1 = ks[co*24 + ci*3 + 1], k2 = ks[co*24 + ci*3 + 2];
            acc0 += k0 * sIn[ci][0][tid] + k1 * sIn[ci][0][tid+1] + k2 * sIn[ci][0][tid+2];
            acc1 += k0 * sIn[ci][1][tid] + k1 * sIn[ci][1][tid+1] + k2 * sIn[ci][1][tid+2];
        }
        size_t head = (size_t)(b*Cn + co) * Hn + h;
        size_t idx = (head * Wn + w) * 16 + jj;
        if (which < 2) {
            float o0 = acc0 * cs - acc1 * sn;
            float o1 = acc1 * cs + acc0 * sn;
            uint32_t lo, hi = pack_split(o0, o1, lo);
            (which == 0 ? qI : kI)[idx] = make_uint2(hi, lo);
        } else {
            ((__nv_bfloat162*)vbf)[idx] = __floats2bfloat162_rn(acc0, acc1);
        }
    }
}

// ======================= tensor-core flash attention (2-term QK) =======================
__global__ void __launch_bounds__(256, 1) attn_mma(const uint2* __restrict__ Qi,
                                                   const uint2* __restrict__ Ki,
                                                   const __nv_bfloat16* __restrict__ Vg,
                                                   __nv_bfloat16* __restrict__ AttH,
                                                   __nv_bfloat16* __restrict__ AttL) {
    __shared__ __nv_bfloat16 Kh[64][40];
    __shared__ __nv_bfloat16 Kl[64][40];
    __shared__ __nv_bfloat16 Vs[64][40];
    int head = blockIdx.x >> 1, half = blockIdx.x & 1;
    int tid = threadIdx.x, lane = tid & 31, wid = tid >> 5;
    int qb = half * 256 + wid * 32;
    size_t hbase = (size_t)head * Wn;

    uint32_t qh[2][2][4];
#pragma unroll
    for (int mi = 0; mi < 2; mi++) {
        int r0 = qb + mi * 16 + (lane >> 2);
#pragma unroll
        for (int kk = 0; kk < 2; kk++) {
            int jp = kk * 8 + (lane & 3);
            qh[mi][kk][0] = Qi[(hbase + r0) * 16 + jp].x;
            qh[mi][kk][1] = Qi[(hbase + r0 + 8) * 16 + jp].x;
            qh[mi][kk][2] = Qi[(hbase + r0) * 16 + jp + 4].x;
            qh[mi][kk][3] = Qi[(hbase + r0 + 8) * 16 + jp + 4].x;
        }
    }
    float m_[4] = {-1e30f, -1e30f, -1e30f, -1e30f};
    float l_[4] = {0.f, 0.f, 0.f, 0.f};
    float o[2][4][4] = {};
    uint32_t sbK = smem_u32(Kh), sbKl = smem_u32(Kl), sbV = smem_u32(Vs);
    int grp = lane >> 3, lr = lane & 7;

    for (int kt = 0; kt < 8; kt++) {
        int kb = kt * 64;
        __syncthreads();
#pragma unroll
        for (int it = 0; it < 4; it++) {
            int idx = tid + it * 256;
            int row = idx >> 4, j = idx & 15;
            uint2 v = Ki[(hbase + kb + row) * 16 + j];
            ((uint32_t*)&Kh[row][0])[j] = v.x;
            ((uint32_t*)&Kl[row][0])[j] = v.y;
        }
        {
            int row = tid >> 2, q = tid & 3;
            uint4 v = ((const uint4*)(Vg + (hbase + kb + row) * HDn))[q];
            *((uint4*)&Vs[row][q * 8]) = v;
        }
        __syncthreads();

        float s[2][8][4] = {};
#pragma unroll
        for (int kk = 0; kk < 2; kk++) {
#pragma unroll
            for (int nb = 0; nb < 4; nb++) {
                uint32_t kh4[4], kl4[4];
                uint32_t off = ((nb * 16 + (grp >> 1) * 8 + lr) * 40 + (grp & 1) * 8 + kk * 16) * 2;
                ldm_x4(kh4[0], kh4[1], kh4[2], kh4[3], sbK + off);
                ldm_x4(kl4[0], kl4[1], kl4[2], kl4[3], sbKl + off);
#pragma unroll
                for (int mi = 0; mi < 2; mi++) {
                    mma_bf16(s[mi][2*nb],   qh[mi][kk], &kh4[0]);
                    mma_bf16(s[mi][2*nb+1], qh[mi][kk], &kh4[2]);
                    mma_bf16(s[mi][2*nb],   qh[mi][kk], &kl4[0]);
                    mma_bf16(s[mi][2*nb+1], qh[mi][kk], &kl4[2]);
                }
            }
        }

        uint32_t pa[2][4][4];
#pragma unroll
        for (int mi = 0; mi < 2; mi++) {
            float mx0 = -1e30f, mx1 = -1e30f;
#pragma unroll
            for (int n = 0; n < 8; n++) {
#pragma unroll
                for (int q = 0; q < 4; q++) s[mi][n][q] *= 0.0625f;
                mx0 = fmaxf(mx0, fmaxf(s[mi][n][0], s[mi][n][1]));
                mx1 = fmaxf(mx1, fmaxf(s[mi][n][2], s[mi][n][3]));
            }
            mx0 = fmaxf(mx0, __shfl_xor_sync(0xffffffffu, mx0, 1));
            mx0 = fmaxf(mx0, __shfl_xor_sync(0xffffffffu, mx0, 2));
            mx1 = fmaxf(mx1, __shfl_xor_sync(0xffffffffu, mx1, 1));
            mx1 = fmaxf(mx1, __shfl_xor_sync(0xffffffffu, mx1, 2));
            int si = mi * 2;
            float mn0 = fmaxf(m_[si], mx0), mn1 = fmaxf(m_[si+1], mx1);
            float c0 = __expf(m_[si] - mn0), c1 = __expf(m_[si+1] - mn1);
            m_[si] = mn0; m_[si+1] = mn1;
            float ls0 = 0.f, ls1 = 0.f;
#pragma unroll
            for (int n = 0; n < 8; n++) {
                float p0 = __expf(s[mi][n][0] - mn0);
                float p1 = __expf(s[mi][n][1] - mn0);
                float p2 = __expf(s[mi][n][2] - mn1);
                float p3 = __expf(s[mi][n][3] - mn1);
                ls0 += p0 + p1; ls1 += p2 + p3;
                s[mi][n][0] = p0; s[mi][n][1] = p1; s[mi][n][2] = p2; s[mi][n][3] = p3;
            }
            ls0 += __shfl_xor_sync(0xffffffffu, ls0, 1);
            ls0 += __shfl_xor_sync(0xffffffffu, ls0, 2);
            ls1 += __shfl_xor_sync(0xffffffffu, ls1, 1);
            ls1 += __shfl_xor_sync(0xffffffffu, ls1, 2);
            l_[si]   = l_[si]   * c0 + ls0;
            l_[si+1] = l_[si+1] * c1 + ls1;
#pragma unroll
            for (int dn = 0; dn < 4; dn++) {
                o[mi][dn][0] *= c0; o[mi][dn][1] *= c0;
                o[mi][dn][2] *= c1; o[mi][dn][3] *= c1;
            }
#pragma unroll
            for (int t = 0; t < 4; t++) {
                pa[mi][t][0] = packbf(s[mi][2*t][0],   s[mi][2*t][1]);
                pa[mi][t][1] = packbf(s[mi][2*t][2],   s[mi][2*t][3]);
                pa[mi][t][2] = packbf(s[mi][2*t+1][0], s[mi][2*t+1][1]);
                pa[mi][t][3] = packbf(s[mi][2*t+1][2], s[mi][2*t+1][3]);
            }
        }

#pragma unroll
        for (int dn = 0; dn < 4; dn++) {
            uint32_t vb[4][2];
#pragma unroll
            for (int t = 0; t < 4; t++) {
                uint32_t off = ((t * 16 + (lane & 15)) * 40 + dn * 8) * 2;
                ldm_x2_trans(vb[t][0], vb[t][1], sbV + off);
            }
#pragma unroll
            for (int mi = 0; mi < 2; mi++)
#pragma unroll
                for (int t = 0; t < 4; t++)
                    mma_bf16(o[mi][dn], pa[mi][t], vb[t]);
        }
    }

    int bc = head >> 3, hh = head & 7;
#pragma unroll
    for (int mi = 0; mi < 2; mi++) {
        int r0 = qb + mi * 16 + (lane >> 2);
        float i0 = 1.0f / l_[mi*2], i1 = 1.0f / l_[mi*2 + 1];
#pragma unroll
        for (int dn = 0; dn < 4; dn++) {
            int d0 = dn * 8 + (lane & 3) * 2;
            size_t a0 = ((size_t)bc * Wn + r0) * Fn + hh * HDn + d0;
            size_t a1 = ((size_t)bc * Wn + r0 + 8) * Fn + hh * HDn + d0;
            uint32_t lo0, hi0 = pack_split(o[mi][dn][0] * i0, o[mi][dn][1] * i0, lo0);
            uint32_t lo1, hi1 = pack_split(o[mi][dn][2] * i1, o[mi][dn][3] * i1, lo1);
            *(uint32_t*)(AttH + a0) = hi0;
            *(uint32_t*)(AttL + a0) = lo0;
            *(uint32_t*)(AttH + a1) = hi1;
            *(uint32_t*)(AttL + a1) = lo1;
        }
    }
}

// ======================= smem-tiled depthwise convs =======================
__global__ void __launch_bounds__(256) frameconv_ab_t(const float* __restrict__ Z,
                                                      const float* __restrict__ k11, const float* __restrict__ b11,
                                                      const float* __restrict__ k7,  const float* __restrict__ b7,
                                                      float* __restrict__ Yo) {
    extern __shared__ float sZ[];
    int tid = threadIdx.x;
    int bc = blockIdx.y, c = bc & (Cn - 1);
    int w0 = blockIdx.x * 64;
    const float* zp = Z + (size_t)bc * Fn * Wn + w0;
    for (int i = tid; i < Fn * 64; i += 256)
        sZ[i] = zp[(size_t)(i >> 6) * Wn + (i & 63)];
    __syncthreads();
    float wk11[11], wk7[7];
#pragma unroll
    for (int t = 0; t < 11; t++) wk11[t] = k11[c * 11 + t];
#pragma unroll
    for (int t = 0; t < 7; t++)  wk7[t]  = k7[c * 7 + t];
    float bb11 = b11[c], bb7 = b7[c];
    int w = tid & 63, fg = tid >> 6;
    float* yo = Yo + (size_t)bc * Fn * Wn + w0 + w;
    for (int f = fg * 64; f < fg * 64 + 64; f++) {
        float a = bb11;
#pragma unroll
        for (int t = 0; t < 11; t++) {
            int ff = f - 5 + t;
            if (ff >= 0 && ff < Fn) a += sZ[ff * 64 + w] * wk11[t];
        }
        a = fmaxf(a, 0.f); a = a * a;
        float bo = bb7;
#pragma unroll
        for (int t = 0; t < 7; t++) {
            int ff = f - 3 + t;
            if (ff >= 0 && ff < Fn) bo += sZ[ff * 64 + w] * wk7[t];
        }
        yo[(size_t)f * Wn] = a + bo;
    }
}

__global__ void __launch_bounds__(256) frameconv2_t(const float* __restrict__ S,
                                                    const float* __restrict__ k7, const float* __restrict__ b7,
                                                    float* __restrict__ Hb) {
    extern __shared__ float sZ[];
    int tid = threadIdx.x;
    int bc = blockIdx.y, c = bc & (Cn - 1);
    int w0 = blockIdx.x * 64;
    const float* sp = S + (size_t)bc * Fn * Wn + w0;
    for (int i = tid; i < Fn * 64; i += 256)
        sZ[i] = sp[(size_t)(i >> 6) * Wn + (i & 63)];
    __syncthreads();
    float wk7[7];
#pragma unroll
    for (int t = 0; t < 7; t++) wk7[t] = k7[c * 7 + t];
    float bb7 = b7[c];
    int w = tid & 63, fg = tid >> 6;
    float* hb = Hb + (size_t)bc * Fn * Wn + w0 + w;
    for (int f = fg * 64; f < fg * 64 + 64; f++) {
        float v = bb7;
#pragma unroll
        for (int t = 0; t < 7; t++) {
            int ff = f - 3 + t;
            if (ff >= 0 && ff < Fn) v += sZ[ff * 64 + w] * wk7[t];
        }
        hb[(size_t)f * Wn] += v;
    }
}

// ======================= misc / FFN / output =======================
__global__ void copy_x(const float* __restrict__ X, float* __restrict__ Hb) {
    int i = blockIdx.x * 256 + threadIdx.x;
    ((float4*)Hb)[i] = ((const float4*)X)[i];
}

// high-occupancy FFN3: grid (Wn/64, Bn*Cn), block 256 = (64 w, 4 f-groups)
__global__ void __launch_bounds__(256) ffn3_v2(const float* __restrict__ Z,
                                               const float* __restrict__ w3,
                                               float* __restrict__ T) {
    __shared__ float ws[En * Fn];
    __shared__ float pacc[4][En][64];
    int tid = threadIdx.x, w = tid & 63, fg = tid >> 6;
    int bc = blockIdx.y, c = bc & (Cn - 1);
    int w0 = blockIdx.x * 64;
    for (int i = tid; i < En * Fn; i += 256) ws[i] = w3[c * En * Fn + i];
    __syncthreads();
    const float* zp = Z + (size_t)bc * Fn * Wn + w0 + w;
    float acc[En] = {};
#pragma unroll 4
    for (int f = fg * 64; f < fg * 64 + 64; f++) {
        float zv = zp[(size_t)f * Wn];
#pragma unroll
        for (int e = 0; e < En; e++) acc[e] += zv * ws[e * Fn + f];
    }
#pragma unroll
    for (int e = 0; e < En; e++) pacc[fg][e][w] = acc[e];
    __syncthreads();
    if (fg == 0) {
        float* tp = T + (size_t)bc * En * Wn + w0 + w;
#pragma unroll
        for (int e = 0; e < En; e++) {
            float v = pacc[0][e][w] + pacc[1][e][w] + pacc[2][e][w] + pacc[3][e][w];
            v = fmaxf(v, 0.f);
            tp[(size_t)e * Wn] = v * v;
        }
    }
}

__global__ void ffn4_add(const float* __restrict__ T, const float* __restrict__ w4,
                         float* __restrict__ Hb) {
    int idx = blockIdx.x * 256 + threadIdx.x;
    int w  = idx & (Wn - 1);
    int f  = (idx >> 9) & (Fn - 1);
    int bc = idx >> 17;
    int c  = bc & (Cn - 1);
    const float* tp = T + (size_t)bc * En * Wn + w;
    const float* wp = w4 + ((size_t)c * Fn + f) * En;
    float v = tp[0] * wp[0] + tp[Wn] * wp[1] + tp[2 * Wn] * wp[2] + tp[3 * Wn] * wp[3];
    Hb[idx] += v;
}

__global__ void write_out(const float* __restrict__ X, const float* __restrict__ Hb,
                          float* __restrict__ O) {
    int idx = blockIdx.x * 256 + threadIdx.x;
    int b = idx / (Cn * Fn * Wn);
    int r = idx - b * (Cn * Fn * Wn);
    O[(size_t)b * 2 * Cn * Fn * Wn + r] = X[idx];
    O[(size_t)b * 2 * Cn * Fn * Wn + Cn * Fn * Wn + r] = Hb[idx];
}

// =====================================================================================

extern "C" void kernel_launch(void* const* d_in, const int* in_sizes, int n_in,
                              void* d_out, int out_size) {
    const float* x     = (const float*)d_in[0];
    const float* skip  = (const float*)d_in[1];
    const float* Wq    = (const float*)d_in[2];
    const float* Kq    = (const float*)d_in[3];
    const float* bq    = (const float*)d_in[4];
    const float* Wk    = (const float*)d_in[5];
    const float* Kk    = (const float*)d_in[6];
    const float* bk    = (const float*)d_in[7];
    const float* Wv    = (const float*)d_in[8];
    const float* Kv    = (const float*)d_in[9];
    const float* bv    = (const float*)d_in[10];
    const float* Wo    = (const float*)d_in[11];
    const float* ng    = (const float*)d_in[12];
    const float* nbet  = (const float*)d_in[13];
    const float* c1a_w = (const float*)d_in[14];
    const float* c1a_b = (const float*)d_in[15];
    const float* c1b_w = (const float*)d_in[16];
    const float* c1b_b = (const float*)d_in[17];
    const float* c2_w  = (const float*)d_in[18];
    const float* c2_b  = (const float*)d_in[19];
    const float* w3    = (const float*)d_in[20];
    const float* w4    = (const float*)d_in[21];
    float* out = (float*)d_out;

    float *hB, *zB, *lin3B, *t1B, *ffnB;
    cudaGetSymbolAddress((void**)&hB,    g_h);
    cudaGetSymbolAddress((void**)&zB,    g_z);
    cudaGetSymbolAddress((void**)&lin3B, g_lin3);
    cudaGetSymbolAddress((void**)&t1B,   g_t1);
    cudaGetSymbolAddress((void**)&ffnB,  g_ffn);
    uint2 *qI, *kI;
    __nv_bfloat16 *vBf;
    cudaGetSymbolAddress((void**)&qI,  g_qI);
    cudaGetSymbolAddress((void**)&kI,  g_kI);
    cudaGetSymbolAddress((void**)&vBf, g_vbf);
    __nv_bfloat16 *zTh, *zTl, *skTh, *skTl, *atTh, *atTl;
    __nv_bfloat16 *WqH, *WqL, *WkH, *WkL, *WvH, *WvL, *WoH, *WoL;
    cudaGetSymbolAddress((void**)&zTh,  g_zTh);  cudaGetSymbolAddress((void**)&zTl,  g_zTl);
    cudaGetSymbolAddress((void**)&skTh, g_skTh); cudaGetSymbolAddress((void**)&skTl, g_skTl);
    cudaGetSymbolAddress((void**)&atTh, g_atTh); cudaGetSymbolAddress((void**)&atTl, g_atTl);
    cudaGetSymbolAddress((void**)&WqH, g_WqH); cudaGetSymbolAddress((void**)&WqL, g_WqL);
    cudaGetSymbolAddress((void**)&WkH, g_WkH); cudaGetSymbolAddress((void**)&WkL, g_WkL);
    cudaGetSymbolAddress((void**)&WvH, g_WvH); cudaGetSymbolAddress((void**)&WvL, g_WvL);
    cudaGetSymbolAddress((void**)&WoH, g_WoH); cudaGetSymbolAddress((void**)&WoL, g_WoL);

    cudaFuncSetAttribute(gemm_qkv, cudaFuncAttributeMaxDynamicSharedMemorySize, GSM);
    cudaFuncSetAttribute(gemm_wo,  cudaFuncAttributeMaxDynamicSharedMemorySize, GSM);
    cudaFuncSetAttribute(frameconv_ab_t, cudaFuncAttributeMaxDynamicSharedMemorySize, Fn*64*4);
    cudaFuncSetAttribute(frameconv2_t,   cudaFuncAttributeMaxDynamicSharedMemorySize, Fn*64*4);

    const int nElemBlocks = NB / 256;
    const int wBlocks = (4 * WOFF) / 1024;
    const dim3 gLN(Wn / 64, Bn * Cn);

    wsplit_all<<<dim3(wBlocks, 4), 256>>>(Wq, Wk, Wv, Wo,
                                          WqH, WqL, WkH, WkL, WvH, WvL, WoH, WoL);
    tsplit_kernel<<<dim3(Wn/32, Fn/32, Bn*Cn), dim3(32, 8)>>>(skip, skTh, skTl);
    copy_x<<<NB / 1024, 256>>>(x, hB);

    auto run_ln = [&](const float* X, int gi, float* Yb) {
        ln_v2<<<gLN, 256>>>(X, ng + gi * Cn * Fn, nbet + gi * Cn * Fn, Yb);
    };
    auto run_ln_t = [&](const float* X, int gi) {
        ln_t_v2<<<gLN, 256>>>(X, ng + gi * Cn * Fn, nbet + gi * Cn * Fn, zTh, zTl);
    };

    auto run_attn = [&](int i, const __nv_bfloat16* th, const __nv_bfloat16* tl,
                        const __nv_bfloat16* mh, const __nv_bfloat16* ml) {
        size_t wo = (size_t)i * WOFF;
        size_t ko = (size_t)i * Cn * Cn * 3;
        gemm_qkv<<<dim3(4, 2, 48), 256, GSM>>>(WqH + wo, WqL + wo, WkH + wo, WkL + wo,
                                               WvH + wo, WvL + wo, th, tl, mh, ml, lin3B);
        conv_qkv<<<dim3(4, 128, 6), 128>>>(lin3B, Kq + ko, bq + i * Cn,
                                           Kk + ko, bk + i * Cn, Kv + ko, bv + i * Cn,
                                           qI, kI, vBf);
        attn_mma<<<NHEAD * 2, 256>>>(qI, kI, vBf, atTh, atTl);
        gemm_wo<<<dim3(4, 2, 16), 256, GSM>>>(WoH + wo, WoL + wo, atTh, atTl, hB);
    };

    // h = x + att0(z,z) + att1(z,skip), z = LN0(x)
    run_ln_t(x, 0);
    run_attn(0, zTh, zTl, zTh, zTl);
    run_attn(1, zTh, zTl, skTh, skTl);

    // conv block
    run_ln(hB, 1, zB);
    frameconv_ab_t<<<dim3(Wn/64, Bn*Cn), 256, Fn*64*4>>>(zB, c1a_w, c1a_b, c1b_w, c1b_b, t1B);
    run_ln(t1B, 2, zB);
    frameconv2_t<<<dim3(Wn/64, Bn*Cn), 256, Fn*64*4>>>(zB, c2_w, c2_b, hB);

    // h += att2(LN3(h), same)
    run_ln_t(hB, 3);
    run_attn(2, zTh, zTl, zTh, zTl);

    // h += att3(LN4(h), skip)
    run_ln_t(hB, 4);
    run_attn(3, zTh, zTl, skTh, skTl);

    // FFN
    run_ln(hB, 5, zB);
    ffn3_v2<<<gLN, 256>>>(zB, w3, ffnB);
    ffn4_add<<<nElemBlocks, 256>>>(ffnB, w4, hB);

    // concat(x, h)
    write_out<<<nElemBlocks, 256>>>(x, hB, out);
}

// round 10
// speedup vs baseline: 2.8149x; 1.0405x over previous
#include <cuda_runtime.h>
#include <cuda_bf16.h>
#include <math.h>
#include <stdint.h>

#define Bn 2
#define Cn 8
#define Fn 256
#define Wn 512
#define Hn 8
#define HDn 32
#define En 4
#define NB (Bn*Cn*Fn*Wn)
#define WOFF (Cn*Fn*Fn)
#define NHEAD (Bn*Cn*Hn)

// ======================= warp-MMA helpers (baseline PTX, sm_80+) =======================
__device__ __forceinline__ uint32_t smem_u32(const void* p) {
    uint32_t a;
    asm("{ .reg .u64 t; cvta.to.shared.u64 t, %1; cvt.u32.u64 %0, t; }" : "=r"(a) : "l"(p));
    return a;
}
__device__ __forceinline__ void ldm_x4(uint32_t& r0, uint32_t& r1, uint32_t& r2, uint32_t& r3,
                                       uint32_t addr) {
    asm volatile("ldmatrix.sync.aligned.m8n8.x4.shared.b16 {%0,%1,%2,%3}, [%4];"
                 : "=r"(r0), "=r"(r1), "=r"(r2), "=r"(r3) : "r"(addr));
}
__device__ __forceinline__ void ldm_x2_trans(uint32_t& r0, uint32_t& r1, uint32_t addr) {
    asm volatile("ldmatrix.sync.aligned.m8n8.x2.trans.shared.b16 {%0,%1}, [%2];"
                 : "=r"(r0), "=r"(r1) : "r"(addr));
}
__device__ __forceinline__ void mma_bf16(float* d, const uint32_t* a, const uint32_t* b) {
    asm volatile("mma.sync.aligned.m16n8k16.row.col.f32.bf16.bf16.f32 "
                 "{%0,%1,%2,%3}, {%4,%5,%6,%7}, {%8,%9}, {%0,%1,%2,%3};"
                 : "+f"(d[0]), "+f"(d[1]), "+f"(d[2]), "+f"(d[3])
                 : "r"(a[0]), "r"(a[1]), "r"(a[2]), "r"(a[3]), "r"(b[0]), "r"(b[1]));
}
__device__ __forceinline__ uint32_t pack_split(float a, float b, uint32_t& lo) {
    __nv_bfloat16 ha = __float2bfloat16(a), hb = __float2bfloat16(b);
    __nv_bfloat16 la = __float2bfloat16(a - __bfloat162float(ha));
    __nv_bfloat16 lb = __float2bfloat16(b - __bfloat162float(hb));
    lo = (uint32_t)__bfloat16_as_ushort(la) | ((uint32_t)__bfloat16_as_ushort(lb) << 16);
    return (uint32_t)__bfloat16_as_ushort(ha) | ((uint32_t)__bfloat16_as_ushort(hb) << 16);
}
__device__ __forceinline__ uint32_t packbf(float a, float b) {
    __nv_bfloat162 v = __floats2bfloat162_rn(a, b);
    return *(uint32_t*)&v;
}

// ======================= scratch (device globals) =======================
__device__ float g_h[NB];
__device__ float g_lin3[3*NB];
__device__ float g_t1[NB];
__device__ float g_ffn[Bn*Cn*En*Wn];
__device__ uint2 g_qI[NHEAD*Wn*16];
__device__ uint2 g_kI[NHEAD*Wn*16];
__device__ __nv_bfloat16 g_vbf[NHEAD*Wn*HDn];
__device__ __nv_bfloat16 g_zTh[Bn*Cn*Wn*Fn];
__device__ __nv_bfloat16 g_zTl[Bn*Cn*Wn*Fn];
__device__ __nv_bfloat16 g_skTh[Bn*Cn*Wn*Fn];
__device__ __nv_bfloat16 g_skTl[Bn*Cn*Wn*Fn];
__device__ __nv_bfloat16 g_atTh[Bn*Cn*Wn*Fn];
__device__ __nv_bfloat16 g_atTl[Bn*Cn*Wn*Fn];
__device__ __nv_bfloat16 g_WqH[4*WOFF]; __device__ __nv_bfloat16 g_WqL[4*WOFF];
__device__ __nv_bfloat16 g_WkH[4*WOFF]; __device__ __nv_bfloat16 g_WkL[4*WOFF];
__device__ __nv_bfloat16 g_WvH[4*WOFF]; __device__ __nv_bfloat16 g_WvL[4*WOFF];
__device__ __nv_bfloat16 g_WoH[4*WOFF]; __device__ __nv_bfloat16 g_WoL[4*WOFF];

// ============ high-occupancy LayerNorm -> transposed bf16 hi/lo; grid (16, 16), blk 256 ============
__global__ void __launch_bounds__(256) ln_t_v3(const float* __restrict__ X,
                                               const float* __restrict__ gam,
                                               const float* __restrict__ bet,
                                               __nv_bfloat16* __restrict__ Zh,
                                               __nv_bfloat16* __restrict__ Zl) {
    __shared__ float ps[8][32], ps2[8][32], mb[32], ib[32];
    int tid = threadIdx.x, w = tid & 31, fg = tid >> 5;
    int bc = blockIdx.y, c = bc & (Cn - 1);
    int w0 = blockIdx.x * 32;
    const float* xp = X + (size_t)bc * Fn * Wn + w0 + w;
    float s = 0.f, s2 = 0.f;
#pragma unroll 4
    for (int f = fg * 32; f < fg * 32 + 32; f++) {
        float v = xp[(size_t)f * Wn];
        s += v; s2 += v * v;
    }
    ps[fg][w] = s; ps2[fg][w] = s2;
    __syncthreads();
    if (tid < 32) {
        float S = 0.f, S2 = 0.f;
#pragma unroll
        for (int g = 0; g < 8; g++) { S += ps[g][tid]; S2 += ps2[g][tid]; }
        float m = S * (1.0f / Fn);
        mb[tid] = m;
        ib[tid] = rsqrtf(S2 * (1.0f / Fn) - m * m + 1e-5f);
    }
    __syncthreads();
    float m = mb[w], inv = ib[w];
    const float* gp = gam + c * Fn;
    const float* bp = bet + c * Fn;
    __nv_bfloat16* th = Zh + ((size_t)bc * Wn + w0 + w) * Fn;
    __nv_bfloat16* tl = Zl + ((size_t)bc * Wn + w0 + w) * Fn;
    for (int f0 = fg * 32; f0 < fg * 32 + 32; f0 += 8) {
        uint32_t ph[4], pl[4];
#pragma unroll
        for (int j = 0; j < 4; j++) {
            int f = f0 + 2 * j;
            float v0 = (xp[(size_t)f * Wn]     - m) * inv * gp[f]   + bp[f];
            float v1 = (xp[(size_t)(f+1) * Wn] - m) * inv * gp[f+1] + bp[f+1];
            ph[j] = pack_split(v0, v1, pl[j]);
        }
        *(uint4*)(th + f0) = make_uint4(ph[0], ph[1], ph[2], ph[3]);
        *(uint4*)(tl + f0) = make_uint4(pl[0], pl[1], pl[2], pl[3]);
    }
}

// ============ transpose + split: (b,c,f,w) fp32 -> [bc][w][f] bf16 hi/lo ============
__global__ void tsplit_kernel(const float* __restrict__ X,
                              __nv_bfloat16* __restrict__ Th, __nv_bfloat16* __restrict__ Tl) {
    __shared__ float t[32][33];
    int bc = blockIdx.z;
    int w0 = blockIdx.x * 32, f0 = blockIdx.y * 32;
    const float* xp = X + ((size_t)bc * Fn + f0) * Wn + w0;
#pragma unroll
    for (int i = 0; i < 4; i++) {
        int fr = threadIdx.y + i * 8;
        t[fr][threadIdx.x] = xp[(size_t)fr * Wn + threadIdx.x];
    }
    __syncthreads();
#pragma unroll
    for (int i = 0; i < 4; i++) {
        int wr = threadIdx.y + i * 8;
        float v = t[threadIdx.x][wr];
        __nv_bfloat16 h = __float2bfloat16(v);
        __nv_bfloat16 l = __float2bfloat16(v - __bfloat162float(h));
        size_t idx = ((size_t)bc * Wn + w0 + wr) * Fn + f0 + threadIdx.x;
        Th[idx] = h; Tl[idx] = l;
    }
}

// ============ weight split: all four weight tensors in one launch ============
__global__ void wsplit_all(const float* __restrict__ S0, const float* __restrict__ S1,
                           const float* __restrict__ S2, const float* __restrict__ S3,
                           __nv_bfloat16* H0, __nv_bfloat16* L0,
                           __nv_bfloat16* H1, __nv_bfloat16* L1,
                           __nv_bfloat16* H2, __nv_bfloat16* L2,
                           __nv_bfloat16* H3, __nv_bfloat16* L3) {
    int which = blockIdx.y;
    const float* X = which == 0 ? S0 : which == 1 ? S1 : which == 2 ? S2 : S3;
    __nv_bfloat16* H = which == 0 ? H0 : which == 1 ? H1 : which == 2 ? H2 : H3;
    __nv_bfloat16* L = which == 0 ? L0 : which == 1 ? L1 : which == 2 ? L2 : L3;
    int i = (blockIdx.x * 256 + threadIdx.x) * 4;
    float4 v = *(const float4*)(X + i);
    uint32_t l0, l1;
    uint32_t h0 = pack_split(v.x, v.y, l0);
    uint32_t h1 = pack_split(v.z, v.w, l1);
    *(uint2*)((unsigned short*)H + i) = make_uint2(h0, h1);
    *(uint2*)((unsigned short*)L + i) = make_uint2(l0, l1);
}

// ======================= synchronous-staging 3xBF16 GEMM body (round-8/9 proven) =======================
#define KCn 64
#define LDT 72
#define TELEM (128 * LDT)
#define GSM (4 * TELEM * 2)          // 73728 bytes

template<bool ACC>
__device__ __forceinline__ void gemm_body(const __nv_bfloat16* __restrict__ gAh,
                                          const __nv_bfloat16* __restrict__ gAl,
                                          const __nv_bfloat16* __restrict__ gBh,
                                          const __nv_bfloat16* __restrict__ gBl,
                                          float* __restrict__ Yrow) {
    extern __shared__ __nv_bfloat16 sm[];
    __nv_bfloat16* sAh = sm;
    __nv_bfloat16* sAl = sm + TELEM;
    __nv_bfloat16* sBh = sm + 2 * TELEM;
    __nv_bfloat16* sBl = sm + 3 * TELEM;
    int tid = threadIdx.x, lane = tid & 31, wid = tid >> 5;
    int wm = wid >> 2, wn = wid & 3;

    float acc[4][4][4] = {};
    int lrow = tid >> 1;
    int lq   = (tid & 1) * 4;

    uint32_t sb = smem_u32(sm);
    int grp = lane >> 3, lr = lane & 7;
    int aRow = wm * 64 + (grp & 1) * 8 + lr;
    int aCol = (grp >> 1) * 8;
    int bRow = wn * 32 + (grp >> 1) * 8 + lr;
    int bCol = (grp & 1) * 8;

    for (int kc = 0; kc < 4; kc++) {
        if (kc) __syncthreads();
        const uint4* pa = (const uint4*)(gAh + (size_t)lrow * Fn + kc * KCn);
        const uint4* pb = (const uint4*)(gAl + (size_t)lrow * Fn + kc * KCn);
        const uint4* pc = (const uint4*)(gBh + (size_t)lrow * Fn + kc * KCn);
        const uint4* pd = (const uint4*)(gBl + (size_t)lrow * Fn + kc * KCn);
        uint4* qa = (uint4*)(sAh + lrow * LDT);
        uint4* qb = (uint4*)(sAl + lrow * LDT);
        uint4* qc = (uint4*)(sBh + lrow * LDT);
        uint4* qd = (uint4*)(sBl + lrow * LDT);
#pragma unroll
        for (int j = 0; j < 4; j++) {
            qa[lq + j] = pa[lq + j];
            qb[lq + j] = pb[lq + j];
            qc[lq + j] = pc[lq + j];
            qd[lq + j] = pd[lq + j];
        }
        __syncthreads();
#pragma unroll
        for (int ks = 0; ks < 4; ks++) {
            int k0 = ks * 16;
            uint32_t ah[4][4], al[4][4], bh[2][4], bl[2][4];
#pragma unroll
            for (int mi = 0; mi < 4; mi++) {
                uint32_t off = ((aRow + mi * 16) * LDT + aCol + k0) * 2;
                ldm_x4(ah[mi][0], ah[mi][1], ah[mi][2], ah[mi][3], sb + off);
                ldm_x4(al[mi][0], al[mi][1], al[mi][2], al[mi][3], sb + TELEM * 2 + off);
            }
#pragma unroll
            for (int nb = 0; nb < 2; nb++) {
                uint32_t off = ((bRow + nb * 16) * LDT + bCol + k0) * 2;
                ldm_x4(bh[nb][0], bh[nb][1], bh[nb][2], bh[nb][3], sb + TELEM * 4 + off);
                ldm_x4(bl[nb][0], bl[nb][1], bl[nb][2], bl[nb][3], sb + TELEM * 6 + off);
            }
#pragma unroll
            for (int mi = 0; mi < 4; mi++) {
#pragma unroll
                for (int nb = 0; nb < 2; nb++) {
                    mma_bf16(acc[mi][2*nb],   ah[mi], &bh[nb][0]);
                    mma_bf16(acc[mi][2*nb+1], ah[mi], &bh[nb][2]);
                    mma_bf16(acc[mi][2*nb],   ah[mi], &bl[nb][0]);
                    mma_bf16(acc[mi][2*nb+1], ah[mi], &bl[nb][2]);
                    mma_bf16(acc[mi][2*nb],   al[mi], &bh[nb][0]);
                    mma_bf16(acc[mi][2*nb+1], al[mi], &bh[nb][2]);
                }
            }
        }
    }

#pragma unroll
    for (int mi = 0; mi < 4; mi++) {
        int row = wm * 64 + mi * 16 + (lane >> 2);
#pragma unroll
        for (int ni = 0; ni < 4; ni++) {
            int col = wn * 32 + ni * 8 + (lane & 3) * 2;
            float* p0 = Yrow + (size_t)row * Wn + col;
            float* p1 = p0 + 8 * Wn;
            float2 v0 = make_float2(acc[mi][ni][0], acc[mi][ni][1]);
            float2 v1 = make_float2(acc[mi][ni][2], acc[mi][ni][3]);
            if (ACC) {
                float2 o0 = *(const float2*)p0, o1 = *(const float2*)p1;
                v0.x += o0.x; v0.y += o0.y; v1.x += o1.x; v1.y += o1.y;
            }
            *(float2*)p0 = v0;
            *(float2*)p1 = v1;
        }
    }
}

// batched Q/K/V projection GEMM: grid (4, 2, 48); z = which*16 + bc
__global__ void __launch_bounds__(256) gemm_qkv(
        const __nv_bfloat16* __restrict__ WqH_, const __nv_bfloat16* __restrict__ WqL_,
        const __nv_bfloat16* __restrict__ WkH_, const __nv_bfloat16* __restrict__ WkL_,
        const __nv_bfloat16* __restrict__ WvH_, const __nv_bfloat16* __restrict__ WvL_,
        const __nv_bfloat16* __restrict__ th, const __nv_bfloat16* __restrict__ tl,
        const __nv_bfloat16* __restrict__ mh, const __nv_bfloat16* __restrict__ ml,
        float* __restrict__ dst3) {
    int z = blockIdx.z;
    int which = z >> 4, bc = z & 15, c = bc & (Cn - 1);
    int tileM = blockIdx.y * 128, tileN = blockIdx.x * 128;
    const __nv_bfloat16* Ah = (which == 0 ? WqH_ : which == 1 ? WkH_ : WvH_) + ((size_t)c * Fn + tileM) * Fn;
    const __nv_bfloat16* Al = (which == 0 ? WqL_ : which == 1 ? WkL_ : WvL_) + ((size_t)c * Fn + tileM) * Fn;
    const __nv_bfloat16* Bh = (which == 0 ? th : mh) + ((size_t)bc * Wn + tileN) * Fn;
    const __nv_bfloat16* Bl = (which == 0 ? tl : ml) + ((size_t)bc * Wn + tileN) * Fn;
    float* Y = dst3 + (size_t)which * NB + ((size_t)bc * Fn + tileM) * Wn + tileN;
    gemm_body<false>(Ah, Al, Bh, Bl, Y);
}

// Wo GEMM, accumulating into h: grid (4, 2, 16)
__global__ void __launch_bounds__(256) gemm_wo(
        const __nv_bfloat16* __restrict__ AhG, const __nv_bfloat16* __restrict__ AlG,
        const __nv_bfloat16* __restrict__ BhG, const __nv_bfloat16* __restrict__ BlG,
        float* __restrict__ Y) {
    int bc = blockIdx.z, c = bc & (Cn - 1);
    int tileM = blockIdx.y * 128, tileN = blockIdx.x * 128;
    gemm_body<true>(AhG + ((size_t)c * Fn + tileM) * Fn,
                    AlG + ((size_t)c * Fn + tileM) * Fn,
                    BhG + ((size_t)bc * Wn + tileN) * Fn,
                    BlG + ((size_t)bc * Wn + tileN) * Fn,
                    Y + ((size_t)bc * Fn + tileM) * Wn + tileN);
}

// ======= batched conv3+bias (+RoPE) for Q/K/V: grid (4, 128, 6); z = which*2 + b =======
__global__ void __launch_bounds__(128) conv_qkv(const float* __restrict__ lin3,
                                                const float* __restrict__ Kcq, const float* __restrict__ bq,
                                                const float* __restrict__ Kck, const float* __restrict__ bk,
                                                const float* __restrict__ Kcv, const float* __restrict__ bv,
                                                uint2* __restrict__ qI, uint2* __restrict__ kI,
                                                __nv_bfloat16* __restrict__ vbf) {
    __shared__ float sIn[Cn][2][132];
    __shared__ float ks[Cn * Cn * 3];
    int tid = threadIdx.x;
    int zz = blockIdx.z;
    int which = zz >> 1, b = zz & 1;
    const float* Lin = lin3 + (size_t)which * NB;
    const float* Kc  = which == 0 ? Kcq : which == 1 ? Kck : Kcv;
    const float* bias = which == 0 ? bq : which == 1 ? bk : bv;
    int w0 = blockIdx.x * 128;
    int p  = blockIdx.y;
    int f0 = 2 * p;
    for (int t = tid; t < Cn * 2 * 130; t += 128) {
        int ci = t / 260, r = t % 260;
        int fi = r / 130, wo = r % 130;
        int gw = w0 + wo - 1;
        float v = (gw >= 0 && gw < Wn) ? Lin[((size_t)(b*Cn + ci) * Fn + f0 + fi) * Wn + gw] : 0.f;
        sIn[ci][fi][wo] = v;
    }
    for (int t = tid; t < Cn * Cn * 3; t += 128) ks[t] = Kc[t];
    __syncthreads();

    int w = w0 + tid;
    float cs = 1.f, sn = 0.f;
    if (which < 2) {
        int j = p & 15;
        float invf = exp10f(-0.25f * (float)j);
        sincosf((float)w * invf, &sn, &cs);
    }
    int h  = p >> 4;
    int jj = p & 15;
#pragma unroll
    for (int co = 0; co < Cn; co++) {
        float acc0 = bias[co], acc1 = acc0;
#pragma unroll
        for (int ci = 0; ci < Cn; ci++) {
            float k0 = ks[co*24 + ci*3], k1 = ks[co*24 + ci*3 + 1], k2 = ks[co*24 + ci*3 + 2];
            acc0 += k0 * sIn[ci][0][tid] + k1 * sIn[ci][0][tid+1] + k2 * sIn[ci][0][tid+2];
            acc1 += k0 * sIn[ci][1][tid] + k1 * sIn[ci][1][tid+1] + k2 * sIn[ci][1][tid+2];
        }
        size_t head = (size_t)(b*Cn + co) * Hn + h;
        size_t idx = (head * Wn + w) * 16 + jj;
        if (which < 2) {
            float o0 = acc0 * cs - acc1 * sn;
            float o1 = acc1 * cs + acc0 * sn;
            uint32_t lo, hi = pack_split(o0, o1, lo);
            (which == 0 ? qI : kI)[idx] = make_uint2(hi, lo);
        } else {
            ((__nv_bfloat162*)vbf)[idx] = __floats2bfloat162_rn(acc0, acc1);
        }
    }
}

// ======================= tensor-core flash attention (2-term QK) =======================
__global__ void __launch_bounds__(256, 1) attn_mma(const uint2* __restrict__ Qi,
                                                   const uint2* __restrict__ Ki,
                                                   const __nv_bfloat16* __restrict__ Vg,
                                                   __nv_bfloat16* __restrict__ AttH,
                                                   __nv_bfloat16* __restrict__ AttL) {
    __shared__ __nv_bfloat16 Kh[64][40];
    __shared__ __nv_bfloat16 Kl[64][40];
    __shared__ __nv_bfloat16 Vs[64][40];
    int head = blockIdx.x >> 1, half = blockIdx.x & 1;
    int tid = threadIdx.x, lane = tid & 31, wid = tid >> 5;
    int qb = half * 256 + wid * 32;
    size_t hbase = (size_t)head * Wn;

    uint32_t qh[2][2][4];
#pragma unroll
    for (int mi = 0; mi < 2; mi++) {
        int r0 = qb + mi * 16 + (lane >> 2);
#pragma unroll
        for (int kk = 0; kk < 2; kk++) {
            int jp = kk * 8 + (lane & 3);
            qh[mi][kk][0] = Qi[(hbase + r0) * 16 + jp].x;
            qh[mi][kk][1] = Qi[(hbase + r0 + 8) * 16 + jp].x;
            qh[mi][kk][2] = Qi[(hbase + r0) * 16 + jp + 4].x;
            qh[mi][kk][3] = Qi[(hbase + r0 + 8) * 16 + jp + 4].x;
        }
    }
    float m_[4] = {-1e30f, -1e30f, -1e30f, -1e30f};
    float l_[4] = {0.f, 0.f, 0.f, 0.f};
    float o[2][4][4] = {};
    uint32_t sbK = smem_u32(Kh), sbKl = smem_u32(Kl), sbV = smem_u32(Vs);
    int grp = lane >> 3, lr = lane & 7;

    for (int kt = 0; kt < 8; kt++) {
        int kb = kt * 64;
        __syncthreads();
#pragma unroll
        for (int it = 0; it < 4; it++) {
            int idx = tid + it * 256;
            int row = idx >> 4, j = idx & 15;
            uint2 v = Ki[(hbase + kb + row) * 16 + j];
            ((uint32_t*)&Kh[row][0])[j] = v.x;
            ((uint32_t*)&Kl[row][0])[j] = v.y;
        }
        {
            int row = tid >> 2, q = tid & 3;
            uint4 v = ((const uint4*)(Vg + (hbase + kb + row) * HDn))[q];
            *((uint4*)&Vs[row][q * 8]) = v;
        }
        __syncthreads();

        float s[2][8][4] = {};
#pragma unroll
        for (int kk = 0; kk < 2; kk++) {
#pragma unroll
            for (int nb = 0; nb < 4; nb++) {
                uint32_t kh4[4], kl4[4];
                uint32_t off = ((nb * 16 + (grp >> 1) * 8 + lr) * 40 + (grp & 1) * 8 + kk * 16) * 2;
                ldm_x4(kh4[0], kh4[1], kh4[2], kh4[3], sbK + off);
                ldm_x4(kl4[0], kl4[1], kl4[2], kl4[3], sbKl + off);
#pragma unroll
                for (int mi = 0; mi < 2; mi++) {
                    mma_bf16(s[mi][2*nb],   qh[mi][kk], &kh4[0]);
                    mma_bf16(s[mi][2*nb+1], qh[mi][kk], &kh4[2]);
                    mma_bf16(s[mi][2*nb],   qh[mi][kk], &kl4[0]);
                    mma_bf16(s[mi][2*nb+1], qh[mi][kk], &kl4[2]);
                }
            }
        }

        uint32_t pa[2][4][4];
#pragma unroll
        for (int mi = 0; mi < 2; mi++) {
            float mx0 = -1e30f, mx1 = -1e30f;
#pragma unroll
            for (int n = 0; n < 8; n++) {
#pragma unroll
                for (int q = 0; q < 4; q++) s[mi][n][q] *= 0.0625f;
                mx0 = fmaxf(mx0, fmaxf(s[mi][n][0], s[mi][n][1]));
                mx1 = fmaxf(mx1, fmaxf(s[mi][n][2], s[mi][n][3]));
            }
            mx0 = fmaxf(mx0, __shfl_xor_sync(0xffffffffu, mx0, 1));
            mx0 = fmaxf(mx0, __shfl_xor_sync(0xffffffffu, mx0, 2));
            mx1 = fmaxf(mx1, __shfl_xor_sync(0xffffffffu, mx1, 1));
            mx1 = fmaxf(mx1, __shfl_xor_sync(0xffffffffu, mx1, 2));
            int si = mi * 2;
            float mn0 = fmaxf(m_[si], mx0), mn1 = fmaxf(m_[si+1], mx1);
            float c0 = __expf(m_[si] - mn0), c1 = __expf(m_[si+1] - mn1);
            m_[si] = mn0; m_[si+1] = mn1;
            float ls0 = 0.f, ls1 = 0.f;
#pragma unroll
            for (int n = 0; n < 8; n++) {
                float p0 = __expf(s[mi][n][0] - mn0);
                float p1 = __expf(s[mi][n][1] - mn0);
                float p2 = __expf(s[mi][n][2] - mn1);
                float p3 = __expf(s[mi][n][3] - mn1);
                ls0 += p0 + p1; ls1 += p2 + p3;
                s[mi][n][0] = p0; s[mi][n][1] = p1; s[mi][n][2] = p2; s[mi][n][3] = p3;
            }
            ls0 += __shfl_xor_sync(0xffffffffu, ls0, 1);
            ls0 += __shfl_xor_sync(0xffffffffu, ls0, 2);
            ls1 += __shfl_xor_sync(0xffffffffu, ls1, 1);
            ls1 += __shfl_xor_sync(0xffffffffu, ls1, 2);
            l_[si]   = l_[si]   * c0 + ls0;
            l_[si+1] = l_[si+1] * c1 + ls1;
#pragma unroll
            for (int dn = 0; dn < 4; dn++) {
                o[mi][dn][0] *= c0; o[mi][dn][1] *= c0;
                o[mi][dn][2] *= c1; o[mi][dn][3] *= c1;
            }
#pragma unroll
            for (int t = 0; t < 4; t++) {
                pa[mi][t][0] = packbf(s[mi][2*t][0],   s[mi][2*t][1]);
                pa[mi][t][1] = packbf(s[mi][2*t][2],   s[mi][2*t][3]);
                pa[mi][t][2] = packbf(s[mi][2*t+1][0], s[mi][2*t+1][1]);
                pa[mi][t][3] = packbf(s[mi][2*t+1][2], s[mi][2*t+1][3]);
            }
        }

#pragma unroll
        for (int dn = 0; dn < 4; dn++) {
            uint32_t vb[4][2];
#pragma unroll
            for (int t = 0; t < 4; t++) {
                uint32_t off = ((t * 16 + (lane & 15)) * 40 + dn * 8) * 2;
                ldm_x2_trans(vb[t][0], vb[t][1], sbV + off);
            }
#pragma unroll
            for (int mi = 0; mi < 2; mi++)
#pragma unroll
                for (int t = 0; t < 4; t++)
                    mma_bf16(o[mi][dn], pa[mi][t], vb[t]);
        }
    }

    int bc = head >> 3, hh = head & 7;
#pragma unroll
    for (int mi = 0; mi < 2; mi++) {
        int r0 = qb + mi * 16 + (lane >> 2);
        float i0 = 1.0f / l_[mi*2], i1 = 1.0f / l_[mi*2 + 1];
#pragma unroll
        for (int dn = 0; dn < 4; dn++) {
            int d0 = dn * 8 + (lane & 3) * 2;
            size_t a0 = ((size_t)bc * Wn + r0) * Fn + hh * HDn + d0;
            size_t a1 = ((size_t)bc * Wn + r0 + 8) * Fn + hh * HDn + d0;
            uint32_t lo0, hi0 = pack_split(o[mi][dn][0] * i0, o[mi][dn][1] * i0, lo0);
            uint32_t lo1, hi1 = pack_split(o[mi][dn][2] * i1, o[mi][dn][3] * i1, lo1);
            *(uint32_t*)(AttH + a0) = hi0;
            *(uint32_t*)(AttL + a0) = lo0;
            *(uint32_t*)(AttH + a1) = hi1;
            *(uint32_t*)(AttL + a1) = lo1;
        }
    }
}

// ============ fused LN + depthwise convs (k11 sq_relu + k7) ============
// grid (Wn/64, Bn*Cn), 256 thr, dyn smem Fn*64*4
__global__ void __launch_bounds__(256) lnconv_ab(const float* __restrict__ X,
                                                 const float* __restrict__ gam,
                                                 const float* __restrict__ bet,
                                                 const float* __restrict__ k11, const float* __restrict__ b11,
                                                 const float* __restrict__ k7,  const float* __restrict__ b7,
                                                 float* __restrict__ Yo) {
    extern __shared__ float sZ[];
    __shared__ float gs[Fn], bs[Fn], ps[4][64], ps2[4][64], mb[64], ib[64];
    int tid = threadIdx.x, w = tid & 63, fg = tid >> 6;
    int bc = blockIdx.y, c = bc & (Cn - 1);
    int w0 = blockIdx.x * 64;
    const float* xp = X + (size_t)bc * Fn * Wn + w0;
    for (int i = tid; i < Fn * 64; i += 256)
        sZ[i] = xp[(size_t)(i >> 6) * Wn + (i & 63)];
    for (int i = tid; i < Fn; i += 256) { gs[i] = gam[c * Fn + i]; bs[i] = bet[c * Fn + i]; }
    __syncthreads();
    float s = 0.f, s2 = 0.f;
#pragma unroll 4
    for (int f = fg * 64; f < fg * 64 + 64; f++) {
        float v = sZ[f * 64 + w];
        s += v; s2 += v * v;
    }
    ps[fg][w] = s; ps2[fg][w] = s2;
    __syncthreads();
    if (fg == 0) {
        float S  = ps[0][w]  + ps[1][w]  + ps[2][w]  + ps[3][w];
        float S2 = ps2[0][w] + ps2[1][w] + ps2[2][w] + ps2[3][w];
        float m = S * (1.0f / Fn);
        mb[w] = m;
        ib[w] = rsqrtf(S2 * (1.0f / Fn) - m * m + 1e-5f);
    }
    __syncthreads();
    float m = mb[w], inv = ib[w];
#pragma unroll 4
    for (int f = fg * 64; f < fg * 64 + 64; f++)
        sZ[f * 64 + w] = (sZ[f * 64 + w] - m) * inv * gs[f] + bs[f];
    __syncthreads();
    float wk11[11], wk7[7];
#pragma unroll
    for (int t = 0; t < 11; t++) wk11[t] = k11[c * 11 + t];
#pragma unroll
    for (int t = 0; t < 7; t++)  wk7[t]  = k7[c * 7 + t];
    float bb11 = b11[c], bb7 = b7[c];
    float* yo = Yo + (size_t)bc * Fn * Wn + w0 + w;
    for (int f = fg * 64; f < fg * 64 + 64; f++) {
        float a = bb11;
#pragma unroll
        for (int t = 0; t < 11; t++) {
            int ff = f - 5 + t;
            if (ff >= 0 && ff < Fn) a += sZ[ff * 64 + w] * wk11[t];
        }
        a = fmaxf(a, 0.f); a = a * a;
        float bo = bb7;
#pragma unroll
        for (int t = 0; t < 7; t++) {
            int ff = f - 3 + t;
            if (ff >= 0 && ff < Fn) bo += sZ[ff * 64 + w] * wk7[t];
        }
        yo[(size_t)f * Wn] = a + bo;
    }
}

// ============ fused LN + k7 conv + residual add into H ============
__global__ void __launch_bounds__(256) lnconv2_add(const float* __restrict__ X,
                                                   const float* __restrict__ gam,
                                                   const float* __restrict__ bet,
                                                   const float* __restrict__ k7, const float* __restrict__ b7,
                                                   float* __restrict__ Hb) {
    extern __shared__ float sZ[];
    __shared__ float gs[Fn], bs[Fn], ps[4][64], ps2[4][64], mb[64], ib[64];
    int tid = threadIdx.x, w = tid & 63, fg = tid >> 6;
    int bc = blockIdx.y, c = bc & (Cn - 1);
    int w0 = blockIdx.x * 64;
    const float* xp = X + (size_t)bc * Fn * Wn + w0;
    for (int i = tid; i < Fn * 64; i += 256)
        sZ[i] = xp[(size_t)(i >> 6) * Wn + (i & 63)];
    for (int i = tid; i < Fn; i += 256) { gs[i] = gam[c * Fn + i]; bs[i] = bet[c * Fn + i]; }
    __syncthreads();
    float s = 0.f, s2 = 0.f;
#pragma unroll 4
    for (int f = fg * 64; f < fg * 64 + 64; f++) {
        float v = sZ[f * 64 + w];
        s += v; s2 += v * v;
    }
    ps[fg][w] = s; ps2[fg][w] = s2;
    __syncthreads();
    if (fg == 0) {
        float S  = ps[0][w]  + ps[1][w]  + ps[2][w]  + ps[3][w];
        float S2 = ps2[0][w] + ps2[1][w] + ps2[2][w] + ps2[3][w];
        float m = S * (1.0f / Fn);
        mb[w] = m;
        ib[w] = rsqrtf(S2 * (1.0f / Fn) - m * m + 1e-5f);
    }
    __syncthreads();
    float m = mb[w], inv = ib[w];
#pragma unroll 4
    for (int f = fg * 64; f < fg * 64 + 64; f++)
        sZ[f * 64 + w] = (sZ[f * 64 + w] - m) * inv * gs[f] + bs[f];
    __syncthreads();
    float wk7[7];
#pragma unroll
    for (int t = 0; t < 7; t++) wk7[t] = k7[c * 7 + t];
    float bb7 = b7[c];
    float* hb = Hb + (size_t)bc * Fn * Wn + w0 + w;
    for (int f = fg * 64; f < fg * 64 + 64; f++) {
        float v = bb7;
#pragma unroll
        for (int t = 0; t < 7; t++) {
            int ff = f - 3 + t;
            if (ff >= 0 && ff < Fn) v += sZ[ff * 64 + w] * wk7[t];
        }
        hb[(size_t)f * Wn] += v;
    }
}

// ============ fused LN + FFN first layer (sq_relu(z @ w3^T)) ============
// grid (Wn/64, Bn*Cn), 256 thr, dyn smem Fn*64*4
__global__ void __launch_bounds__(256) ln_ffn3(const float* __restrict__ X,
                                               const float* __restrict__ gam,
                                               const float* __restrict__ bet,
                                               const float* __restrict__ w3,
                                               float* __restrict__ T) {
    extern __shared__ float sZ[];
    __shared__ float ws[En * Fn], gs[Fn], bs[Fn];
    __shared__ float ps[4][64], ps2[4][64], mb[64], ib[64];
    __shared__ float pacc[4][En][64];
    int tid = threadIdx.x, w = tid & 63, fg = tid >> 6;
    int bc = blockIdx.y, c = bc & (Cn - 1);
    int w0 = blockIdx.x * 64;
    const float* xp = X + (size_t)bc * Fn * Wn + w0;
    for (int i = tid; i < Fn * 64; i += 256)
        sZ[i] = xp[(size_t)(i >> 6) * Wn + (i & 63)];
    for (int i = tid; i < En * Fn; i += 256) ws[i] = w3[c * En * Fn + i];
    for (int i = tid; i < Fn; i += 256) { gs[i] = gam[c * Fn + i]; bs[i] = bet[c * Fn + i]; }
    __syncthreads();
    float s = 0.f, s2 = 0.f;
#pragma unroll 4
    for (int f = fg * 64; f < fg * 64 + 64; f++) {
        float v = sZ[f * 64 + w];
        s += v; s2 += v * v;
    }
    ps[fg][w] = s; ps2[fg][w] = s2;
    __syncthreads();
    if (fg == 0) {
        float S  = ps[0][w]  + ps[1][w]  + ps[2][w]  + ps[3][w];
        float S2 = ps2[0][w] + ps2[1][w] + ps2[2][w] + ps2[3][w];
        float m = S * (1.0f / Fn);
        mb[w] = m;
        ib[w] = rsqrtf(S2 * (1.0f / Fn) - m * m + 1e-5f);
    }
    __syncthreads();
    float m = mb[w], inv = ib[w];
    float acc[En] = {};
#pragma unroll 4
    for (int f = fg * 64; f < fg * 64 + 64; f++) {
        float zn = (sZ[f * 64 + w] - m) * inv * gs[f] + bs[f];
#pragma unroll
        for (int e = 0; e < En; e++) acc[e] += zn * ws[e * Fn + f];
    }
#pragma unroll
    for (int e = 0; e < En; e++) pacc[fg][e][w] = acc[e];
    __syncthreads();
    if (fg == 0) {
        float* tp = T + (size_t)bc * En * Wn + w0 + w;
#pragma unroll
        for (int e = 0; e < En; e++) {
            float v = pacc[0][e][w] + pacc[1][e][w] + pacc[2][e][w] + pacc[3][e][w];
            v = fmaxf(v, 0.f);
            tp[(size_t)e * Wn] = v * v;
        }
    }
}

// ============ fused FFN second layer + residual + concat output ============
__global__ void ffn4_write(const float* __restrict__ T, const float* __restrict__ w4,
                           const float* __restrict__ Hb, const float* __restrict__ X,
                           float* __restrict__ O) {
    int idx = blockIdx.x * 256 + threadIdx.x;
    int w  = idx & (Wn - 1);
    int f  = (idx >> 9) & (Fn - 1);
    int bc = idx >> 17;
    int c  = bc & (Cn - 1);
    const float* tp = T + (size_t)bc * En * Wn + w;
    const float* wp = w4 + ((size_t)c * Fn + f) * En;
    float v = tp[0] * wp[0] + tp[Wn] * wp[1] + tp[2 * Wn] * wp[2] + tp[3 * Wn] * wp[3];
    float h = Hb[idx] + v;
    int b = idx / (Cn * Fn * Wn);
    int r = idx - b * (Cn * Fn * Wn);
    O[(size_t)b * 2 * Cn * Fn * Wn + r] = X[idx];
    O[(size_t)b * 2 * Cn * Fn * Wn + Cn * Fn * Wn + r] = h;
}

__global__ void copy_x(const float* __restrict__ X, float* __restrict__ Hb) {
    int i = blockIdx.x * 256 + threadIdx.x;
    ((float4*)Hb)[i] = ((const float4*)X)[i];
}

// =====================================================================================

extern "C" void kernel_launch(void* const* d_in, const int* in_sizes, int n_in,
                              void* d_out, int out_size) {
    const float* x     = (const float*)d_in[0];
    const float* skip  = (const float*)d_in[1];
    const float* Wq    = (const float*)d_in[2];
    const float* Kq    = (const float*)d_in[3];
    const float* bq    = (const float*)d_in[4];
    const float* Wk    = (const float*)d_in[5];
    const float* Kk    = (const float*)d_in[6];
    const float* bk    = (const float*)d_in[7];
    const float* Wv    = (const float*)d_in[8];
    const float* Kv    = (const float*)d_in[9];
    const float* bv    = (const float*)d_in[10];
    const float* Wo    = (const float*)d_in[11];
    const float* ng    = (const float*)d_in[12];
    const float* nbet  = (const float*)d_in[13];
    const float* c1a_w = (const float*)d_in[14];
    const float* c1a_b = (const float*)d_in[15];
    const float* c1b_w = (const float*)d_in[16];
    const float* c1b_b = (const float*)d_in[17];
    const float* c2_w  = (const float*)d_in[18];
    const float* c2_b  = (const float*)d_in[19];
    const float* w3    = (const float*)d_in[20];
    const float* w4    = (const float*)d_in[21];
    float* out = (float*)d_out;

    float *hB, *lin3B, *t1B, *ffnB;
    cudaGetSymbolAddress((void**)&hB,    g_h);
    cudaGetSymbolAddress((void**)&lin3B, g_lin3);
    cudaGetSymbolAddress((void**)&t1B,   g_t1);
    cudaGetSymbolAddress((void**)&ffnB,  g_ffn);
    uint2 *qI, *kI;
    __nv_bfloat16 *vBf;
    cudaGetSymbolAddress((void**)&qI,  g_qI);
    cudaGetSymbolAddress((void**)&kI,  g_kI);
    cudaGetSymbolAddress((void**)&vBf, g_vbf);
    __nv_bfloat16 *zTh, *zTl, *skTh, *skTl, *atTh, *atTl;
    __nv_bfloat16 *WqH, *WqL, *WkH, *WkL, *WvH, *WvL, *WoH, *WoL;
    cudaGetSymbolAddress((void**)&zTh,  g_zTh);  cudaGetSymbolAddress((void**)&zTl,  g_zTl);
    cudaGetSymbolAddress((void**)&skTh, g_skTh); cudaGetSymbolAddress((void**)&skTl, g_skTl);
    cudaGetSymbolAddress((void**)&atTh, g_atTh); cudaGetSymbolAddress((void**)&atTl, g_atTl);
    cudaGetSymbolAddress((void**)&WqH, g_WqH); cudaGetSymbolAddress((void**)&WqL, g_WqL);
    cudaGetSymbolAddress((void**)&WkH, g_WkH); cudaGetSymbolAddress((void**)&WkL, g_WkL);
    cudaGetSymbolAddress((void**)&WvH, g_WvH); cudaGetSymbolAddress((void**)&WvL, g_WvL);
    cudaGetSymbolAddress((void**)&WoH, g_WoH); cudaGetSymbolAddress((void**)&WoL, g_WoL);

    const int TSM = Fn * 64 * 4;
    cudaFuncSetAttribute(gemm_qkv, cudaFuncAttributeMaxDynamicSharedMemorySize, GSM);
    cudaFuncSetAttribute(gemm_wo,  cudaFuncAttributeMaxDynamicSharedMemorySize, GSM);
    cudaFuncSetAttribute(lnconv_ab,   cudaFuncAttributeMaxDynamicSharedMemorySize, TSM);
    cudaFuncSetAttribute(lnconv2_add, cudaFuncAttributeMaxDynamicSharedMemorySize, TSM);
    cudaFuncSetAttribute(ln_ffn3,     cudaFuncAttributeMaxDynamicSharedMemorySize, TSM);

    const int nElemBlocks = NB / 256;
    const int wBlocks = (4 * WOFF) / 1024;
    const dim3 gLN(Wn / 32, Bn * Cn);
    const dim3 gT64(Wn / 64, Bn * Cn);

    wsplit_all<<<dim3(wBlocks, 4), 256>>>(Wq, Wk, Wv, Wo,
                                          WqH, WqL, WkH, WkL, WvH, WvL, WoH, WoL);
    tsplit_kernel<<<dim3(Wn/32, Fn/32, Bn*Cn), dim3(32, 8)>>>(skip, skTh, skTl);
    copy_x<<<NB / 1024, 256>>>(x, hB);

    auto run_ln_t = [&](const float* X, int gi) {
        ln_t_v3<<<gLN, 256>>>(X, ng + gi * Cn * Fn, nbet + gi * Cn * Fn, zTh, zTl);
    };

    auto run_attn = [&](int i, const __nv_bfloat16* th, const __nv_bfloat16* tl,
                        const __nv_bfloat16* mh, const __nv_bfloat16* ml) {
        size_t wo = (size_t)i * WOFF;
        size_t ko = (size_t)i * Cn * Cn * 3;
        gemm_qkv<<<dim3(4, 2, 48), 256, GSM>>>(WqH + wo, WqL + wo, WkH + wo, WkL + wo,
                                               WvH + wo, WvL + wo, th, tl, mh, ml, lin3B);
        conv_qkv<<<dim3(4, 128, 6), 128>>>(lin3B, Kq + ko, bq + i * Cn,
                                           Kk + ko, bk + i * Cn, Kv + ko, bv + i * Cn,
                                           qI, kI, vBf);
        attn_mma<<<NHEAD * 2, 256>>>(qI, kI, vBf, atTh, atTl);
        gemm_wo<<<dim3(4, 2, 16), 256, GSM>>>(WoH + wo, WoL + wo, atTh, atTl, hB);
    };

    // h = x + att0(z,z) + att1(z,skip), z = LN0(x)
    run_ln_t(x, 0);
    run_attn(0, zTh, zTl, zTh, zTl);
    run_attn(1, zTh, zTl, skTh, skTl);

    // conv block: LN1+convs fused, LN2+conv2 fused
    lnconv_ab<<<gT64, 256, TSM>>>(hB, ng + 1 * Cn * Fn, nbet + 1 * Cn * Fn,
                                  c1a_w, c1a_b, c1b_w, c1b_b, t1B);
    lnconv2_add<<<gT64, 256, TSM>>>(t1B, ng + 2 * Cn * Fn, nbet + 2 * Cn * Fn,
                                    c2_w, c2_b, hB);

    // h += att2(LN3(h), same)
    run_ln_t(hB, 3);
    run_attn(2, zTh, zTl, zTh, zTl);

    // h += att3(LN4(h), skip)
    run_ln_t(hB, 4);
    run_attn(3, zTh, zTl, skTh, skTl);

    // FFN (LN5 fused into ffn3; ffn4 fused with concat output)
    ln_ffn3<<<gT64, 256, TSM>>>(hB, ng + 5 * Cn * Fn, nbet + 5 * Cn * Fn, w3, ffnB);
    ffn4_write<<<nElemBlocks, 256>>>(ffnB, w4, hB, x, out);
}

// round 11
// speedup vs baseline: 2.9806x; 1.0589x over previous
#include <cuda_runtime.h>
#include <cuda_bf16.h>
#include <math.h>
#include <stdint.h>

#define Bn 2
#define Cn 8
#define Fn 256
#define Wn 512
#define Hn 8
#define HDn 32
#define En 4
#define NB (Bn*Cn*Fn*Wn)
#define WOFF (Cn*Fn*Fn)
#define NHEAD (Bn*Cn*Hn)
#define QS ((size_t)NHEAD*Wn*16)          // uint2 elems per pair (Q/K)
#define VS ((size_t)NHEAD*Wn*HDn)         // bf16 elems per pair (V)
#define AS ((size_t)Bn*Cn*Wn*Fn)          // bf16 elems per pair (attn out)

// ======================= warp-MMA helpers (baseline PTX, sm_80+) =======================
__device__ __forceinline__ uint32_t smem_u32(const void* p) {
    uint32_t a;
    asm("{ .reg .u64 t; cvta.to.shared.u64 t, %1; cvt.u32.u64 %0, t; }" : "=r"(a) : "l"(p));
    return a;
}
__device__ __forceinline__ void ldm_x4(uint32_t& r0, uint32_t& r1, uint32_t& r2, uint32_t& r3,
                                       uint32_t addr) {
    asm volatile("ldmatrix.sync.aligned.m8n8.x4.shared.b16 {%0,%1,%2,%3}, [%4];"
                 : "=r"(r0), "=r"(r1), "=r"(r2), "=r"(r3) : "r"(addr));
}
__device__ __forceinline__ void ldm_x2_trans(uint32_t& r0, uint32_t& r1, uint32_t addr) {
    asm volatile("ldmatrix.sync.aligned.m8n8.x2.trans.shared.b16 {%0,%1}, [%2];"
                 : "=r"(r0), "=r"(r1) : "r"(addr));
}
__device__ __forceinline__ void mma_bf16(float* d, const uint32_t* a, const uint32_t* b) {
    asm volatile("mma.sync.aligned.m16n8k16.row.col.f32.bf16.bf16.f32 "
                 "{%0,%1,%2,%3}, {%4,%5,%6,%7}, {%8,%9}, {%0,%1,%2,%3};"
                 : "+f"(d[0]), "+f"(d[1]), "+f"(d[2]), "+f"(d[3])
                 : "r"(a[0]), "r"(a[1]), "r"(a[2]), "r"(a[3]), "r"(b[0]), "r"(b[1]));
}
__device__ __forceinline__ uint32_t pack_split(float a, float b, uint32_t& lo) {
    __nv_bfloat16 ha = __float2bfloat16(a), hb = __float2bfloat16(b);
    __nv_bfloat16 la = __float2bfloat16(a - __bfloat162float(ha));
    __nv_bfloat16 lb = __float2bfloat16(b - __bfloat162float(hb));
    lo = (uint32_t)__bfloat16_as_ushort(la) | ((uint32_t)__bfloat16_as_ushort(lb) << 16);
    return (uint32_t)__bfloat16_as_ushort(ha) | ((uint32_t)__bfloat16_as_ushort(hb) << 16);
}
__device__ __forceinline__ uint32_t packbf(float a, float b) {
    __nv_bfloat162 v = __floats2bfloat162_rn(a, b);
    return *(uint32_t*)&v;
}

// ======================= scratch (device globals) =======================
__device__ float g_h[NB];
__device__ float g_lin6[6*NB];
__device__ float g_t1[NB];
__device__ float g_ffn[Bn*Cn*En*Wn];
__device__ uint2 g_qI[2*NHEAD*Wn*16];
__device__ uint2 g_kI[2*NHEAD*Wn*16];
__device__ __nv_bfloat16 g_vbf[2*NHEAD*Wn*HDn];
__device__ __nv_bfloat16 g_zTh[Bn*Cn*Wn*Fn];
__device__ __nv_bfloat16 g_zTl[Bn*Cn*Wn*Fn];
__device__ __nv_bfloat16 g_skTh[Bn*Cn*Wn*Fn];
__device__ __nv_bfloat16 g_skTl[Bn*Cn*Wn*Fn];
__device__ __nv_bfloat16 g_atTh[2*Bn*Cn*Wn*Fn];
__device__ __nv_bfloat16 g_atTl[2*Bn*Cn*Wn*Fn];
__device__ __nv_bfloat16 g_WqH[4*WOFF]; __device__ __nv_bfloat16 g_WqL[4*WOFF];
__device__ __nv_bfloat16 g_WkH[4*WOFF]; __device__ __nv_bfloat16 g_WkL[4*WOFF];
__device__ __nv_bfloat16 g_WvH[4*WOFF]; __device__ __nv_bfloat16 g_WvL[4*WOFF];
__device__ __nv_bfloat16 g_WoH[4*WOFF]; __device__ __nv_bfloat16 g_WoL[4*WOFF];

// ============ LayerNorm -> transposed bf16 hi/lo; grid (32, 16), blk 256 = 16w x 16fg ============
__global__ void __launch_bounds__(256) ln_t_v4(const float* __restrict__ X,
                                               const float* __restrict__ gam,
                                               const float* __restrict__ bet,
                                               __nv_bfloat16* __restrict__ Zh,
                                               __nv_bfloat16* __restrict__ Zl) {
    __shared__ float ps[16][17], ps2[16][17], mb[16], ib[16];
    int tid = threadIdx.x, w = tid & 15, fg = tid >> 4;
    int bc = blockIdx.y, c = bc & (Cn - 1);
    int w0 = blockIdx.x * 16;
    const float* xp = X + (size_t)bc * Fn * Wn + w0 + w;
    float s = 0.f, s2 = 0.f;
#pragma unroll 4
    for (int f = fg * 16; f < fg * 16 + 16; f++) {
        float v = xp[(size_t)f * Wn];
        s += v; s2 += v * v;
    }
    ps[fg][w] = s; ps2[fg][w] = s2;
    __syncthreads();
    if (tid < 16) {
        float S = 0.f, S2 = 0.f;
#pragma unroll
        for (int g = 0; g < 16; g++) { S += ps[g][tid]; S2 += ps2[g][tid]; }
        float m = S * (1.0f / Fn);
        mb[tid] = m;
        ib[tid] = rsqrtf(S2 * (1.0f / Fn) - m * m + 1e-5f);
    }
    __syncthreads();
    float m = mb[w], inv = ib[w];
    const float* gp = gam + c * Fn;
    const float* bp = bet + c * Fn;
    __nv_bfloat16* th = Zh + ((size_t)bc * Wn + w0 + w) * Fn;
    __nv_bfloat16* tl = Zl + ((size_t)bc * Wn + w0 + w) * Fn;
    for (int f0 = fg * 16; f0 < fg * 16 + 16; f0 += 8) {
        uint32_t ph[4], pl[4];
#pragma unroll
        for (int j = 0; j < 4; j++) {
            int f = f0 + 2 * j;
            float v0 = (xp[(size_t)f * Wn]     - m) * inv * gp[f]   + bp[f];
            float v1 = (xp[(size_t)(f+1) * Wn] - m) * inv * gp[f+1] + bp[f+1];
            ph[j] = pack_split(v0, v1, pl[j]);
        }
        *(uint4*)(th + f0) = make_uint4(ph[0], ph[1], ph[2], ph[3]);
        *(uint4*)(tl + f0) = make_uint4(pl[0], pl[1], pl[2], pl[3]);
    }
}

// ============ transpose + split: (b,c,f,w) fp32 -> [bc][w][f] bf16 hi/lo ============
__global__ void tsplit_kernel(const float* __restrict__ X,
                              __nv_bfloat16* __restrict__ Th, __nv_bfloat16* __restrict__ Tl) {
    __shared__ float t[32][33];
    int bc = blockIdx.z;
    int w0 = blockIdx.x * 32, f0 = blockIdx.y * 32;
    const float* xp = X + ((size_t)bc * Fn + f0) * Wn + w0;
#pragma unroll
    for (int i = 0; i < 4; i++) {
        int fr = threadIdx.y + i * 8;
        t[fr][threadIdx.x] = xp[(size_t)fr * Wn + threadIdx.x];
    }
    __syncthreads();
#pragma unroll
    for (int i = 0; i < 4; i++) {
        int wr = threadIdx.y + i * 8;
        float v = t[threadIdx.x][wr];
        __nv_bfloat16 h = __float2bfloat16(v);
        __nv_bfloat16 l = __float2bfloat16(v - __bfloat162float(h));
        size_t idx = ((size_t)bc * Wn + w0 + wr) * Fn + f0 + threadIdx.x;
        Th[idx] = h; Tl[idx] = l;
    }
}

// ============ weight split: all four weight tensors in one launch ============
__global__ void wsplit_all(const float* __restrict__ S0, const float* __restrict__ S1,
                           const float* __restrict__ S2, const float* __restrict__ S3,
                           __nv_bfloat16* H0, __nv_bfloat16* L0,
                           __nv_bfloat16* H1, __nv_bfloat16* L1,
                           __nv_bfloat16* H2, __nv_bfloat16* L2,
                           __nv_bfloat16* H3, __nv_bfloat16* L3) {
    int which = blockIdx.y;
    const float* X = which == 0 ? S0 : which == 1 ? S1 : which == 2 ? S2 : S3;
    __nv_bfloat16* H = which == 0 ? H0 : which == 1 ? H1 : which == 2 ? H2 : H3;
    __nv_bfloat16* L = which == 0 ? L0 : which == 1 ? L1 : which == 2 ? L2 : L3;
    int i = (blockIdx.x * 256 + threadIdx.x) * 4;
    float4 v = *(const float4*)(X + i);
    uint32_t l0, l1;
    uint32_t h0 = pack_split(v.x, v.y, l0);
    uint32_t h1 = pack_split(v.z, v.w, l1);
    *(uint2*)((unsigned short*)H + i) = make_uint2(h0, h1);
    *(uint2*)((unsigned short*)L + i) = make_uint2(l0, l1);
}

// ======================= synchronous-staging 3xBF16 GEMM body (proven) =======================
#define KCn 64
#define LDT 72
#define TELEM (128 * LDT)
#define GSM (4 * TELEM * 2)          // 73728 bytes

template<bool ACC>
__device__ __forceinline__ void gemm_body(const __nv_bfloat16* __restrict__ gAh,
                                          const __nv_bfloat16* __restrict__ gAl,
                                          const __nv_bfloat16* __restrict__ gBh,
                                          const __nv_bfloat16* __restrict__ gBl,
                                          float* __restrict__ Yrow) {
    extern __shared__ __nv_bfloat16 sm[];
    __nv_bfloat16* sAh = sm;
    __nv_bfloat16* sAl = sm + TELEM;
    __nv_bfloat16* sBh = sm + 2 * TELEM;
    __nv_bfloat16* sBl = sm + 3 * TELEM;
    int tid = threadIdx.x, lane = tid & 31, wid = tid >> 5;
    int wm = wid >> 2, wn = wid & 3;

    float acc[4][4][4] = {};
    int lrow = tid >> 1;
    int lq   = (tid & 1) * 4;

    uint32_t sb = smem_u32(sm);
    int grp = lane >> 3, lr = lane & 7;
    int aRow = wm * 64 + (grp & 1) * 8 + lr;
    int aCol = (grp >> 1) * 8;
    int bRow = wn * 32 + (grp >> 1) * 8 + lr;
    int bCol = (grp & 1) * 8;

    for (int kc = 0; kc < 4; kc++) {
        if (kc) __syncthreads();
        const uint4* pa = (const uint4*)(gAh + (size_t)lrow * Fn + kc * KCn);
        const uint4* pb = (const uint4*)(gAl + (size_t)lrow * Fn + kc * KCn);
        const uint4* pc = (const uint4*)(gBh + (size_t)lrow * Fn + kc * KCn);
        const uint4* pd = (const uint4*)(gBl + (size_t)lrow * Fn + kc * KCn);
        uint4* qa = (uint4*)(sAh + lrow * LDT);
        uint4* qb = (uint4*)(sAl + lrow * LDT);
        uint4* qc = (uint4*)(sBh + lrow * LDT);
        uint4* qd = (uint4*)(sBl + lrow * LDT);
#pragma unroll
        for (int j = 0; j < 4; j++) {
            qa[lq + j] = pa[lq + j];
            qb[lq + j] = pb[lq + j];
            qc[lq + j] = pc[lq + j];
            qd[lq + j] = pd[lq + j];
        }
        __syncthreads();
#pragma unroll
        for (int ks = 0; ks < 4; ks++) {
            int k0 = ks * 16;
            uint32_t ah[4][4], al[4][4], bh[2][4], bl[2][4];
#pragma unroll
            for (int mi = 0; mi < 4; mi++) {
                uint32_t off = ((aRow + mi * 16) * LDT + aCol + k0) * 2;
                ldm_x4(ah[mi][0], ah[mi][1], ah[mi][2], ah[mi][3], sb + off);
                ldm_x4(al[mi][0], al[mi][1], al[mi][2], al[mi][3], sb + TELEM * 2 + off);
            }
#pragma unroll
            for (int nb = 0; nb < 2; nb++) {
                uint32_t off = ((bRow + nb * 16) * LDT + bCol + k0) * 2;
                ldm_x4(bh[nb][0], bh[nb][1], bh[nb][2], bh[nb][3], sb + TELEM * 4 + off);
                ldm_x4(bl[nb][0], bl[nb][1], bl[nb][2], bl[nb][3], sb + TELEM * 6 + off);
            }
#pragma unroll
            for (int mi = 0; mi < 4; mi++) {
#pragma unroll
                for (int nb = 0; nb < 2; nb++) {
                    mma_bf16(acc[mi][2*nb],   ah[mi], &bh[nb][0]);
                    mma_bf16(acc[mi][2*nb+1], ah[mi], &bh[nb][2]);
                    mma_bf16(acc[mi][2*nb],   ah[mi], &bl[nb][0]);
                    mma_bf16(acc[mi][2*nb+1], ah[mi], &bl[nb][2]);
                    mma_bf16(acc[mi][2*nb],   al[mi], &bh[nb][0]);
                    mma_bf16(acc[mi][2*nb+1], al[mi], &bh[nb][2]);
                }
            }
        }
    }

#pragma unroll
    for (int mi = 0; mi < 4; mi++) {
        int row = wm * 64 + mi * 16 + (lane >> 2);
#pragma unroll
        for (int ni = 0; ni < 4; ni++) {
            int col = wn * 32 + ni * 8 + (lane & 3) * 2;
            float* p0 = Yrow + (size_t)row * Wn + col;
            float* p1 = p0 + 8 * Wn;
            float2 v0 = make_float2(acc[mi][ni][0], acc[mi][ni][1]);
            float2 v1 = make_float2(acc[mi][ni][2], acc[mi][ni][3]);
            if (ACC) {
                float2 o0 = *(const float2*)p0, o1 = *(const float2*)p1;
                v0.x += o0.x; v0.y += o0.y; v1.x += o1.x; v1.y += o1.y;
            }
            *(float2*)p0 = v0;
            *(float2*)p1 = v1;
        }
    }
}

// Q/K/V projection GEMM, pair-capable: grid (4, 2, 48*NPAIR); z = pair*48 + which*16 + bc
// Weight bases point at attention block i0; pair adds WOFF.
__global__ void __launch_bounds__(256) gemm_qkv(
        const __nv_bfloat16* __restrict__ WqH_, const __nv_bfloat16* __restrict__ WqL_,
        const __nv_bfloat16* __restrict__ WkH_, const __nv_bfloat16* __restrict__ WkL_,
        const __nv_bfloat16* __restrict__ WvH_, const __nv_bfloat16* __restrict__ WvL_,
        const __nv_bfloat16* __restrict__ th, const __nv_bfloat16* __restrict__ tl,
        const __nv_bfloat16* __restrict__ m0h, const __nv_bfloat16* __restrict__ m0l,
        const __nv_bfloat16* __restrict__ m1h, const __nv_bfloat16* __restrict__ m1l,
        float* __restrict__ dst6) {
    int z = blockIdx.z;
    int pair = z / 48, inner = z % 48;
    int which = inner >> 4, bc = inner & 15, c = bc & (Cn - 1);
    int tileM = blockIdx.y * 128, tileN = blockIdx.x * 128;
    size_t wofs = (size_t)pair * WOFF + ((size_t)c * Fn + tileM) * Fn;
    const __nv_bfloat16* Ah = (which == 0 ? WqH_ : which == 1 ? WkH_ : WvH_) + wofs;
    const __nv_bfloat16* Al = (which == 0 ? WqL_ : which == 1 ? WkL_ : WvL_) + wofs;
    const __nv_bfloat16* Bh = (which == 0 ? th : (pair == 0 ? m0h : m1h)) + ((size_t)bc * Wn + tileN) * Fn;
    const __nv_bfloat16* Bl = (which == 0 ? tl : (pair == 0 ? m0l : m1l)) + ((size_t)bc * Wn + tileN) * Fn;
    float* Y = dst6 + ((size_t)pair * 3 + which) * NB + ((size_t)bc * Fn + tileM) * Wn + tileN;
    gemm_body<false>(Ah, Al, Bh, Bl, Y);
}

// Wo GEMM over NP pairs, accumulating into h: grid (4, 2, 16)
template<int NP>
__global__ void __launch_bounds__(256) gemm_woN(
        const __nv_bfloat16* __restrict__ AhG, const __nv_bfloat16* __restrict__ AlG,
        const __nv_bfloat16* __restrict__ BhG, const __nv_bfloat16* __restrict__ BlG,
        float* __restrict__ Y) {
    extern __shared__ __nv_bfloat16 sm[];
    __nv_bfloat16* sAh = sm;
    __nv_bfloat16* sAl = sm + TELEM;
    __nv_bfloat16* sBh = sm + 2 * TELEM;
    __nv_bfloat16* sBl = sm + 3 * TELEM;
    int bc = blockIdx.z, c = bc & (Cn - 1);
    int tileM = blockIdx.y * 128, tileN = blockIdx.x * 128;
    int tid = threadIdx.x, lane = tid & 31, wid = tid >> 5;
    int wm = wid >> 2, wn = wid & 3;
    float acc[4][4][4] = {};
    int lrow = tid >> 1;
    int lq   = (tid & 1) * 4;
    uint32_t sb = smem_u32(sm);
    int grp = lane >> 3, lr = lane & 7;
    int aRow = wm * 64 + (grp & 1) * 8 + lr;
    int aCol = (grp >> 1) * 8;
    int bRow = wn * 32 + (grp >> 1) * 8 + lr;
    int bCol = (grp & 1) * 8;

#pragma unroll
    for (int pp = 0; pp < NP; pp++) {
        const __nv_bfloat16* gAh = AhG + (size_t)pp * WOFF + ((size_t)c * Fn + tileM) * Fn;
        const __nv_bfloat16* gAl = AlG + (size_t)pp * WOFF + ((size_t)c * Fn + tileM) * Fn;
        const __nv_bfloat16* gBh = BhG + (size_t)pp * AS + ((size_t)bc * Wn + tileN) * Fn;
        const __nv_bfloat16* gBl = BlG + (size_t)pp * AS + ((size_t)bc * Wn + tileN) * Fn;
        for (int kc = 0; kc < 4; kc++) {
            if (pp || kc) __syncthreads();
            const uint4* pa = (const uint4*)(gAh + (size_t)lrow * Fn + kc * KCn);
            const uint4* pb = (const uint4*)(gAl + (size_t)lrow * Fn + kc * KCn);
            const uint4* pc = (const uint4*)(gBh + (size_t)lrow * Fn + kc * KCn);
            const uint4* pd = (const uint4*)(gBl + (size_t)lrow * Fn + kc * KCn);
            uint4* qa = (uint4*)(sAh + lrow * LDT);
            uint4* qb = (uint4*)(sAl + lrow * LDT);
            uint4* qc = (uint4*)(sBh + lrow * LDT);
            uint4* qd = (uint4*)(sBl + lrow * LDT);
#pragma unroll
            for (int j = 0; j < 4; j++) {
                qa[lq + j] = pa[lq + j];
                qb[lq + j] = pb[lq + j];
                qc[lq + j] = pc[lq + j];
                qd[lq + j] = pd[lq + j];
            }
            __syncthreads();
#pragma unroll
            for (int ks = 0; ks < 4; ks++) {
                int k0 = ks * 16;
                uint32_t ah[4][4], al[4][4], bh[2][4], bl[2][4];
#pragma unroll
                for (int mi = 0; mi < 4; mi++) {
                    uint32_t off = ((aRow + mi * 16) * LDT + aCol + k0) * 2;
                    ldm_x4(ah[mi][0], ah[mi][1], ah[mi][2], ah[mi][3], sb + off);
                    ldm_x4(al[mi][0], al[mi][1], al[mi][2], al[mi][3], sb + TELEM * 2 + off);
                }
#pragma unroll
                for (int nb = 0; nb < 2; nb++) {
                    uint32_t off = ((bRow + nb * 16) * LDT + bCol + k0) * 2;
                    ldm_x4(bh[nb][0], bh[nb][1], bh[nb][2], bh[nb][3], sb + TELEM * 4 + off);
                    ldm_x4(bl[nb][0], bl[nb][1], bl[nb][2], bl[nb][3], sb + TELEM * 6 + off);
                }
#pragma unroll
                for (int mi = 0; mi < 4; mi++) {
#pragma unroll
                    for (int nb = 0; nb < 2; nb++) {
                        mma_bf16(acc[mi][2*nb],   ah[mi], &bh[nb][0]);
                        mma_bf16(acc[mi][2*nb+1], ah[mi], &bh[nb][2]);
                        mma_bf16(acc[mi][2*nb],   ah[mi], &bl[nb][0]);
                        mma_bf16(acc[mi][2*nb+1], ah[mi], &bl[nb][2]);
                        mma_bf16(acc[mi][2*nb],   al[mi], &bh[nb][0]);
                        mma_bf16(acc[mi][2*nb+1], al[mi], &bh[nb][2]);
                    }
                }
            }
        }
    }

    float* Yrow = Y + ((size_t)bc * Fn + tileM) * Wn + tileN;
#pragma unroll
    for (int mi = 0; mi < 4; mi++) {
        int row = wm * 64 + mi * 16 + (lane >> 2);
#pragma unroll
        for (int ni = 0; ni < 4; ni++) {
            int col = wn * 32 + ni * 8 + (lane & 3) * 2;
            float* p0 = Yrow + (size_t)row * Wn + col;
            float* p1 = p0 + 8 * Wn;
            float2 o0 = *(const float2*)p0, o1 = *(const float2*)p1;
            o0.x += acc[mi][ni][0]; o0.y += acc[mi][ni][1];
            o1.x += acc[mi][ni][2]; o1.y += acc[mi][ni][3];
            *(float2*)p0 = o0;
            *(float2*)p1 = o1;
        }
    }
}

// ======= conv3+bias (+RoPE) for Q/K/V, pair-capable: grid (4, 128, 6*NPAIR) =======
__global__ void __launch_bounds__(128) conv_qkv(const float* __restrict__ lin6,
                                                const float* __restrict__ KqG, const float* __restrict__ bqG,
                                                const float* __restrict__ KkG, const float* __restrict__ bkG,
                                                const float* __restrict__ KvG, const float* __restrict__ bvG,
                                                int i0,
                                                uint2* __restrict__ qI, uint2* __restrict__ kI,
                                                __nv_bfloat16* __restrict__ vbf) {
    __shared__ float sIn[Cn][2][132];
    __shared__ float ks[Cn * Cn * 3];
    int tid = threadIdx.x;
    int zz = blockIdx.z;
    int pair = zz / 6, r = zz % 6;
    int which = r >> 1, b = r & 1;
    int i = i0 + pair;
    const float* Lin = lin6 + ((size_t)pair * 3 + which) * NB;
    const float* Kc  = (which == 0 ? KqG : which == 1 ? KkG : KvG) + (size_t)i * Cn * Cn * 3;
    const float* bias = (which == 0 ? bqG : which == 1 ? bkG : bvG) + i * Cn;
    int w0 = blockIdx.x * 128;
    int p  = blockIdx.y;
    int f0 = 2 * p;
    for (int t = tid; t < Cn * 2 * 130; t += 128) {
        int ci = t / 260, rr = t % 260;
        int fi = rr / 130, wo = rr % 130;
        int gw = w0 + wo - 1;
        float v = (gw >= 0 && gw < Wn) ? Lin[((size_t)(b*Cn + ci) * Fn + f0 + fi) * Wn + gw] : 0.f;
        sIn[ci][fi][wo] = v;
    }
    for (int t = tid; t < Cn * Cn * 3; t += 128) ks[t] = Kc[t];
    __syncthreads();

    int w = w0 + tid;
    float cs = 1.f, sn = 0.f;
    if (which < 2) {
        int j = p & 15;
        float invf = exp10f(-0.25f * (float)j);
        sincosf((float)w * invf, &sn, &cs);
    }
    int h  = p >> 4;
    int jj = p & 15;
#pragma unroll
    for (int co = 0; co < Cn; co++) {
        float acc0 = bias[co], acc1 = acc0;
#pragma unroll
        for (int ci = 0; ci < Cn; ci++) {
            float k0 = ks[co*24 + ci*3], k1 = ks[co*24 + ci*3 + 1], k2 = ks[co*24 + ci*3 + 2];
            acc0 += k0 * sIn[ci][0][tid] + k1 * sIn[ci][0][tid+1] + k2 * sIn[ci][0][tid+2];
            acc1 += k0 * sIn[ci][1][tid] + k1 * sIn[ci][1][tid+1] + k2 * sIn[ci][1][tid+2];
        }
        size_t head = (size_t)(b*Cn + co) * Hn + h;
        size_t idx = (head * Wn + w) * 16 + jj;
        if (which < 2) {
            float o0 = acc0 * cs - acc1 * sn;
            float o1 = acc1 * cs + acc0 * sn;
            uint32_t lo, hi = pack_split(o0, o1, lo);
            (which == 0 ? qI : kI)[pair * QS + idx] = make_uint2(hi, lo);
        } else {
            ((__nv_bfloat162*)vbf)[pair * (VS/2) + idx] = __floats2bfloat162_rn(acc0, acc1);
        }
    }
}

// ========== tensor-core flash attention (2-term QK), register-prefetched staging ==========
// grid = 256*NPAIR blocks: pair = blockIdx.x >> 8, rest = blockIdx.x & 255
__global__ void __launch_bounds__(256, 1) attn_mma(const uint2* __restrict__ Qi,
                                                   const uint2* __restrict__ Ki,
                                                   const __nv_bfloat16* __restrict__ Vg,
                                                   __nv_bfloat16* __restrict__ AttH,
                                                   __nv_bfloat16* __restrict__ AttL) {
    __shared__ __nv_bfloat16 Kh[64][40];
    __shared__ __nv_bfloat16 Kl[64][40];
    __shared__ __nv_bfloat16 Vs[64][40];
    int pair = blockIdx.x >> 8, rest = blockIdx.x & 255;
    int head = rest >> 1, half = rest & 1;
    int tid = threadIdx.x, lane = tid & 31, wid = tid >> 5;
    int qb = half * 256 + wid * 32;
    size_t hbase = (size_t)head * Wn;
    Qi += pair * QS; Ki += pair * QS; Vg += pair * VS;
    AttH += pair * AS; AttL += pair * AS;

    uint32_t qh[2][2][4];
#pragma unroll
    for (int mi = 0; mi < 2; mi++) {
        int r0 = qb + mi * 16 + (lane >> 2);
#pragma unroll
        for (int kk = 0; kk < 2; kk++) {
            int jp = kk * 8 + (lane & 3);
            qh[mi][kk][0] = Qi[(hbase + r0) * 16 + jp].x;
            qh[mi][kk][1] = Qi[(hbase + r0 + 8) * 16 + jp].x;
            qh[mi][kk][2] = Qi[(hbase + r0) * 16 + jp + 4].x;
            qh[mi][kk][3] = Qi[(hbase + r0 + 8) * 16 + jp + 4].x;
        }
    }
    float m_[4] = {-1e30f, -1e30f, -1e30f, -1e30f};
    float l_[4] = {0.f, 0.f, 0.f, 0.f};
    float o[2][4][4] = {};
    uint32_t sbK = smem_u32(Kh), sbKl = smem_u32(Kl), sbV = smem_u32(Vs);
    int grp = lane >> 3, lr = lane & 7;
    int rowV = tid >> 2, qV = tid & 3;

    // register prefetch buffers
    uint2 kreg[4];
    uint4 vreg;
#pragma unroll
    for (int it = 0; it < 4; it++) {
        int idx = tid + it * 256;
        kreg[it] = Ki[(hbase + (idx >> 4)) * 16 + (idx & 15)];
    }
    vreg = ((const uint4*)(Vg + (hbase + rowV) * HDn))[qV];

    for (int kt = 0; kt < 8; kt++) {
        // stage prefetched regs into smem
#pragma unroll
        for (int it = 0; it < 4; it++) {
            int idx = tid + it * 256;
            int row = idx >> 4, j = idx & 15;
            ((uint32_t*)&Kh[row][0])[j] = kreg[it].x;
            ((uint32_t*)&Kl[row][0])[j] = kreg[it].y;
        }
        *((uint4*)&Vs[rowV][qV * 8]) = vreg;
        __syncthreads();
        // issue next tile's loads early (hidden behind compute)
        if (kt < 7) {
            int kb = (kt + 1) * 64;
#pragma unroll
            for (int it = 0; it < 4; it++) {
                int idx = tid + it * 256;
                kreg[it] = Ki[(hbase + kb + (idx >> 4)) * 16 + (idx & 15)];
            }
            vreg = ((const uint4*)(Vg + (hbase + kb + rowV) * HDn))[qV];
        }

        float s[2][8][4] = {};
#pragma unroll
        for (int kk = 0; kk < 2; kk++) {
#pragma unroll
            for (int nb = 0; nb < 4; nb++) {
                uint32_t kh4[4], kl4[4];
                uint32_t off = ((nb * 16 + (grp >> 1) * 8 + lr) * 40 + (grp & 1) * 8 + kk * 16) * 2;
                ldm_x4(kh4[0], kh4[1], kh4[2], kh4[3], sbK + off);
                ldm_x4(kl4[0], kl4[1], kl4[2], kl4[3], sbKl + off);
#pragma unroll
                for (int mi = 0; mi < 2; mi++) {
                    mma_bf16(s[mi][2*nb],   qh[mi][kk], &kh4[0]);
                    mma_bf16(s[mi][2*nb+1], qh[mi][kk], &kh4[2]);
                    mma_bf16(s[mi][2*nb],   qh[mi][kk], &kl4[0]);
                    mma_bf16(s[mi][2*nb+1], qh[mi][kk], &kl4[2]);
                }
            }
        }

        uint32_t pa[2][4][4];
#pragma unroll
        for (int mi = 0; mi < 2; mi++) {
            float mx0 = -1e30f, mx1 = -1e30f;
#pragma unroll
            for (int n = 0; n < 8; n++) {
#pragma unroll
                for (int q = 0; q < 4; q++) s[mi][n][q] *= 0.0625f;
                mx0 = fmaxf(mx0, fmaxf(s[mi][n][0], s[mi][n][1]));
                mx1 = fmaxf(mx1, fmaxf(s[mi][n][2], s[mi][n][3]));
            }
            mx0 = fmaxf(mx0, __shfl_xor_sync(0xffffffffu, mx0, 1));
            mx0 = fmaxf(mx0, __shfl_xor_sync(0xffffffffu, mx0, 2));
            mx1 = fmaxf(mx1, __shfl_xor_sync(0xffffffffu, mx1, 1));
            mx1 = fmaxf(mx1, __shfl_xor_sync(0xffffffffu, mx1, 2));
            int si = mi * 2;
            float mn0 = fmaxf(m_[si], mx0), mn1 = fmaxf(m_[si+1], mx1);
            float c0 = __expf(m_[si] - mn0), c1 = __expf(m_[si+1] - mn1);
            m_[si] = mn0; m_[si+1] = mn1;
            float ls0 = 0.f, ls1 = 0.f;
#pragma unroll
            for (int n = 0; n < 8; n++) {
                float p0 = __expf(s[mi][n][0] - mn0);
                float p1 = __expf(s[mi][n][1] - mn0);
                float p2 = __expf(s[mi][n][2] - mn1);
                float p3 = __expf(s[mi][n][3] - mn1);
                ls0 += p0 + p1; ls1 += p2 + p3;
                s[mi][n][0] = p0; s[mi][n][1] = p1; s[mi][n][2] = p2; s[mi][n][3] = p3;
            }
            ls0 += __shfl_xor_sync(0xffffffffu, ls0, 1);
            ls0 += __shfl_xor_sync(0xffffffffu, ls0, 2);
            ls1 += __shfl_xor_sync(0xffffffffu, ls1, 1);
            ls1 += __shfl_xor_sync(0xffffffffu, ls1, 2);
            l_[si]   = l_[si]   * c0 + ls0;
            l_[si+1] = l_[si+1] * c1 + ls1;
#pragma unroll
            for (int dn = 0; dn < 4; dn++) {
                o[mi][dn][0] *= c0; o[mi][dn][1] *= c0;
                o[mi][dn][2] *= c1; o[mi][dn][3] *= c1;
            }
#pragma unroll
            for (int t = 0; t < 4; t++) {
                pa[mi][t][0] = packbf(s[mi][2*t][0],   s[mi][2*t][1]);
                pa[mi][t][1] = packbf(s[mi][2*t][2],   s[mi][2*t][3]);
                pa[mi][t][2] = packbf(s[mi][2*t+1][0], s[mi][2*t+1][1]);
                pa[mi][t][3] = packbf(s[mi][2*t+1][2], s[mi][2*t+1][3]);
            }
        }

#pragma unroll
        for (int dn = 0; dn < 4; dn++) {
            uint32_t vb[4][2];
#pragma unroll
            for (int t = 0; t < 4; t++) {
                uint32_t off = ((t * 16 + (lane & 15)) * 40 + dn * 8) * 2;
                ldm_x2_trans(vb[t][0], vb[t][1], sbV + off);
            }
#pragma unroll
            for (int mi = 0; mi < 2; mi++)
#pragma unroll
                for (int t = 0; t < 4; t++)
                    mma_bf16(o[mi][dn], pa[mi][t], vb[t]);
        }
        __syncthreads();
    }

    int bc = head >> 3, hh = head & 7;
#pragma unroll
    for (int mi = 0; mi < 2; mi++) {
        int r0 = qb + mi * 16 + (lane >> 2);
        float i0 = 1.0f / l_[mi*2], i1 = 1.0f / l_[mi*2 + 1];
#pragma unroll
        for (int dn = 0; dn < 4; dn++) {
            int d0 = dn * 8 + (lane & 3) * 2;
            size_t a0 = ((size_t)bc * Wn + r0) * Fn + hh * HDn + d0;
            size_t a1 = ((size_t)bc * Wn + r0 + 8) * Fn + hh * HDn + d0;
            uint32_t lo0, hi0 = pack_split(o[mi][dn][0] * i0, o[mi][dn][1] * i0, lo0);
            uint32_t lo1, hi1 = pack_split(o[mi][dn][2] * i1, o[mi][dn][3] * i1, lo1);
            *(uint32_t*)(AttH + a0) = hi0;
            *(uint32_t*)(AttL + a0) = lo0;
            *(uint32_t*)(AttH + a1) = hi1;
            *(uint32_t*)(AttL + a1) = lo1;
        }
    }
}

// ============ fused LN + depthwise convs (k11 sq_relu + k7) ============
__global__ void __launch_bounds__(256) lnconv_ab(const float* __restrict__ X,
                                                 const float* __restrict__ gam,
                                                 const float* __restrict__ bet,
                                                 const float* __restrict__ k11, const float* __restrict__ b11,
                                                 const float* __restrict__ k7,  const float* __restrict__ b7,
                                                 float* __restrict__ Yo) {
    extern __shared__ float sZ[];
    __shared__ float gs[Fn], bs[Fn], ps[4][64], ps2[4][64], mb[64], ib[64];
    int tid = threadIdx.x, w = tid & 63, fg = tid >> 6;
    int bc = blockIdx.y, c = bc & (Cn - 1);
    int w0 = blockIdx.x * 64;
    const float* xp = X + (size_t)bc * Fn * Wn + w0;
    for (int i = tid; i < Fn * 64; i += 256)
        sZ[i] = xp[(size_t)(i >> 6) * Wn + (i & 63)];
    for (int i = tid; i < Fn; i += 256) { gs[i] = gam[c * Fn + i]; bs[i] = bet[c * Fn + i]; }
    __syncthreads();
    float s = 0.f, s2 = 0.f;
#pragma unroll 4
    for (int f = fg * 64; f < fg * 64 + 64; f++) {
        float v = sZ[f * 64 + w];
        s += v; s2 += v * v;
    }
    ps[fg][w] = s; ps2[fg][w] = s2;
    __syncthreads();
    if (fg == 0) {
        float S  = ps[0][w]  + ps[1][w]  + ps[2][w]  + ps[3][w];
        float S2 = ps2[0][w] + ps2[1][w] + ps2[2][w] + ps2[3][w];
        float m = S * (1.0f / Fn);
        mb[w] = m;
        ib[w] = rsqrtf(S2 * (1.0f / Fn) - m * m + 1e-5f);
    }
    __syncthreads();
    float m = mb[w], inv = ib[w];
#pragma unroll 4
    for (int f = fg * 64; f < fg * 64 + 64; f++)
        sZ[f * 64 + w] = (sZ[f * 64 + w] - m) * inv * gs[f] + bs[f];
    __syncthreads();
    float wk11[11], wk7[7];
#pragma unroll
    for (int t = 0; t < 11; t++) wk11[t] = k11[c * 11 + t];
#pragma unroll
    for (int t = 0; t < 7; t++)  wk7[t]  = k7[c * 7 + t];
    float bb11 = b11[c], bb7 = b7[c];
    float* yo = Yo + (size_t)bc * Fn * Wn + w0 + w;
    for (int f = fg * 64; f < fg * 64 + 64; f++) {
        float a = bb11;
#pragma unroll
        for (int t = 0; t < 11; t++) {
            int ff = f - 5 + t;
            if (ff >= 0 && ff < Fn) a += sZ[ff * 64 + w] * wk11[t];
        }
        a = fmaxf(a, 0.f); a = a * a;
        float bo = bb7;
#pragma unroll
        for (int t = 0; t < 7; t++) {
            int ff = f - 3 + t;
            if (ff >= 0 && ff < Fn) bo += sZ[ff * 64 + w] * wk7[t];
        }
        yo[(size_t)f * Wn] = a + bo;
    }
}

// ============ fused LN + k7 conv + residual add into H ============
__global__ void __launch_bounds__(256) lnconv2_add(const float* __restrict__ X,
                                                   const float* __restrict__ gam,
                                                   const float* __restrict__ bet,
                                                   const float* __restrict__ k7, const float* __restrict__ b7,
                                                   float* __restrict__ Hb) {
    extern __shared__ float sZ[];
    __shared__ float gs[Fn], bs[Fn], ps[4][64], ps2[4][64], mb[64], ib[64];
    int tid = threadIdx.x, w = tid & 63, fg = tid >> 6;
    int bc = blockIdx.y, c = bc & (Cn - 1);
    int w0 = blockIdx.x * 64;
    const float* xp = X + (size_t)bc * Fn * Wn + w0;
    for (int i = tid; i < Fn * 64; i += 256)
        sZ[i] = xp[(size_t)(i >> 6) * Wn + (i & 63)];
    for (int i = tid; i < Fn; i += 256) { gs[i] = gam[c * Fn + i]; bs[i] = bet[c * Fn + i]; }
    __syncthreads();
    float s = 0.f, s2 = 0.f;
#pragma unroll 4
    for (int f = fg * 64; f < fg * 64 + 64; f++) {
        float v = sZ[f * 64 + w];
        s += v; s2 += v * v;
    }
    ps[fg][w] = s; ps2[fg][w] = s2;
    __syncthreads();
    if (fg == 0) {
        float S  = ps[0][w]  + ps[1][w]  + ps[2][w]  + ps[3][w];
        float S2 = ps2[0][w] + ps2[1][w] + ps2[2][w] + ps2[3][w];
        float m = S * (1.0f / Fn);
        mb[w] = m;
        ib[w] = rsqrtf(S2 * (1.0f / Fn) - m * m + 1e-5f);
    }
    __syncthreads();
    float m = mb[w], inv = ib[w];
#pragma unroll 4
    for (int f = fg * 64; f < fg * 64 + 64; f++)
        sZ[f * 64 + w] = (sZ[f * 64 + w] - m) * inv * gs[f] + bs[f];
    __syncthreads();
    float wk7[7];
#pragma unroll
    for (int t = 0; t < 7; t++) wk7[t] = k7[c * 7 + t];
    float bb7 = b7[c];
    float* hb = Hb + (size_t)bc * Fn * Wn + w0 + w;
    for (int f = fg * 64; f < fg * 64 + 64; f++) {
        float v = bb7;
#pragma unroll
        for (int t = 0; t < 7; t++) {
            int ff = f - 3 + t;
            if (ff >= 0 && ff < Fn) v += sZ[ff * 64 + w] * wk7[t];
        }
        hb[(size_t)f * Wn] += v;
    }
}

// ============ fused LN + FFN first layer ============
__global__ void __launch_bounds__(256) ln_ffn3(const float* __restrict__ X,
                                               const float* __restrict__ gam,
                                               const float* __restrict__ bet,
                                               const float* __restrict__ w3,
                                               float* __restrict__ T) {
    extern __shared__ float sZ[];
    __shared__ float ws[En * Fn], gs[Fn], bs[Fn];
    __shared__ float ps[4][64], ps2[4][64], mb[64], ib[64];
    __shared__ float pacc[4][En][64];
    int tid = threadIdx.x, w = tid & 63, fg = tid >> 6;
    int bc = blockIdx.y, c = bc & (Cn - 1);
    int w0 = blockIdx.x * 64;
    const float* xp = X + (size_t)bc * Fn * Wn + w0;
    for (int i = tid; i < Fn * 64; i += 256)
        sZ[i] = xp[(size_t)(i >> 6) * Wn + (i & 63)];
    for (int i = tid; i < En * Fn; i += 256) ws[i] = w3[c * En * Fn + i];
    for (int i = tid; i < Fn; i += 256) { gs[i] = gam[c * Fn + i]; bs[i] = bet[c * Fn + i]; }
    __syncthreads();
    float s = 0.f, s2 = 0.f;
#pragma unroll 4
    for (int f = fg * 64; f < fg * 64 + 64; f++) {
        float v = sZ[f * 64 + w];
        s += v; s2 += v * v;
    }
    ps[fg][w] = s; ps2[fg][w] = s2;
    __syncthreads();
    if (fg == 0) {
        float S  = ps[0][w]  + ps[1][w]  + ps[2][w]  + ps[3][w];
        float S2 = ps2[0][w] + ps2[1][w] + ps2[2][w] + ps2[3][w];
        float m = S * (1.0f / Fn);
        mb[w] = m;
        ib[w] = rsqrtf(S2 * (1.0f / Fn) - m * m + 1e-5f);
    }
    __syncthreads();
    float m = mb[w], inv = ib[w];
    float acc[En] = {};
#pragma unroll 4
    for (int f = fg * 64; f < fg * 64 + 64; f++) {
        float zn = (sZ[f * 64 + w] - m) * inv * gs[f] + bs[f];
#pragma unroll
        for (int e = 0; e < En; e++) acc[e] += zn * ws[e * Fn + f];
    }
#pragma unroll
    for (int e = 0; e < En; e++) pacc[fg][e][w] = acc[e];
    __syncthreads();
    if (fg == 0) {
        float* tp = T + (size_t)bc * En * Wn + w0 + w;
#pragma unroll
        for (int e = 0; e < En; e++) {
            float v = pacc[0][e][w] + pacc[1][e][w] + pacc[2][e][w] + pacc[3][e][w];
            v = fmaxf(v, 0.f);
            tp[(size_t)e * Wn] = v * v;
        }
    }
}

// ============ fused FFN second layer + residual + concat output ============
__global__ void ffn4_write(const float* __restrict__ T, const float* __restrict__ w4,
                           const float* __restrict__ Hb, const float* __restrict__ X,
                           float* __restrict__ O) {
    int idx = blockIdx.x * 256 + threadIdx.x;
    int w  = idx & (Wn - 1);
    int f  = (idx >> 9) & (Fn - 1);
    int bc = idx >> 17;
    int c  = bc & (Cn - 1);
    const float* tp = T + (size_t)bc * En * Wn + w;
    const float* wp = w4 + ((size_t)c * Fn + f) * En;
    float v = tp[0] * wp[0] + tp[Wn] * wp[1] + tp[2 * Wn] * wp[2] + tp[3 * Wn] * wp[3];
    float h = Hb[idx] + v;
    int b = idx / (Cn * Fn * Wn);
    int r = idx - b * (Cn * Fn * Wn);
    O[(size_t)b * 2 * Cn * Fn * Wn + r] = X[idx];
    O[(size_t)b * 2 * Cn * Fn * Wn + Cn * Fn * Wn + r] = h;
}

__global__ void copy_x(const float* __restrict__ X, float* __restrict__ Hb) {
    int i = blockIdx.x * 256 + threadIdx.x;
    ((float4*)Hb)[i] = ((const float4*)X)[i];
}

// =====================================================================================

extern "C" void kernel_launch(void* const* d_in, const int* in_sizes, int n_in,
                              void* d_out, int out_size) {
    const float* x     = (const float*)d_in[0];
    const float* skip  = (const float*)d_in[1];
    const float* Wq    = (const float*)d_in[2];
    const float* Kq    = (const float*)d_in[3];
    const float* bq    = (const float*)d_in[4];
    const float* Wk    = (const float*)d_in[5];
    const float* Kk    = (const float*)d_in[6];
    const float* bk    = (const float*)d_in[7];
    const float* Wv    = (const float*)d_in[8];
    const float* Kv    = (const float*)d_in[9];
    const float* bv    = (const float*)d_in[10];
    const float* Wo    = (const float*)d_in[11];
    const float* ng    = (const float*)d_in[12];
    const float* nbet  = (const float*)d_in[13];
    const float* c1a_w = (const float*)d_in[14];
    const float* c1a_b = (const float*)d_in[15];
    const float* c1b_w = (const float*)d_in[16];
    const float* c1b_b = (const float*)d_in[17];
    const float* c2_w  = (const float*)d_in[18];
    const float* c2_b  = (const float*)d_in[19];
    const float* w3    = (const float*)d_in[20];
    const float* w4    = (const float*)d_in[21];
    float* out = (float*)d_out;

    float *hB, *lin6B, *t1B, *ffnB;
    cudaGetSymbolAddress((void**)&hB,    g_h);
    cudaGetSymbolAddress((void**)&lin6B, g_lin6);
    cudaGetSymbolAddress((void**)&t1B,   g_t1);
    cudaGetSymbolAddress((void**)&ffnB,  g_ffn);
    uint2 *qI, *kI;
    __nv_bfloat16 *vBf;
    cudaGetSymbolAddress((void**)&qI,  g_qI);
    cudaGetSymbolAddress((void**)&kI,  g_kI);
    cudaGetSymbolAddress((void**)&vBf, g_vbf);
    __nv_bfloat16 *zTh, *zTl, *skTh, *skTl, *atTh, *atTl;
    __nv_bfloat16 *WqH, *WqL, *WkH, *WkL, *WvH, *WvL, *WoH, *WoL;
    cudaGetSymbolAddress((void**)&zTh,  g_zTh);  cudaGetSymbolAddress((void**)&zTl,  g_zTl);
    cudaGetSymbolAddress((void**)&skTh, g_skTh); cudaGetSymbolAddress((void**)&skTl, g_skTl);
    cudaGetSymbolAddress((void**)&atTh, g_atTh); cudaGetSymbolAddress((void**)&atTl, g_atTl);
    cudaGetSymbolAddress((void**)&WqH, g_WqH); cudaGetSymbolAddress((void**)&WqL, g_WqL);
    cudaGetSymbolAddress((void**)&WkH, g_WkH); cudaGetSymbolAddress((void**)&WkL, g_WkL);
    cudaGetSymbolAddress((void**)&WvH, g_WvH); cudaGetSymbolAddress((void**)&WvL, g_WvL);
    cudaGetSymbolAddress((void**)&WoH, g_WoH); cudaGetSymbolAddress((void**)&WoL, g_WoL);

    const int TSM = Fn * 64 * 4;
    cudaFuncSetAttribute(gemm_qkv,    cudaFuncAttributeMaxDynamicSharedMemorySize, GSM);
    cudaFuncSetAttribute(gemm_woN<1>, cudaFuncAttributeMaxDynamicSharedMemorySize, GSM);
    cudaFuncSetAttribute(gemm_woN<2>, cudaFuncAttributeMaxDynamicSharedMemorySize, GSM);
    cudaFuncSetAttribute(lnconv_ab,   cudaFuncAttributeMaxDynamicSharedMemorySize, TSM);
    cudaFuncSetAttribute(lnconv2_add, cudaFuncAttributeMaxDynamicSharedMemorySize, TSM);
    cudaFuncSetAttribute(ln_ffn3,     cudaFuncAttributeMaxDynamicSharedMemorySize, TSM);

    const int nElemBlocks = NB / 256;
    const int wBlocks = (4 * WOFF) / 1024;
    const dim3 gLN(Wn / 16, Bn * Cn);
    const dim3 gT64(Wn / 64, Bn * Cn);

    wsplit_all<<<dim3(wBlocks, 4), 256>>>(Wq, Wk, Wv, Wo,
                                          WqH, WqL, WkH, WkL, WvH, WvL, WoH, WoL);
    tsplit_kernel<<<dim3(Wn/32, Fn/32, Bn*Cn), dim3(32, 8)>>>(skip, skTh, skTl);
    copy_x<<<NB / 1024, 256>>>(x, hB);

    auto run_ln_t = [&](const float* X, int gi) {
        ln_t_v4<<<gLN, 256>>>(X, ng + gi * Cn * Fn, nbet + gi * Cn * Fn, zTh, zTl);
    };

    // --- att0 + att1 as one batched pair (z = LN0(x); mem0 = z, mem1 = skip) ---
    run_ln_t(x, 0);
    gemm_qkv<<<dim3(4, 2, 96), 256, GSM>>>(WqH, WqL, WkH, WkL, WvH, WvL,
                                           zTh, zTl, zTh, zTl, skTh, skTl, lin6B);
    conv_qkv<<<dim3(4, 128, 12), 128>>>(lin6B, Kq, bq, Kk, bk, Kv, bv, 0, qI, kI, vBf);
    attn_mma<<<512, 256>>>(qI, kI, vBf, atTh, atTl);
    gemm_woN<2><<<dim3(4, 2, 16), 256, GSM>>>(WoH, WoL, atTh, atTl, hB);

    // conv block
    lnconv_ab<<<gT64, 256, TSM>>>(hB, ng + 1 * Cn * Fn, nbet + 1 * Cn * Fn,
                                  c1a_w, c1a_b, c1b_w, c1b_b, t1B);
    lnconv2_add<<<gT64, 256, TSM>>>(t1B, ng + 2 * Cn * Fn, nbet + 2 * Cn * Fn,
                                    c2_w, c2_b, hB);

    // h += att2(LN3(h), same)
    run_ln_t(hB, 3);
    gemm_qkv<<<dim3(4, 2, 48), 256, GSM>>>(WqH + 2*(size_t)WOFF, WqL + 2*(size_t)WOFF,
                                           WkH + 2*(size_t)WOFF, WkL + 2*(size_t)WOFF,
                                           WvH + 2*(size_t)WOFF, WvL + 2*(size_t)WOFF,
                                           zTh, zTl, zTh, zTl, zTh, zTl, lin6B);
    conv_qkv<<<dim3(4, 128, 6), 128>>>(lin6B, Kq, bq, Kk, bk, Kv, bv, 2, qI, kI, vBf);
    attn_mma<<<256, 256>>>(qI, kI, vBf, atTh, atTl);
    gemm_woN<1><<<dim3(4, 2, 16), 256, GSM>>>(WoH + 2*(size_t)WOFF, WoL + 2*(size_t)WOFF,
                                              atTh, atTl, hB);

    // h += att3(LN4(h), skip)
    run_ln_t(hB, 4);
    gemm_qkv<<<dim3(4, 2, 48), 256, GSM>>>(WqH + 3*(size_t)WOFF, WqL + 3*(size_t)WOFF,
                                           WkH + 3*(size_t)WOFF, WkL + 3*(size_t)WOFF,
                                           WvH + 3*(size_t)WOFF, WvL + 3*(size_t)WOFF,
                                           zTh, zTl, skTh, skTl, skTh, skTl, lin6B);
    conv_qkv<<<dim3(4, 128, 6), 128>>>(lin6B, Kq, bq, Kk, bk, Kv, bv, 3, qI, kI, vBf);
    attn_mma<<<256, 256>>>(qI, kI, vBf, atTh, atTl);
    gemm_woN<1><<<dim3(4, 2, 16), 256, GSM>>>(WoH + 3*(size_t)WOFF, WoL + 3*(size_t)WOFF,
                                              atTh, atTl, hB);

    // FFN (LN5 fused into ffn3; ffn4 fused with concat output)
    ln_ffn3<<<gT64, 256, TSM>>>(hB, ng + 5 * Cn * Fn, nbet + 5 * Cn * Fn, w3, ffnB);
    ffn4_write<<<nElemBlocks, 256>>>(ffnB, w4, hB, x, out);
}

// round 14
// speedup vs baseline: 3.0296x; 1.0165x over previous
#include <cuda_runtime.h>
#include <cuda_bf16.h>
#include <math.h>
#include <stdint.h>

#define Bn 2
#define Cn 8
#define Fn 256
#define Wn 512
#define Hn 8
#define HDn 32
#define En 4
#define NB (Bn*Cn*Fn*Wn)
#define WOFF (Cn*Fn*Fn)
#define NHEAD (Bn*Cn*Hn)
#define QS ((size_t)NHEAD*Wn*16)
#define VS ((size_t)NHEAD*Wn*HDn)
#define AS ((size_t)Bn*Cn*Wn*Fn)

// ======================= warp-MMA helpers (baseline PTX, sm_80+) =======================
__device__ __forceinline__ uint32_t smem_u32(const void* p) {
    uint32_t a;
    asm("{ .reg .u64 t; cvta.to.shared.u64 t, %1; cvt.u32.u64 %0, t; }" : "=r"(a) : "l"(p));
    return a;
}
__device__ __forceinline__ void ldm_x4(uint32_t& r0, uint32_t& r1, uint32_t& r2, uint32_t& r3,
                                       uint32_t addr) {
    asm volatile("ldmatrix.sync.aligned.m8n8.x4.shared.b16 {%0,%1,%2,%3}, [%4];"
                 : "=r"(r0), "=r"(r1), "=r"(r2), "=r"(r3) : "r"(addr));
}
__device__ __forceinline__ void ldm_x2_trans(uint32_t& r0, uint32_t& r1, uint32_t addr) {
    asm volatile("ldmatrix.sync.aligned.m8n8.x2.trans.shared.b16 {%0,%1}, [%2];"
                 : "=r"(r0), "=r"(r1) : "r"(addr));
}
__device__ __forceinline__ void mma_bf16(float* d, const uint32_t* a, const uint32_t* b) {
    asm volatile("mma.sync.aligned.m16n8k16.row.col.f32.bf16.bf16.f32 "
                 "{%0,%1,%2,%3}, {%4,%5,%6,%7}, {%8,%9}, {%0,%1,%2,%3};"
                 : "+f"(d[0]), "+f"(d[1]), "+f"(d[2]), "+f"(d[3])
                 : "r"(a[0]), "r"(a[1]), "r"(a[2]), "r"(a[3]), "r"(b[0]), "r"(b[1]));
}
__device__ __forceinline__ uint32_t pack_split(float a, float b, uint32_t& lo) {
    __nv_bfloat16 ha = __float2bfloat16(a), hb = __float2bfloat16(b);
    __nv_bfloat16 la = __float2bfloat16(a - __bfloat162float(ha));
    __nv_bfloat16 lb = __float2bfloat16(b - __bfloat162float(hb));
    lo = (uint32_t)__bfloat16_as_ushort(la) | ((uint32_t)__bfloat16_as_ushort(lb) << 16);
    return (uint32_t)__bfloat16_as_ushort(ha) | ((uint32_t)__bfloat16_as_ushort(hb) << 16);
}
__device__ __forceinline__ uint32_t packbf(float a, float b) {
    __nv_bfloat162 v = __floats2bfloat162_rn(a, b);
    return *(uint32_t*)&v;
}

// ======================= scratch (device globals) =======================
__device__ float g_h[NB];
__device__ float g_lin6[6*NB];
__device__ float g_t1[NB];
__device__ float g_ffn[Bn*Cn*En*Wn];
__device__ uint2 g_qI[2*NHEAD*Wn*16];
__device__ uint2 g_kI[2*NHEAD*Wn*16];
__device__ __nv_bfloat16 g_vbf[2*NHEAD*Wn*HDn];
__device__ __nv_bfloat16 g_zTh[Bn*Cn*Wn*Fn];
__device__ __nv_bfloat16 g_zTl[Bn*Cn*Wn*Fn];
__device__ __nv_bfloat16 g_skTh[Bn*Cn*Wn*Fn];
__device__ __nv_bfloat16 g_skTl[Bn*Cn*Wn*Fn];
__device__ __nv_bfloat16 g_atTh[2*Bn*Cn*Wn*Fn];
__device__ __nv_bfloat16 g_atTl[2*Bn*Cn*Wn*Fn];
__device__ __nv_bfloat16 g_WqH[4*WOFF]; __device__ __nv_bfloat16 g_WqL[4*WOFF];
__device__ __nv_bfloat16 g_WkH[4*WOFF]; __device__ __nv_bfloat16 g_WkL[4*WOFF];
__device__ __nv_bfloat16 g_WvH[4*WOFF]; __device__ __nv_bfloat16 g_WvL[4*WOFF];
__device__ __nv_bfloat16 g_WoH[4*WOFF]; __device__ __nv_bfloat16 g_WoL[4*WOFF];

// ============ LayerNorm -> transposed bf16 hi/lo; grid (32, 16), blk 256 = 16w x 16fg ============
__global__ void __launch_bounds__(256) ln_t_v4(const float* __restrict__ X,
                                               const float* __restrict__ gam,
                                               const float* __restrict__ bet,
                                               __nv_bfloat16* __restrict__ Zh,
                                               __nv_bfloat16* __restrict__ Zl) {
    __shared__ float ps[16][17], ps2[16][17], mb[16], ib[16];
    int tid = threadIdx.x, w = tid & 15, fg = tid >> 4;
    int bc = blockIdx.y, c = bc & (Cn - 1);
    int w0 = blockIdx.x * 16;
    const float* xp = X + (size_t)bc * Fn * Wn + w0 + w;
    float s = 0.f, s2 = 0.f;
#pragma unroll 4
    for (int f = fg * 16; f < fg * 16 + 16; f++) {
        float v = xp[(size_t)f * Wn];
        s += v; s2 += v * v;
    }
    ps[fg][w] = s; ps2[fg][w] = s2;
    __syncthreads();
    if (tid < 16) {
        float S = 0.f, S2 = 0.f;
#pragma unroll
        for (int g = 0; g < 16; g++) { S += ps[g][tid]; S2 += ps2[g][tid]; }
        float m = S * (1.0f / Fn);
        mb[tid] = m;
        ib[tid] = rsqrtf(S2 * (1.0f / Fn) - m * m + 1e-5f);
    }
    __syncthreads();
    float m = mb[w], inv = ib[w];
    const float* gp = gam + c * Fn;
    const float* bp = bet + c * Fn;
    __nv_bfloat16* th = Zh + ((size_t)bc * Wn + w0 + w) * Fn;
    __nv_bfloat16* tl = Zl + ((size_t)bc * Wn + w0 + w) * Fn;
    for (int f0 = fg * 16; f0 < fg * 16 + 16; f0 += 8) {
        uint32_t ph[4], pl[4];
#pragma unroll
        for (int j = 0; j < 4; j++) {
            int f = f0 + 2 * j;
            float v0 = (xp[(size_t)f * Wn]     - m) * inv * gp[f]   + bp[f];
            float v1 = (xp[(size_t)(f+1) * Wn] - m) * inv * gp[f+1] + bp[f+1];
            ph[j] = pack_split(v0, v1, pl[j]);
        }
        *(uint4*)(th + f0) = make_uint4(ph[0], ph[1], ph[2], ph[3]);
        *(uint4*)(tl + f0) = make_uint4(pl[0], pl[1], pl[2], pl[3]);
    }
}

// ============ transpose + split: (b,c,f,w) fp32 -> [bc][w][f] bf16 hi/lo ============
__global__ void tsplit_kernel(const float* __restrict__ X,
                              __nv_bfloat16* __restrict__ Th, __nv_bfloat16* __restrict__ Tl) {
    __shared__ float t[32][33];
    int bc = blockIdx.z;
    int w0 = blockIdx.x * 32, f0 = blockIdx.y * 32;
    const float* xp = X + ((size_t)bc * Fn + f0) * Wn + w0;
#pragma unroll
    for (int i = 0; i < 4; i++) {
        int fr = threadIdx.y + i * 8;
        t[fr][threadIdx.x] = xp[(size_t)fr * Wn + threadIdx.x];
    }
    __syncthreads();
#pragma unroll
    for (int i = 0; i < 4; i++) {
        int wr = threadIdx.y + i * 8;
        float v = t[threadIdx.x][wr];
        __nv_bfloat16 h = __float2bfloat16(v);
        __nv_bfloat16 l = __float2bfloat16(v - __bfloat162float(h));
        size_t idx = ((size_t)bc * Wn + w0 + wr) * Fn + f0 + threadIdx.x;
        Th[idx] = h; Tl[idx] = l;
    }
}

// ============ weight split: all four weight tensors in one launch ============
__global__ void wsplit_all(const float* __restrict__ S0, const float* __restrict__ S1,
                           const float* __restrict__ S2, const float* __restrict__ S3,
                           __nv_bfloat16* H0, __nv_bfloat16* L0,
                           __nv_bfloat16* H1, __nv_bfloat16* L1,
                           __nv_bfloat16* H2, __nv_bfloat16* L2,
                           __nv_bfloat16* H3, __nv_bfloat16* L3) {
    int which = blockIdx.y;
    const float* X = which == 0 ? S0 : which == 1 ? S1 : which == 2 ? S2 : S3;
    __nv_bfloat16* H = which == 0 ? H0 : which == 1 ? H1 : which == 2 ? H2 : H3;
    __nv_bfloat16* L = which == 0 ? L0 : which == 1 ? L1 : which == 2 ? L2 : L3;
    int i = (blockIdx.x * 256 + threadIdx.x) * 4;
    float4 v = *(const float4*)(X + i);
    uint32_t l0, l1;
    uint32_t h0 = pack_split(v.x, v.y, l0);
    uint32_t h1 = pack_split(v.z, v.w, l1);
    *(uint2*)((unsigned short*)H + i) = make_uint2(h0, h1);
    *(uint2*)((unsigned short*)L + i) = make_uint2(l0, l1);
}

// ======================= synchronous-staging 3xBF16 GEMM body (proven) =======================
#define KCn 64
#define LDT 72
#define TELEM (128 * LDT)
#define GSM (4 * TELEM * 2)          // 73728 bytes

template<bool ACC>
__device__ __forceinline__ void gemm_body(const __nv_bfloat16* __restrict__ gAh,
                                          const __nv_bfloat16* __restrict__ gAl,
                                          const __nv_bfloat16* __restrict__ gBh,
                                          const __nv_bfloat16* __restrict__ gBl,
                                          float* __restrict__ Yrow) {
    extern __shared__ __nv_bfloat16 sm[];
    __nv_bfloat16* sAh = sm;
    __nv_bfloat16* sAl = sm + TELEM;
    __nv_bfloat16* sBh = sm + 2 * TELEM;
    __nv_bfloat16* sBl = sm + 3 * TELEM;
    int tid = threadIdx.x, lane = tid & 31, wid = tid >> 5;
    int wm = wid >> 2, wn = wid & 3;

    float acc[4][4][4] = {};
    int lrow = tid >> 1;
    int lq   = (tid & 1) * 4;

    uint32_t sb = smem_u32(sm);
    int grp = lane >> 3, lr = lane & 7;
    int aRow = wm * 64 + (grp & 1) * 8 + lr;
    int aCol = (grp >> 1) * 8;
    int bRow = wn * 32 + (grp >> 1) * 8 + lr;
    int bCol = (grp & 1) * 8;

    for (int kc = 0; kc < 4; kc++) {
        if (kc) __syncthreads();
        const uint4* pa = (const uint4*)(gAh + (size_t)lrow * Fn + kc * KCn);
        const uint4* pb = (const uint4*)(gAl + (size_t)lrow * Fn + kc * KCn);
        const uint4* pc = (const uint4*)(gBh + (size_t)lrow * Fn + kc * KCn);
        const uint4* pd = (const uint4*)(gBl + (size_t)lrow * Fn + kc * KCn);
        uint4* qa = (uint4*)(sAh + lrow * LDT);
        uint4* qb = (uint4*)(sAl + lrow * LDT);
        uint4* qc = (uint4*)(sBh + lrow * LDT);
        uint4* qd = (uint4*)(sBl + lrow * LDT);
#pragma unroll
        for (int j = 0; j < 4; j++) {
            qa[lq + j] = pa[lq + j];
            qb[lq + j] = pb[lq + j];
            qc[lq + j] = pc[lq + j];
            qd[lq + j] = pd[lq + j];
        }
        __syncthreads();
#pragma unroll
        for (int ks = 0; ks < 4; ks++) {
            int k0 = ks * 16;
            uint32_t ah[4][4], al[4][4], bh[2][4], bl[2][4];
#pragma unroll
            for (int mi = 0; mi < 4; mi++) {
                uint32_t off = ((aRow + mi * 16) * LDT + aCol + k0) * 2;
                ldm_x4(ah[mi][0], ah[mi][1], ah[mi][2], ah[mi][3], sb + off);
                ldm_x4(al[mi][0], al[mi][1], al[mi][2], al[mi][3], sb + TELEM * 2 + off);
            }
#pragma unroll
            for (int nb = 0; nb < 2; nb++) {
                uint32_t off = ((bRow + nb * 16) * LDT + bCol + k0) * 2;
                ldm_x4(bh[nb][0], bh[nb][1], bh[nb][2], bh[nb][3], sb + TELEM * 4 + off);
                ldm_x4(bl[nb][0], bl[nb][1], bl[nb][2], bl[nb][3], sb + TELEM * 6 + off);
            }
#pragma unroll
            for (int mi = 0; mi < 4; mi++) {
#pragma unroll
                for (int nb = 0; nb < 2; nb++) {
                    mma_bf16(acc[mi][2*nb],   ah[mi], &bh[nb][0]);
                    mma_bf16(acc[mi][2*nb+1], ah[mi], &bh[nb][2]);
                    mma_bf16(acc[mi][2*nb],   ah[mi], &bl[nb][0]);
                    mma_bf16(acc[mi][2*nb+1], ah[mi], &bl[nb][2]);
                    mma_bf16(acc[mi][2*nb],   al[mi], &bh[nb][0]);
                    mma_bf16(acc[mi][2*nb+1], al[mi], &bh[nb][2]);
                }
            }
        }
    }

#pragma unroll
    for (int mi = 0; mi < 4; mi++) {
        int row = wm * 64 + mi * 16 + (lane >> 2);
#pragma unroll
        for (int ni = 0; ni < 4; ni++) {
            int col = wn * 32 + ni * 8 + (lane & 3) * 2;
            float* p0 = Yrow + (size_t)row * Wn + col;
            float* p1 = p0 + 8 * Wn;
            float2 v0 = make_float2(acc[mi][ni][0], acc[mi][ni][1]);
            float2 v1 = make_float2(acc[mi][ni][2], acc[mi][ni][3]);
            if (ACC) {
                float2 o0 = *(const float2*)p0, o1 = *(const float2*)p1;
                v0.x += o0.x; v0.y += o0.y; v1.x += o1.x; v1.y += o1.y;
            }
            *(float2*)p0 = v0;
            *(float2*)p1 = v1;
        }
    }
}

// Q/K/V projection GEMM, pair-capable: grid (4, 2, 48*NPAIR); z = pair*48 + which*16 + bc
__global__ void __launch_bounds__(256) gemm_qkv(
        const __nv_bfloat16* __restrict__ WqH_, const __nv_bfloat16* __restrict__ WqL_,
        const __nv_bfloat16* __restrict__ WkH_, const __nv_bfloat16* __restrict__ WkL_,
        const __nv_bfloat16* __restrict__ WvH_, const __nv_bfloat16* __restrict__ WvL_,
        const __nv_bfloat16* __restrict__ th, const __nv_bfloat16* __restrict__ tl,
        const __nv_bfloat16* __restrict__ m0h, const __nv_bfloat16* __restrict__ m0l,
        const __nv_bfloat16* __restrict__ m1h, const __nv_bfloat16* __restrict__ m1l,
        float* __restrict__ dst6) {
    int z = blockIdx.z;
    int pair = z / 48, inner = z % 48;
    int which = inner >> 4, bc = inner & 15, c = bc & (Cn - 1);
    int tileM = blockIdx.y * 128, tileN = blockIdx.x * 128;
    size_t wofs = (size_t)pair * WOFF + ((size_t)c * Fn + tileM) * Fn;
    const __nv_bfloat16* Ah = (which == 0 ? WqH_ : which == 1 ? WkH_ : WvH_) + wofs;
    const __nv_bfloat16* Al = (which == 0 ? WqL_ : which == 1 ? WkL_ : WvL_) + wofs;
    const __nv_bfloat16* Bh = (which == 0 ? th : (pair == 0 ? m0h : m1h)) + ((size_t)bc * Wn + tileN) * Fn;
    const __nv_bfloat16* Bl = (which == 0 ? tl : (pair == 0 ? m0l : m1l)) + ((size_t)bc * Wn + tileN) * Fn;
    float* Y = dst6 + ((size_t)pair * 3 + which) * NB + ((size_t)bc * Fn + tileM) * Wn + tileN;
    gemm_body<false>(Ah, Al, Bh, Bl, Y);
}

// Wo GEMM over NP pairs: Y = Ybase + sum of pair GEMMs (Ybase may differ from Y)
template<int NP>
__global__ void __launch_bounds__(256) gemm_woN(
        const __nv_bfloat16* __restrict__ AhG, const __nv_bfloat16* __restrict__ AlG,
        const __nv_bfloat16* __restrict__ BhG, const __nv_bfloat16* __restrict__ BlG,
        const float* __restrict__ Ybase, float* __restrict__ Y) {
    extern __shared__ __nv_bfloat16 sm[];
    __nv_bfloat16* sAh = sm;
    __nv_bfloat16* sAl = sm + TELEM;
    __nv_bfloat16* sBh = sm + 2 * TELEM;
    __nv_bfloat16* sBl = sm + 3 * TELEM;
    int bc = blockIdx.z, c = bc & (Cn - 1);
    int tileM = blockIdx.y * 128, tileN = blockIdx.x * 128;
    int tid = threadIdx.x, lane = tid & 31, wid = tid >> 5;
    int wm = wid >> 2, wn = wid & 3;
    float acc[4][4][4] = {};
    int lrow = tid >> 1;
    int lq   = (tid & 1) * 4;
    uint32_t sb = smem_u32(sm);
    int grp = lane >> 3, lr = lane & 7;
    int aRow = wm * 64 + (grp & 1) * 8 + lr;
    int aCol = (grp >> 1) * 8;
    int bRow = wn * 32 + (grp >> 1) * 8 + lr;
    int bCol = (grp & 1) * 8;

#pragma unroll
    for (int pp = 0; pp < NP; pp++) {
        const __nv_bfloat16* gAh = AhG + (size_t)pp * WOFF + ((size_t)c * Fn + tileM) * Fn;
        const __nv_bfloat16* gAl = AlG + (size_t)pp * WOFF + ((size_t)c * Fn + tileM) * Fn;
        const __nv_bfloat16* gBh = BhG + (size_t)pp * AS + ((size_t)bc * Wn + tileN) * Fn;
        const __nv_bfloat16* gBl = BlG + (size_t)pp * AS + ((size_t)bc * Wn + tileN) * Fn;
        for (int kc = 0; kc < 4; kc++) {
            if (pp || kc) __syncthreads();
            const uint4* pa = (const uint4*)(gAh + (size_t)lrow * Fn + kc * KCn);
            const uint4* pb = (const uint4*)(gAl + (size_t)lrow * Fn + kc * KCn);
            const uint4* pc = (const uint4*)(gBh + (size_t)lrow * Fn + kc * KCn);
            const uint4* pd = (const uint4*)(gBl + (size_t)lrow * Fn + kc * KCn);
            uint4* qa = (uint4*)(sAh + lrow * LDT);
            uint4* qb = (uint4*)(sAl + lrow * LDT);
            uint4* qc = (uint4*)(sBh + lrow * LDT);
            uint4* qd = (uint4*)(sBl + lrow * LDT);
#pragma unroll
            for (int j = 0; j < 4; j++) {
                qa[lq + j] = pa[lq + j];
                qb[lq + j] = pb[lq + j];
                qc[lq + j] = pc[lq + j];
                qd[lq + j] = pd[lq + j];
            }
            __syncthreads();
#pragma unroll
            for (int ks = 0; ks < 4; ks++) {
                int k0 = ks * 16;
                uint32_t ah[4][4], al[4][4], bh[2][4], bl[2][4];
#pragma unroll
                for (int mi = 0; mi < 4; mi++) {
                    uint32_t off = ((aRow + mi * 16) * LDT + aCol + k0) * 2;
                    ldm_x4(ah[mi][0], ah[mi][1], ah[mi][2], ah[mi][3], sb + off);
                    ldm_x4(al[mi][0], al[mi][1], al[mi][2], al[mi][3], sb + TELEM * 2 + off);
                }
#pragma unroll
                for (int nb = 0; nb < 2; nb++) {
                    uint32_t off = ((bRow + nb * 16) * LDT + bCol + k0) * 2;
                    ldm_x4(bh[nb][0], bh[nb][1], bh[nb][2], bh[nb][3], sb + TELEM * 4 + off);
                    ldm_x4(bl[nb][0], bl[nb][1], bl[nb][2], bl[nb][3], sb + TELEM * 6 + off);
                }
#pragma unroll
                for (int mi = 0; mi < 4; mi++) {
#pragma unroll
                    for (int nb = 0; nb < 2; nb++) {
                        mma_bf16(acc[mi][2*nb],   ah[mi], &bh[nb][0]);
                        mma_bf16(acc[mi][2*nb+1], ah[mi], &bh[nb][2]);
                        mma_bf16(acc[mi][2*nb],   ah[mi], &bl[nb][0]);
                        mma_bf16(acc[mi][2*nb+1], ah[mi], &bl[nb][2]);
                        mma_bf16(acc[mi][2*nb],   al[mi], &bh[nb][0]);
                        mma_bf16(acc[mi][2*nb+1], al[mi], &bh[nb][2]);
                    }
                }
            }
        }
    }

    size_t base = ((size_t)bc * Fn + tileM) * Wn + tileN;
    const float* Brow = Ybase + base;
    float* Yrow = Y + base;
#pragma unroll
    for (int mi = 0; mi < 4; mi++) {
        int row = wm * 64 + mi * 16 + (lane >> 2);
#pragma unroll
        for (int ni = 0; ni < 4; ni++) {
            int col = wn * 32 + ni * 8 + (lane & 3) * 2;
            const float* b0 = Brow + (size_t)row * Wn + col;
            const float* b1 = b0 + 8 * Wn;
            float* p0 = Yrow + (size_t)row * Wn + col;
            float* p1 = p0 + 8 * Wn;
            float2 o0 = *(const float2*)b0, o1 = *(const float2*)b1;
            o0.x += acc[mi][ni][0]; o0.y += acc[mi][ni][1];
            o1.x += acc[mi][ni][2]; o1.y += acc[mi][ni][3];
            *(float2*)p0 = o0;
            *(float2*)p1 = o1;
        }
    }
}

// ======= conv3+bias (+RoPE) for Q/K/V, pair-capable: grid (4, 128, 6*NPAIR) =======
__global__ void __launch_bounds__(128) conv_qkv(const float* __restrict__ lin6,
                                                const float* __restrict__ KqG, const float* __restrict__ bqG,
                                                const float* __restrict__ KkG, const float* __restrict__ bkG,
                                                const float* __restrict__ KvG, const float* __restrict__ bvG,
                                                int i0,
                                                uint2* __restrict__ qI, uint2* __restrict__ kI,
                                                __nv_bfloat16* __restrict__ vbf) {
    __shared__ float sIn[Cn][2][132];
    __shared__ float ks[Cn * Cn * 3];
    int tid = threadIdx.x;
    int zz = blockIdx.z;
    int pair = zz / 6, r = zz % 6;
    int which = r >> 1, b = r & 1;
    int i = i0 + pair;
    const float* Lin = lin6 + ((size_t)pair * 3 + which) * NB;
    const float* Kc  = (which == 0 ? KqG : which == 1 ? KkG : KvG) + (size_t)i * Cn * Cn * 3;
    const float* bias = (which == 0 ? bqG : which == 1 ? bkG : bvG) + i * Cn;
    int w0 = blockIdx.x * 128;
    int p  = blockIdx.y;
    int f0 = 2 * p;
    for (int t = tid; t < Cn * 2 * 130; t += 128) {
        int ci = t / 260, rr = t % 260;
        int fi = rr / 130, wo = rr % 130;
        int gw = w0 + wo - 1;
        float v = (gw >= 0 && gw < Wn) ? Lin[((size_t)(b*Cn + ci) * Fn + f0 + fi) * Wn + gw] : 0.f;
        sIn[ci][fi][wo] = v;
    }
    for (int t = tid; t < Cn * Cn * 3; t += 128) ks[t] = Kc[t];
    __syncthreads();

    int w = w0 + tid;
    float cs = 1.f, sn = 0.f;
    if (which < 2) {
        int j = p & 15;
        float invf = exp10f(-0.25f * (float)j);
        sincosf((float)w * invf, &sn, &cs);
    }
    int h  = p >> 4;
    int jj = p & 15;
#pragma unroll
    for (int co = 0; co < Cn; co++) {
        float acc0 = bias[co], acc1 = acc0;
#pragma unroll
        for (int ci = 0; ci < Cn; ci++) {
            float k0 = ks[co*24 + ci*3], k1 = ks[co*24 + ci*3 + 1], k2 = ks[co*24 + ci*3 + 2];
            acc0 += k0 * sIn[ci][0][tid] + k1 * sIn[ci][0][tid+1] + k2 * sIn[ci][0][tid+2];
            acc1 += k0 * sIn[ci][1][tid] + k1 * sIn[ci][1][tid+1] + k2 * sIn[ci][1][tid+2];
        }
        size_t head = (size_t)(b*Cn + co) * Hn + h;
        size_t idx = (head * Wn + w) * 16 + jj;
        if (which < 2) {
            float o0 = acc0 * cs - acc1 * sn;
            float o1 = acc1 * cs + acc0 * sn;
            uint32_t lo, hi = pack_split(o0, o1, lo);
            (which == 0 ? qI : kI)[pair * QS + idx] = make_uint2(hi, lo);
        } else {
            ((__nv_bfloat162*)vbf)[pair * (VS/2) + idx] = __floats2bfloat162_rn(acc0, acc1);
        }
    }
}

// ========== tensor-core flash attention (2-term QK), register-prefetched staging ==========
__global__ void __launch_bounds__(256, 1) attn_mma(const uint2* __restrict__ Qi,
                                                   const uint2* __restrict__ Ki,
                                                   const __nv_bfloat16* __restrict__ Vg,
                                                   __nv_bfloat16* __restrict__ AttH,
                                                   __nv_bfloat16* __restrict__ AttL) {
    __shared__ __nv_bfloat16 Kh[64][40];
    __shared__ __nv_bfloat16 Kl[64][40];
    __shared__ __nv_bfloat16 Vs[64][40];
    int pair = blockIdx.x >> 8, rest = blockIdx.x & 255;
    int head = rest >> 1, half = rest & 1;
    int tid = threadIdx.x, lane = tid & 31, wid = tid >> 5;
    int qb = half * 256 + wid * 32;
    size_t hbase = (size_t)head * Wn;
    Qi += pair * QS; Ki += pair * QS; Vg += pair * VS;
    AttH += pair * AS; AttL += pair * AS;

    uint32_t qh[2][2][4];
#pragma unroll
    for (int mi = 0; mi < 2; mi++) {
        int r0 = qb + mi * 16 + (lane >> 2);
#pragma unroll
        for (int kk = 0; kk < 2; kk++) {
            int jp = kk * 8 + (lane & 3);
            qh[mi][kk][0] = Qi[(hbase + r0) * 16 + jp].x;
            qh[mi][kk][1] = Qi[(hbase + r0 + 8) * 16 + jp].x;
            qh[mi][kk][2] = Qi[(hbase + r0) * 16 + jp + 4].x;
            qh[mi][kk][3] = Qi[(hbase + r0 + 8) * 16 + jp + 4].x;
        }
    }
    float m_[4] = {-1e30f, -1e30f, -1e30f, -1e30f};
    float l_[4] = {0.f, 0.f, 0.f, 0.f};
    float o[2][4][4] = {};
    uint32_t sbK = smem_u32(Kh), sbKl = smem_u32(Kl), sbV = smem_u32(Vs);
    int grp = lane >> 3, lr = lane & 7;
    int rowV = tid >> 2, qV = tid & 3;

    uint2 kreg[4];
    uint4 vreg;
#pragma unroll
    for (int it = 0; it < 4; it++) {
        int idx = tid + it * 256;
        kreg[it] = Ki[(hbase + (idx >> 4)) * 16 + (idx & 15)];
    }
    vreg = ((const uint4*)(Vg + (hbase + rowV) * HDn))[qV];

    for (int kt = 0; kt < 8; kt++) {
#pragma unroll
        for (int it = 0; it < 4; it++) {
            int idx = tid + it * 256;
            int row = idx >> 4, j = idx & 15;
            ((uint32_t*)&Kh[row][0])[j] = kreg[it].x;
            ((uint32_t*)&Kl[row][0])[j] = kreg[it].y;
        }
        *((uint4*)&Vs[rowV][qV * 8]) = vreg;
        __syncthreads();
        if (kt < 7) {
            int kb = (kt + 1) * 64;
#pragma unroll
            for (int it = 0; it < 4; it++) {
                int idx = tid + it * 256;
                kreg[it] = Ki[(hbase + kb + (idx >> 4)) * 16 + (idx & 15)];
            }
            vreg = ((const uint4*)(Vg + (hbase + kb + rowV) * HDn))[qV];
        }

        float s[2][8][4] = {};
#pragma unroll
        for (int kk = 0; kk < 2; kk++) {
#pragma unroll
            for (int nb = 0; nb < 4; nb++) {
                uint32_t kh4[4], kl4[4];
                uint32_t off = ((nb * 16 + (grp >> 1) * 8 + lr) * 40 + (grp & 1) * 8 + kk * 16) * 2;
                ldm_x4(kh4[0], kh4[1], kh4[2], kh4[3], sbK + off);
                ldm_x4(kl4[0], kl4[1], kl4[2], kl4[3], sbKl + off);
#pragma unroll
                for (int mi = 0; mi < 2; mi++) {
                    mma_bf16(s[mi][2*nb],   qh[mi][kk], &kh4[0]);
                    mma_bf16(s[mi][2*nb+1], qh[mi][kk], &kh4[2]);
                    mma_bf16(s[mi][2*nb],   qh[mi][kk], &kl4[0]);
                    mma_bf16(s[mi][2*nb+1], qh[mi][kk], &kl4[2]);
                }
            }
        }

        uint32_t pa[2][4][4];
#pragma unroll
        for (int mi = 0; mi < 2; mi++) {
            float mx0 = -1e30f, mx1 = -1e30f;
#pragma unroll
            for (int n = 0; n < 8; n++) {
#pragma unroll
                for (int q = 0; q < 4; q++) s[mi][n][q] *= 0.0625f;
                mx0 = fmaxf(mx0, fmaxf(s[mi][n][0], s[mi][n][1]));
                mx1 = fmaxf(mx1, fmaxf(s[mi][n][2], s[mi][n][3]));
            }
            mx0 = fmaxf(mx0, __shfl_xor_sync(0xffffffffu, mx0, 1));
            mx0 = fmaxf(mx0, __shfl_xor_sync(0xffffffffu, mx0, 2));
            mx1 = fmaxf(mx1, __shfl_xor_sync(0xffffffffu, mx1, 1));
            mx1 = fmaxf(mx1, __shfl_xor_sync(0xffffffffu, mx1, 2));
            int si = mi * 2;
            float mn0 = fmaxf(m_[si], mx0), mn1 = fmaxf(m_[si+1], mx1);
            float c0 = __expf(m_[si] - mn0), c1 = __expf(m_[si+1] - mn1);
            m_[si] = mn0; m_[si+1] = mn1;
            float ls0 = 0.f, ls1 = 0.f;
#pragma unroll
            for (int n = 0; n < 8; n++) {
                float p0 = __expf(s[mi][n][0] - mn0);
                float p1 = __expf(s[mi][n][1] - mn0);
                float p2 = __expf(s[mi][n][2] - mn1);
                float p3 = __expf(s[mi][n][3] - mn1);
                ls0 += p0 + p1; ls1 += p2 + p3;
                s[mi][n][0] = p0; s[mi][n][1] = p1; s[mi][n][2] = p2; s[mi][n][3] = p3;
            }
            ls0 += __shfl_xor_sync(0xffffffffu, ls0, 1);
            ls0 += __shfl_xor_sync(0xffffffffu, ls0, 2);
            ls1 += __shfl_xor_sync(0xffffffffu, ls1, 1);
            ls1 += __shfl_xor_sync(0xffffffffu, ls1, 2);
            l_[si]   = l_[si]   * c0 + ls0;
            l_[si+1] = l_[si+1] * c1 + ls1;
#pragma unroll
            for (int dn = 0; dn < 4; dn++) {
                o[mi][dn][0] *= c0; o[mi][dn][1] *= c0;
                o[mi][dn][2] *= c1; o[mi][dn][3] *= c1;
            }
#pragma unroll
            for (int t = 0; t < 4; t++) {
                pa[mi][t][0] = packbf(s[mi][2*t][0],   s[mi][2*t][1]);
                pa[mi][t][1] = packbf(s[mi][2*t][2],   s[mi][2*t][3]);
                pa[mi][t][2] = packbf(s[mi][2*t+1][0], s[mi][2*t+1][1]);
                pa[mi][t][3] = packbf(s[mi][2*t+1][2], s[mi][2*t+1][3]);
            }
        }

#pragma unroll
        for (int dn = 0; dn < 4; dn++) {
            uint32_t vb[4][2];
#pragma unroll
            for (int t = 0; t < 4; t++) {
                uint32_t off = ((t * 16 + (lane & 15)) * 40 + dn * 8) * 2;
                ldm_x2_trans(vb[t][0], vb[t][1], sbV + off);
            }
#pragma unroll
            for (int mi = 0; mi < 2; mi++)
#pragma unroll
                for (int t = 0; t < 4; t++)
                    mma_bf16(o[mi][dn], pa[mi][t], vb[t]);
        }
        __syncthreads();
    }

    int bc = head >> 3, hh = head & 7;
#pragma unroll
    for (int mi = 0; mi < 2; mi++) {
        int r0 = qb + mi * 16 + (lane >> 2);
        float i0 = 1.0f / l_[mi*2], i1 = 1.0f / l_[mi*2 + 1];
#pragma unroll
        for (int dn = 0; dn < 4; dn++) {
            int d0 = dn * 8 + (lane & 3) * 2;
            size_t a0 = ((size_t)bc * Wn + r0) * Fn + hh * HDn + d0;
            size_t a1 = ((size_t)bc * Wn + r0 + 8) * Fn + hh * HDn + d0;
            uint32_t lo0, hi0 = pack_split(o[mi][dn][0] * i0, o[mi][dn][1] * i0, lo0);
            uint32_t lo1, hi1 = pack_split(o[mi][dn][2] * i1, o[mi][dn][3] * i1, lo1);
            *(uint32_t*)(AttH + a0) = hi0;
            *(uint32_t*)(AttL + a0) = lo0;
            *(uint32_t*)(AttH + a1) = hi1;
            *(uint32_t*)(AttL + a1) = lo1;
        }
    }
}

// ============ fused LN + depthwise convs (k11 sq_relu + k7) — proven r10/r11 ============
__global__ void __launch_bounds__(256) lnconv_ab(const float* __restrict__ X,
                                                 const float* __restrict__ gam,
                                                 const float* __restrict__ bet,
                                                 const float* __restrict__ k11, const float* __restrict__ b11,
                                                 const float* __restrict__ k7,  const float* __restrict__ b7,
                                                 float* __restrict__ Yo) {
    extern __shared__ float sZ[];
    __shared__ float gs[Fn], bs[Fn], ps[4][64], ps2[4][64], mb[64], ib[64];
    int tid = threadIdx.x, w = tid & 63, fg = tid >> 6;
    int bc = blockIdx.y, c = bc & (Cn - 1);
    int w0 = blockIdx.x * 64;
    const float* xp = X + (size_t)bc * Fn * Wn + w0;
    for (int i = tid; i < Fn * 64; i += 256)
        sZ[i] = xp[(size_t)(i >> 6) * Wn + (i & 63)];
    for (int i = tid; i < Fn; i += 256) { gs[i] = gam[c * Fn + i]; bs[i] = bet[c * Fn + i]; }
    __syncthreads();
    float s = 0.f, s2 = 0.f;
#pragma unroll 4
    for (int f = fg * 64; f < fg * 64 + 64; f++) {
        float v = sZ[f * 64 + w];
        s += v; s2 += v * v;
    }
    ps[fg][w] = s; ps2[fg][w] = s2;
    __syncthreads();
    if (fg == 0) {
        float S  = ps[0][w]  + ps[1][w]  + ps[2][w]  + ps[3][w];
        float S2 = ps2[0][w] + ps2[1][w] + ps2[2][w] + ps2[3][w];
        float m = S * (1.0f / Fn);
        mb[w] = m;
        ib[w] = rsqrtf(S2 * (1.0f / Fn) - m * m + 1e-5f);
    }
    __syncthreads();
    float m = mb[w], inv = ib[w];
#pragma unroll 4
    for (int f = fg * 64; f < fg * 64 + 64; f++)
        sZ[f * 64 + w] = (sZ[f * 64 + w] - m) * inv * gs[f] + bs[f];
    __syncthreads();
    float wk11[11], wk7[7];
#pragma unroll
    for (int t = 0; t < 11; t++) wk11[t] = k11[c * 11 + t];
#pragma unroll
    for (int t = 0; t < 7; t++)  wk7[t]  = k7[c * 7 + t];
    float bb11 = b11[c], bb7 = b7[c];
    float* yo = Yo + (size_t)bc * Fn * Wn + w0 + w;
    for (int f = fg * 64; f < fg * 64 + 64; f++) {
        float a = bb11;
#pragma unroll
        for (int t = 0; t < 11; t++) {
            int ff = f - 5 + t;
            if (ff >= 0 && ff < Fn) a += sZ[ff * 64 + w] * wk11[t];
        }
        a = fmaxf(a, 0.f); a = a * a;
        float bo = bb7;
#pragma unroll
        for (int t = 0; t < 7; t++) {
            int ff = f - 3 + t;
            if (ff >= 0 && ff < Fn) bo += sZ[ff * 64 + w] * wk7[t];
        }
        yo[(size_t)f * Wn] = a + bo;
    }
}

// ============ fused LN + k7 conv + residual add into H — proven r10/r11 ============
__global__ void __launch_bounds__(256) lnconv2_add(const float* __restrict__ X,
                                                   const float* __restrict__ gam,
                                                   const float* __restrict__ bet,
                                                   const float* __restrict__ k7, const float* __restrict__ b7,
                                                   float* __restrict__ Hb) {
    extern __shared__ float sZ[];
    __shared__ float gs[Fn], bs[Fn], ps[4][64], ps2[4][64], mb[64], ib[64];
    int tid = threadIdx.x, w = tid & 63, fg = tid >> 6;
    int bc = blockIdx.y, c = bc & (Cn - 1);
    int w0 = blockIdx.x * 64;
    const float* xp = X + (size_t)bc * Fn * Wn + w0;
    for (int i = tid; i < Fn * 64; i += 256)
        sZ[i] = xp[(size_t)(i >> 6) * Wn + (i & 63)];
    for (int i = tid; i < Fn; i += 256) { gs[i] = gam[c * Fn + i]; bs[i] = bet[c * Fn + i]; }
    __syncthreads();
    float s = 0.f, s2 = 0.f;
#pragma unroll 4
    for (int f = fg * 64; f < fg * 64 + 64; f++) {
        float v = sZ[f * 64 + w];
        s += v; s2 += v * v;
    }
    ps[fg][w] = s; ps2[fg][w] = s2;
    __syncthreads();
    if (fg == 0) {
        float S  = ps[0][w]  + ps[1][w]  + ps[2][w]  + ps[3][w];
        float S2 = ps2[0][w] + ps2[1][w] + ps2[2][w] + ps2[3][w];
        float m = S * (1.0f / Fn);
        mb[w] = m;
        ib[w] = rsqrtf(S2 * (1.0f / Fn) - m * m + 1e-5f);
    }
    __syncthreads();
    float m = mb[w], inv = ib[w];
#pragma unroll 4
    for (int f = fg * 64; f < fg * 64 + 64; f++)
        sZ[f * 64 + w] = (sZ[f * 64 + w] - m) * inv * gs[f] + bs[f];
    __syncthreads();
    float wk7[7];
#pragma unroll
    for (int t = 0; t < 7; t++) wk7[t] = k7[c * 7 + t];
    float bb7 = b7[c];
    float* hb = Hb + (size_t)bc * Fn * Wn + w0 + w;
    for (int f = fg * 64; f < fg * 64 + 64; f++) {
        float v = bb7;
#pragma unroll
        for (int t = 0; t < 7; t++) {
            int ff = f - 3 + t;
            if (ff >= 0 && ff < Fn) v += sZ[ff * 64 + w] * wk7[t];
        }
        hb[(size_t)f * Wn] += v;
    }
}

// ============ fused LN + FFN first layer ============
__global__ void __launch_bounds__(256) ln_ffn3(const float* __restrict__ X,
                                               const float* __restrict__ gam,
                                               const float* __restrict__ bet,
                                               const float* __restrict__ w3,
                                               float* __restrict__ T) {
    extern __shared__ float sZ[];
    __shared__ float ws[En * Fn], gs[Fn], bs[Fn];
    __shared__ float ps[4][64], ps2[4][64], mb[64], ib[64];
    __shared__ float pacc[4][En][64];
    int tid = threadIdx.x, w = tid & 63, fg = tid >> 6;
    int bc = blockIdx.y, c = bc & (Cn - 1);
    int w0 = blockIdx.x * 64;
    const float* xp = X + (size_t)bc * Fn * Wn + w0;
    for (int i = tid; i < Fn * 64; i += 256)
        sZ[i] = xp[(size_t)(i >> 6) * Wn + (i & 63)];
    for (int i = tid; i < En * Fn; i += 256) ws[i] = w3[c * En * Fn + i];
    for (int i = tid; i < Fn; i += 256) { gs[i] = gam[c * Fn + i]; bs[i] = bet[c * Fn + i]; }
    __syncthreads();
    float s = 0.f, s2 = 0.f;
#pragma unroll 4
    for (int f = fg * 64; f < fg * 64 + 64; f++) {
        float v = sZ[f * 64 + w];
        s += v; s2 += v * v;
    }
    ps[fg][w] = s; ps2[fg][w] = s2;
    __syncthreads();
    if (fg == 0) {
        float S  = ps[0][w]  + ps[1][w]  + ps[2][w]  + ps[3][w];
        float S2 = ps2[0][w] + ps2[1][w] + ps2[2][w] + ps2[3][w];
        float m = S * (1.0f / Fn);
        mb[w] = m;
        ib[w] = rsqrtf(S2 * (1.0f / Fn) - m * m + 1e-5f);
    }
    __syncthreads();
    float m = mb[w], inv = ib[w];
    float acc[En] = {};
#pragma unroll 4
    for (int f = fg * 64; f < fg * 64 + 64; f++) {
        float zn = (sZ[f * 64 + w] - m) * inv * gs[f] + bs[f];
#pragma unroll
        for (int e = 0; e < En; e++) acc[e] += zn * ws[e * Fn + f];
    }
#pragma unroll
    for (int e = 0; e < En; e++) pacc[fg][e][w] = acc[e];
    __syncthreads();
    if (fg == 0) {
        float* tp = T + (size_t)bc * En * Wn + w0 + w;
#pragma unroll
        for (int e = 0; e < En; e++) {
            float v = pacc[0][e][w] + pacc[1][e][w] + pacc[2][e][w] + pacc[3][e][w];
            v = fmaxf(v, 0.f);
            tp[(size_t)e * Wn] = v * v;
        }
    }
}

// ============ fused FFN second layer + residual + concat output ============
__global__ void ffn4_write(const float* __restrict__ T, const float* __restrict__ w4,
                           const float* __restrict__ Hb, const float* __restrict__ X,
                           float* __restrict__ O) {
    int idx = blockIdx.x * 256 + threadIdx.x;
    int w  = idx & (Wn - 1);
    int f  = (idx >> 9) & (Fn - 1);
    int bc = idx >> 17;
    int c  = bc & (Cn - 1);
    const float* tp = T + (size_t)bc * En * Wn + w;
    const float* wp = w4 + ((size_t)c * Fn + f) * En;
    float v = tp[0] * wp[0] + tp[Wn] * wp[1] + tp[2 * Wn] * wp[2] + tp[3 * Wn] * wp[3];
    float h = Hb[idx] + v;
    int b = idx / (Cn * Fn * Wn);
    int r = idx - b * (Cn * Fn * Wn);
    O[(size_t)b * 2 * Cn * Fn * Wn + r] = X[idx];
    O[(size_t)b * 2 * Cn * Fn * Wn + Cn * Fn * Wn + r] = h;
}

// =====================================================================================

extern "C" void kernel_launch(void* const* d_in, const int* in_sizes, int n_in,
                              void* d_out, int out_size) {
    const float* x     = (const float*)d_in[0];
    const float* skip  = (const float*)d_in[1];
    const float* Wq    = (const float*)d_in[2];
    const float* Kq    = (const float*)d_in[3];
    const float* bq    = (const float*)d_in[4];
    const float* Wk    = (const float*)d_in[5];
    const float* Kk    = (const float*)d_in[6];
    const float* bk    = (const float*)d_in[7];
    const float* Wv    = (const float*)d_in[8];
    const float* Kv    = (const float*)d_in[9];
    const float* bv    = (const float*)d_in[10];
    const float* Wo    = (const float*)d_in[11];
    const float* ng    = (const float*)d_in[12];
    const float* nbet  = (const float*)d_in[13];
    const float* c1a_w = (const float*)d_in[14];
    const float* c1a_b = (const float*)d_in[15];
    const float* c1b_w = (const float*)d_in[16];
    const float* c1b_b = (const float*)d_in[17];
    const float* c2_w  = (const float*)d_in[18];
    const float* c2_b  = (const float*)d_in[19];
    const float* w3    = (const float*)d_in[20];
    const float* w4    = (const float*)d_in[21];
    float* out = (float*)d_out;

    float *hB, *lin6B, *t1B, *ffnB;
    cudaGetSymbolAddress((void**)&hB,    g_h);
    cudaGetSymbolAddress((void**)&lin6B, g_lin6);
    cudaGetSymbolAddress((void**)&t1B,   g_t1);
    cudaGetSymbolAddress((void**)&ffnB,  g_ffn);
    uint2 *qI, *kI;
    __nv_bfloat16 *vBf;
    cudaGetSymbolAddress((void**)&qI,  g_qI);
    cudaGetSymbolAddress((void**)&kI,  g_kI);
    cudaGetSymbolAddress((void**)&vBf, g_vbf);
    __nv_bfloat16 *zTh, *zTl, *skTh, *skTl, *atTh, *atTl;
    __nv_bfloat16 *WqH, *WqL, *WkH, *WkL, *WvH, *WvL, *WoH, *WoL;
    cudaGetSymbolAddress((void**)&zTh,  g_zTh);  cudaGetSymbolAddress((void**)&zTl,  g_zTl);
    cudaGetSymbolAddress((void**)&skTh, g_skTh); cudaGetSymbolAddress((void**)&skTl, g_skTl);
    cudaGetSymbolAddress((void**)&atTh, g_atTh); cudaGetSymbolAddress((void**)&atTl, g_atTl);
    cudaGetSymbolAddress((void**)&WqH, g_WqH); cudaGetSymbolAddress((void**)&WqL, g_WqL);
    cudaGetSymbolAddress((void**)&WkH, g_WkH); cudaGetSymbolAddress((void**)&WkL, g_WkL);
    cudaGetSymbolAddress((void**)&WvH, g_WvH); cudaGetSymbolAddress((void**)&WvL, g_WvL);
    cudaGetSymbolAddress((void**)&WoH, g_WoH); cudaGetSymbolAddress((void**)&WoL, g_WoL);

    const int TSM = Fn * 64 * 4;
    cudaFuncSetAttribute(gemm_qkv,    cudaFuncAttributeMaxDynamicSharedMemorySize, GSM);
    cudaFuncSetAttribute(gemm_woN<1>, cudaFuncAttributeMaxDynamicSharedMemorySize, GSM);
    cudaFuncSetAttribute(gemm_woN<2>, cudaFuncAttributeMaxDynamicSharedMemorySize, GSM);
    cudaFuncSetAttribute(lnconv_ab,   cudaFuncAttributeMaxDynamicSharedMemorySize, TSM);
    cudaFuncSetAttribute(lnconv2_add, cudaFuncAttributeMaxDynamicSharedMemorySize, TSM);
    cudaFuncSetAttribute(ln_ffn3,     cudaFuncAttributeMaxDynamicSharedMemorySize, TSM);

    const int nElemBlocks = NB / 256;
    const int wBlocks = (4 * WOFF) / 1024;
    const dim3 gLN(Wn / 16, Bn * Cn);
    const dim3 gT64(Wn / 64, Bn * Cn);

    wsplit_all<<<dim3(wBlocks, 4), 256>>>(Wq, Wk, Wv, Wo,
                                          WqH, WqL, WkH, WkL, WvH, WvL, WoH, WoL);
    tsplit_kernel<<<dim3(Wn/32, Fn/32, Bn*Cn), dim3(32, 8)>>>(skip, skTh, skTl);

    auto run_ln_t = [&](const float* X, int gi) {
        ln_t_v4<<<gLN, 256>>>(X, ng + gi * Cn * Fn, nbet + gi * Cn * Fn, zTh, zTl);
    };

    // --- att0 + att1 as one batched pair; h = x + both (seeded inside Wo GEMM) ---
    run_ln_t(x, 0);
    gemm_qkv<<<dim3(4, 2, 96), 256, GSM>>>(WqH, WqL, WkH, WkL, WvH, WvL,
                                           zTh, zTl, zTh, zTl, skTh, skTl, lin6B);
    conv_qkv<<<dim3(4, 128, 12), 128>>>(lin6B, Kq, bq, Kk, bk, Kv, bv, 0, qI, kI, vBf);
    attn_mma<<<512, 256>>>(qI, kI, vBf, atTh, atTl);
    gemm_woN<2><<<dim3(4, 2, 16), 256, GSM>>>(WoH, WoL, atTh, atTl, x, hB);

    // conv block (proven two-kernel form)
    lnconv_ab<<<gT64, 256, TSM>>>(hB, ng + 1 * Cn * Fn, nbet + 1 * Cn * Fn,
                                  c1a_w, c1a_b, c1b_w, c1b_b, t1B);
    lnconv2_add<<<gT64, 256, TSM>>>(t1B, ng + 2 * Cn * Fn, nbet + 2 * Cn * Fn,
                                    c2_w, c2_b, hB);

    // h += att2(LN3(h), same)
    run_ln_t(hB, 3);
    gemm_qkv<<<dim3(4, 2, 48), 256, GSM>>>(WqH + 2*(size_t)WOFF, WqL + 2*(size_t)WOFF,
                                           WkH + 2*(size_t)WOFF, WkL + 2*(size_t)WOFF,
                                           WvH + 2*(size_t)WOFF, WvL + 2*(size_t)WOFF,
                                           zTh, zTl, zTh, zTl, zTh, zTl, lin6B);
    conv_qkv<<<dim3(4, 128, 6), 128>>>(lin6B, Kq, bq, Kk, bk, Kv, bv, 2, qI, kI, vBf);
    attn_mma<<<256, 256>>>(qI, kI, vBf, atTh, atTl);
    gemm_woN<1><<<dim3(4, 2, 16), 256, GSM>>>(WoH + 2*(size_t)WOFF, WoL + 2*(size_t)WOFF,
                                              atTh, atTl, hB, hB);

    // h += att3(LN4(h), skip)
    run_ln_t(hB, 4);
    gemm_qkv<<<dim3(4, 2, 48), 256, GSM>>>(WqH + 3*(size_t)WOFF, WqL + 3*(size_t)WOFF,
                                           WkH + 3*(size_t)WOFF, WkL + 3*(size_t)WOFF,
                                           WvH + 3*(size_t)WOFF, WvL + 3*(size_t)WOFF,
                                           zTh, zTl, skTh, skTl, skTh, skTl, lin6B);
    conv_qkv<<<dim3(4, 128, 6), 128>>>(lin6B, Kq, bq, Kk, bk, Kv, bv, 3, qI, kI, vBf);
    attn_mma<<<256, 256>>>(qI, kI, vBf, atTh, atTl);
    gemm_woN<1><<<dim3(4, 2, 16), 256, GSM>>>(WoH + 3*(size_t)WOFF, WoL + 3*(size_t)WOFF,
                                              atTh, atTl, hB, hB);

    // FFN (LN5 fused into ffn3; ffn4 fused with concat output)
    ln_ffn3<<<gT64, 256, TSM>>>(hB, ng + 5 * Cn * Fn, nbet + 5 * Cn * Fn, w3, ffnB);
    ffn4_write<<<nElemBlocks, 256>>>(ffnB, w4, hB, x, out);
}

// round 15
// speedup vs baseline: 3.3428x; 1.1034x over previous
#include <cuda_runtime.h>
#include <cuda_bf16.h>
#include <math.h>
#include <stdint.h>

#define Bn 2
#define Cn 8
#define Fn 256
#define Wn 512
#define Hn 8
#define HDn 32
#define En 4
#define NB (Bn*Cn*Fn*Wn)
#define WOFF (Cn*Fn*Fn)
#define NHEAD (Bn*Cn*Hn)
#define QS ((size_t)NHEAD*Wn*16)
#define VS ((size_t)NHEAD*Wn*HDn)
#define AS ((size_t)Bn*Cn*Wn*Fn)

// ======================= warp-MMA helpers (baseline PTX, sm_80+) =======================
__device__ __forceinline__ uint32_t smem_u32(const void* p) {
    uint32_t a;
    asm("{ .reg .u64 t; cvta.to.shared.u64 t, %1; cvt.u32.u64 %0, t; }" : "=r"(a) : "l"(p));
    return a;
}
__device__ __forceinline__ void ldm_x4(uint32_t& r0, uint32_t& r1, uint32_t& r2, uint32_t& r3,
                                       uint32_t addr) {
    asm volatile("ldmatrix.sync.aligned.m8n8.x4.shared.b16 {%0,%1,%2,%3}, [%4];"
                 : "=r"(r0), "=r"(r1), "=r"(r2), "=r"(r3) : "r"(addr));
}
__device__ __forceinline__ void ldm_x2_trans(uint32_t& r0, uint32_t& r1, uint32_t addr) {
    asm volatile("ldmatrix.sync.aligned.m8n8.x2.trans.shared.b16 {%0,%1}, [%2];"
                 : "=r"(r0), "=r"(r1) : "r"(addr));
}
__device__ __forceinline__ void mma_bf16(float* d, const uint32_t* a, const uint32_t* b) {
    asm volatile("mma.sync.aligned.m16n8k16.row.col.f32.bf16.bf16.f32 "
                 "{%0,%1,%2,%3}, {%4,%5,%6,%7}, {%8,%9}, {%0,%1,%2,%3};"
                 : "+f"(d[0]), "+f"(d[1]), "+f"(d[2]), "+f"(d[3])
                 : "r"(a[0]), "r"(a[1]), "r"(a[2]), "r"(a[3]), "r"(b[0]), "r"(b[1]));
}
__device__ __forceinline__ uint32_t pack_split(float a, float b, uint32_t& lo) {
    __nv_bfloat16 ha = __float2bfloat16(a), hb = __float2bfloat16(b);
    __nv_bfloat16 la = __float2bfloat16(a - __bfloat162float(ha));
    __nv_bfloat16 lb = __float2bfloat16(b - __bfloat162float(hb));
    lo = (uint32_t)__bfloat16_as_ushort(la) | ((uint32_t)__bfloat16_as_ushort(lb) << 16);
    return (uint32_t)__bfloat16_as_ushort(ha) | ((uint32_t)__bfloat16_as_ushort(hb) << 16);
}
__device__ __forceinline__ uint32_t packbf(float a, float b) {
    __nv_bfloat162 v = __floats2bfloat162_rn(a, b);
    return *(uint32_t*)&v;
}

// ======================= scratch (device globals) =======================
__device__ float g_h[NB];
__device__ float g_lin6[6*NB];
__device__ float g_t1[NB];
__device__ float g_ffn[Bn*Cn*En*Wn];
__device__ uint2 g_qI[2*NHEAD*Wn*16];
__device__ uint2 g_kI[2*NHEAD*Wn*16];
__device__ __nv_bfloat16 g_vbf[2*NHEAD*Wn*HDn];
__device__ __nv_bfloat16 g_zTh[Bn*Cn*Wn*Fn];
__device__ __nv_bfloat16 g_zTl[Bn*Cn*Wn*Fn];
__device__ __nv_bfloat16 g_skTh[Bn*Cn*Wn*Fn];
__device__ __nv_bfloat16 g_skTl[Bn*Cn*Wn*Fn];
__device__ __nv_bfloat16 g_atTh[2*Bn*Cn*Wn*Fn];
__device__ __nv_bfloat16 g_atTl[2*Bn*Cn*Wn*Fn];
__device__ __nv_bfloat16 g_WqH[4*WOFF];
__device__ __nv_bfloat16 g_WkH[4*WOFF];
__device__ __nv_bfloat16 g_WvH[4*WOFF];
__device__ __nv_bfloat16 g_WoH[4*WOFF];

// ============ LayerNorm -> transposed bf16 hi/lo; grid (32, 16), blk 256 = 16w x 16fg ============
__global__ void __launch_bounds__(256) ln_t_v4(const float* __restrict__ X,
                                               const float* __restrict__ gam,
                                               const float* __restrict__ bet,
                                               __nv_bfloat16* __restrict__ Zh,
                                               __nv_bfloat16* __restrict__ Zl) {
    __shared__ float ps[16][17], ps2[16][17], mb[16], ib[16];
    int tid = threadIdx.x, w = tid & 15, fg = tid >> 4;
    int bc = blockIdx.y, c = bc & (Cn - 1);
    int w0 = blockIdx.x * 16;
    const float* xp = X + (size_t)bc * Fn * Wn + w0 + w;
    float s = 0.f, s2 = 0.f;
#pragma unroll 4
    for (int f = fg * 16; f < fg * 16 + 16; f++) {
        float v = xp[(size_t)f * Wn];
        s += v; s2 += v * v;
    }
    ps[fg][w] = s; ps2[fg][w] = s2;
    __syncthreads();
    if (tid < 16) {
        float S = 0.f, S2 = 0.f;
#pragma unroll
        for (int g = 0; g < 16; g++) { S += ps[g][tid]; S2 += ps2[g][tid]; }
        float m = S * (1.0f / Fn);
        mb[tid] = m;
        ib[tid] = rsqrtf(S2 * (1.0f / Fn) - m * m + 1e-5f);
    }
    __syncthreads();
    float m = mb[w], inv = ib[w];
    const float* gp = gam + c * Fn;
    const float* bp = bet + c * Fn;
    __nv_bfloat16* th = Zh + ((size_t)bc * Wn + w0 + w) * Fn;
    __nv_bfloat16* tl = Zl + ((size_t)bc * Wn + w0 + w) * Fn;
    for (int f0 = fg * 16; f0 < fg * 16 + 16; f0 += 8) {
        uint32_t ph[4], pl[4];
#pragma unroll
        for (int j = 0; j < 4; j++) {
            int f = f0 + 2 * j;
            float v0 = (xp[(size_t)f * Wn]     - m) * inv * gp[f]   + bp[f];
            float v1 = (xp[(size_t)(f+1) * Wn] - m) * inv * gp[f+1] + bp[f+1];
            ph[j] = pack_split(v0, v1, pl[j]);
        }
        *(uint4*)(th + f0) = make_uint4(ph[0], ph[1], ph[2], ph[3]);
        *(uint4*)(tl + f0) = make_uint4(pl[0], pl[1], pl[2], pl[3]);
    }
}

// ============ transpose + split: (b,c,f,w) fp32 -> [bc][w][f] bf16 hi/lo ============
__global__ void tsplit_kernel(const float* __restrict__ X,
                              __nv_bfloat16* __restrict__ Th, __nv_bfloat16* __restrict__ Tl) {
    __shared__ float t[32][33];
    int bc = blockIdx.z;
    int w0 = blockIdx.x * 32, f0 = blockIdx.y * 32;
    const float* xp = X + ((size_t)bc * Fn + f0) * Wn + w0;
#pragma unroll
    for (int i = 0; i < 4; i++) {
        int fr = threadIdx.y + i * 8;
        t[fr][threadIdx.x] = xp[(size_t)fr * Wn + threadIdx.x];
    }
    __syncthreads();
#pragma unroll
    for (int i = 0; i < 4; i++) {
        int wr = threadIdx.y + i * 8;
        float v = t[threadIdx.x][wr];
        __nv_bfloat16 h = __float2bfloat16(v);
        __nv_bfloat16 l = __float2bfloat16(v - __bfloat162float(h));
        size_t idx = ((size_t)bc * Wn + w0 + wr) * Fn + f0 + threadIdx.x;
        Th[idx] = h; Tl[idx] = l;
    }
}

// ============ weight split: bf16-hi only (2-term GEMM needs no weight-lo) ============
__global__ void wsplit_all(const float* __restrict__ S0, const float* __restrict__ S1,
                           const float* __restrict__ S2, const float* __restrict__ S3,
                           __nv_bfloat16* H0, __nv_bfloat16* H1,
                           __nv_bfloat16* H2, __nv_bfloat16* H3) {
    int which = blockIdx.y;
    const float* X = which == 0 ? S0 : which == 1 ? S1 : which == 2 ? S2 : S3;
    __nv_bfloat16* H = which == 0 ? H0 : which == 1 ? H1 : which == 2 ? H2 : H3;
    int i = (blockIdx.x * 256 + threadIdx.x) * 4;
    float4 v = *(const float4*)(X + i);
    uint32_t h0 = packbf(v.x, v.y);
    uint32_t h1 = packbf(v.z, v.w);
    *(uint2*)((unsigned short*)H + i) = make_uint2(h0, h1);
}

// ======================= 2-term bf16 GEMM body: A_hi x (B_hi + B_lo) =======================
#define KCn 64
#define LDT 72
#define TELEM (128 * LDT)
#define GSM (3 * TELEM * 2)          // 55296 bytes (3 tiles: Ah, Bh, Bl)

template<bool ACC>
__device__ __forceinline__ void gemm_body(const __nv_bfloat16* __restrict__ gAh,
                                          const __nv_bfloat16* __restrict__ gBh,
                                          const __nv_bfloat16* __restrict__ gBl,
                                          float* __restrict__ Yrow) {
    extern __shared__ __nv_bfloat16 sm[];
    __nv_bfloat16* sAh = sm;
    __nv_bfloat16* sBh = sm + TELEM;
    __nv_bfloat16* sBl = sm + 2 * TELEM;
    int tid = threadIdx.x, lane = tid & 31, wid = tid >> 5;
    int wm = wid >> 2, wn = wid & 3;

    float acc[4][4][4] = {};
    int lrow = tid >> 1;
    int lq   = (tid & 1) * 4;

    uint32_t sb = smem_u32(sm);
    int grp = lane >> 3, lr = lane & 7;
    int aRow = wm * 64 + (grp & 1) * 8 + lr;
    int aCol = (grp >> 1) * 8;
    int bRow = wn * 32 + (grp >> 1) * 8 + lr;
    int bCol = (grp & 1) * 8;

    for (int kc = 0; kc < 4; kc++) {
        if (kc) __syncthreads();
        const uint4* pa = (const uint4*)(gAh + (size_t)lrow * Fn + kc * KCn);
        const uint4* pc = (const uint4*)(gBh + (size_t)lrow * Fn + kc * KCn);
        const uint4* pd = (const uint4*)(gBl + (size_t)lrow * Fn + kc * KCn);
        uint4* qa = (uint4*)(sAh + lrow * LDT);
        uint4* qc = (uint4*)(sBh + lrow * LDT);
        uint4* qd = (uint4*)(sBl + lrow * LDT);
#pragma unroll
        for (int j = 0; j < 4; j++) {
            qa[lq + j] = pa[lq + j];
            qc[lq + j] = pc[lq + j];
            qd[lq + j] = pd[lq + j];
        }
        __syncthreads();
#pragma unroll
        for (int ks = 0; ks < 4; ks++) {
            int k0 = ks * 16;
            uint32_t ah[4][4], bh[2][4], bl[2][4];
#pragma unroll
            for (int mi = 0; mi < 4; mi++) {
                uint32_t off = ((aRow + mi * 16) * LDT + aCol + k0) * 2;
                ldm_x4(ah[mi][0], ah[mi][1], ah[mi][2], ah[mi][3], sb + off);
            }
#pragma unroll
            for (int nb = 0; nb < 2; nb++) {
                uint32_t off = ((bRow + nb * 16) * LDT + bCol + k0) * 2;
                ldm_x4(bh[nb][0], bh[nb][1], bh[nb][2], bh[nb][3], sb + TELEM * 2 + off);
                ldm_x4(bl[nb][0], bl[nb][1], bl[nb][2], bl[nb][3], sb + TELEM * 4 + off);
            }
#pragma unroll
            for (int mi = 0; mi < 4; mi++) {
#pragma unroll
                for (int nb = 0; nb < 2; nb++) {
                    mma_bf16(acc[mi][2*nb],   ah[mi], &bh[nb][0]);
                    mma_bf16(acc[mi][2*nb+1], ah[mi], &bh[nb][2]);
                    mma_bf16(acc[mi][2*nb],   ah[mi], &bl[nb][0]);
                    mma_bf16(acc[mi][2*nb+1], ah[mi], &bl[nb][2]);
                }
            }
        }
    }

#pragma unroll
    for (int mi = 0; mi < 4; mi++) {
        int row = wm * 64 + mi * 16 + (lane >> 2);
#pragma unroll
        for (int ni = 0; ni < 4; ni++) {
            int col = wn * 32 + ni * 8 + (lane & 3) * 2;
            float* p0 = Yrow + (size_t)row * Wn + col;
            float* p1 = p0 + 8 * Wn;
            float2 v0 = make_float2(acc[mi][ni][0], acc[mi][ni][1]);
            float2 v1 = make_float2(acc[mi][ni][2], acc[mi][ni][3]);
            if (ACC) {
                float2 o0 = *(const float2*)p0, o1 = *(const float2*)p1;
                v0.x += o0.x; v0.y += o0.y; v1.x += o1.x; v1.y += o1.y;
            }
            *(float2*)p0 = v0;
            *(float2*)p1 = v1;
        }
    }
}

// Q/K/V projection GEMM, pair-capable: grid (4, 2, 48*NPAIR); z = pair*48 + which*16 + bc
__global__ void __launch_bounds__(256) gemm_qkv(
        const __nv_bfloat16* __restrict__ WqH_,
        const __nv_bfloat16* __restrict__ WkH_,
        const __nv_bfloat16* __restrict__ WvH_,
        const __nv_bfloat16* __restrict__ th, const __nv_bfloat16* __restrict__ tl,
        const __nv_bfloat16* __restrict__ m0h, const __nv_bfloat16* __restrict__ m0l,
        const __nv_bfloat16* __restrict__ m1h, const __nv_bfloat16* __restrict__ m1l,
        float* __restrict__ dst6) {
    int z = blockIdx.z;
    int pair = z / 48, inner = z % 48;
    int which = inner >> 4, bc = inner & 15, c = bc & (Cn - 1);
    int tileM = blockIdx.y * 128, tileN = blockIdx.x * 128;
    size_t wofs = (size_t)pair * WOFF + ((size_t)c * Fn + tileM) * Fn;
    const __nv_bfloat16* Ah = (which == 0 ? WqH_ : which == 1 ? WkH_ : WvH_) + wofs;
    const __nv_bfloat16* Bh = (which == 0 ? th : (pair == 0 ? m0h : m1h)) + ((size_t)bc * Wn + tileN) * Fn;
    const __nv_bfloat16* Bl = (which == 0 ? tl : (pair == 0 ? m0l : m1l)) + ((size_t)bc * Wn + tileN) * Fn;
    float* Y = dst6 + ((size_t)pair * 3 + which) * NB + ((size_t)bc * Fn + tileM) * Wn + tileN;
    gemm_body<false>(Ah, Bh, Bl, Y);
}

// Wo GEMM over NP pairs: Y = Ybase + sum of pair GEMMs (Ybase may differ from Y)
template<int NP>
__global__ void __launch_bounds__(256) gemm_woN(
        const __nv_bfloat16* __restrict__ AhG,
        const __nv_bfloat16* __restrict__ BhG, const __nv_bfloat16* __restrict__ BlG,
        const float* __restrict__ Ybase, float* __restrict__ Y) {
    extern __shared__ __nv_bfloat16 sm[];
    __nv_bfloat16* sAh = sm;
    __nv_bfloat16* sBh = sm + TELEM;
    __nv_bfloat16* sBl = sm + 2 * TELEM;
    int bc = blockIdx.z, c = bc & (Cn - 1);
    int tileM = blockIdx.y * 128, tileN = blockIdx.x * 128;
    int tid = threadIdx.x, lane = tid & 31, wid = tid >> 5;
    int wm = wid >> 2, wn = wid & 3;
    float acc[4][4][4] = {};
    int lrow = tid >> 1;
    int lq   = (tid & 1) * 4;
    uint32_t sb = smem_u32(sm);
    int grp = lane >> 3, lr = lane & 7;
    int aRow = wm * 64 + (grp & 1) * 8 + lr;
    int aCol = (grp >> 1) * 8;
    int bRow = wn * 32 + (grp >> 1) * 8 + lr;
    int bCol = (grp & 1) * 8;

#pragma unroll
    for (int pp = 0; pp < NP; pp++) {
        const __nv_bfloat16* gAh = AhG + (size_t)pp * WOFF + ((size_t)c * Fn + tileM) * Fn;
        const __nv_bfloat16* gBh = BhG + (size_t)pp * AS + ((size_t)bc * Wn + tileN) * Fn;
        const __nv_bfloat16* gBl = BlG + (size_t)pp * AS + ((size_t)bc * Wn + tileN) * Fn;
        for (int kc = 0; kc < 4; kc++) {
            if (pp || kc) __syncthreads();
            const uint4* pa = (const uint4*)(gAh + (size_t)lrow * Fn + kc * KCn);
            const uint4* pc = (const uint4*)(gBh + (size_t)lrow * Fn + kc * KCn);
            const uint4* pd = (const uint4*)(gBl + (size_t)lrow * Fn + kc * KCn);
            uint4* qa = (uint4*)(sAh + lrow * LDT);
            uint4* qc = (uint4*)(sBh + lrow * LDT);
            uint4* qd = (uint4*)(sBl + lrow * LDT);
#pragma unroll
            for (int j = 0; j < 4; j++) {
                qa[lq + j] = pa[lq + j];
                qc[lq + j] = pc[lq + j];
                qd[lq + j] = pd[lq + j];
            }
            __syncthreads();
#pragma unroll
            for (int ks = 0; ks < 4; ks++) {
                int k0 = ks * 16;
                uint32_t ah[4][4], bh[2][4], bl[2][4];
#pragma unroll
                for (int mi = 0; mi < 4; mi++) {
                    uint32_t off = ((aRow + mi * 16) * LDT + aCol + k0) * 2;
                    ldm_x4(ah[mi][0], ah[mi][1], ah[mi][2], ah[mi][3], sb + off);
                }
#pragma unroll
                for (int nb = 0; nb < 2; nb++) {
                    uint32_t off = ((bRow + nb * 16) * LDT + bCol + k0) * 2;
                    ldm_x4(bh[nb][0], bh[nb][1], bh[nb][2], bh[nb][3], sb + TELEM * 2 + off);
                    ldm_x4(bl[nb][0], bl[nb][1], bl[nb][2], bl[nb][3], sb + TELEM * 4 + off);
                }
#pragma unroll
                for (int mi = 0; mi < 4; mi++) {
#pragma unroll
                    for (int nb = 0; nb < 2; nb++) {
                        mma_bf16(acc[mi][2*nb],   ah[mi], &bh[nb][0]);
                        mma_bf16(acc[mi][2*nb+1], ah[mi], &bh[nb][2]);
                        mma_bf16(acc[mi][2*nb],   ah[mi], &bl[nb][0]);
                        mma_bf16(acc[mi][2*nb+1], ah[mi], &bl[nb][2]);
                    }
                }
            }
        }
    }

    size_t base = ((size_t)bc * Fn + tileM) * Wn + tileN;
    const float* Brow = Ybase + base;
    float* Yrow = Y + base;
#pragma unroll
    for (int mi = 0; mi < 4; mi++) {
        int row = wm * 64 + mi * 16 + (lane >> 2);
#pragma unroll
        for (int ni = 0; ni < 4; ni++) {
            int col = wn * 32 + ni * 8 + (lane & 3) * 2;
            const float* b0 = Brow + (size_t)row * Wn + col;
            const float* b1 = b0 + 8 * Wn;
            float* p0 = Yrow + (size_t)row * Wn + col;
            float* p1 = p0 + 8 * Wn;
            float2 o0 = *(const float2*)b0, o1 = *(const float2*)b1;
            o0.x += acc[mi][ni][0]; o0.y += acc[mi][ni][1];
            o1.x += acc[mi][ni][2]; o1.y += acc[mi][ni][3];
            *(float2*)p0 = o0;
            *(float2*)p1 = o1;
        }
    }
}

// ======= conv3+bias (+RoPE) for Q/K/V, pair-capable: grid (4, 128, 6*NPAIR) =======
__global__ void __launch_bounds__(128) conv_qkv(const float* __restrict__ lin6,
                                                const float* __restrict__ KqG, const float* __restrict__ bqG,
                                                const float* __restrict__ KkG, const float* __restrict__ bkG,
                                                const float* __restrict__ KvG, const float* __restrict__ bvG,
                                                int i0,
                                                uint2* __restrict__ qI, uint2* __restrict__ kI,
                                                __nv_bfloat16* __restrict__ vbf) {
    __shared__ float sIn[Cn][2][132];
    __shared__ float ks[Cn * Cn * 3];
    int tid = threadIdx.x;
    int zz = blockIdx.z;
    int pair = zz / 6, r = zz % 6;
    int which = r >> 1, b = r & 1;
    int i = i0 + pair;
    const float* Lin = lin6 + ((size_t)pair * 3 + which) * NB;
    const float* Kc  = (which == 0 ? KqG : which == 1 ? KkG : KvG) + (size_t)i * Cn * Cn * 3;
    const float* bias = (which == 0 ? bqG : which == 1 ? bkG : bvG) + i * Cn;
    int w0 = blockIdx.x * 128;
    int p  = blockIdx.y;
    int f0 = 2 * p;
    for (int t = tid; t < Cn * 2 * 130; t += 128) {
        int ci = t / 260, rr = t % 260;
        int fi = rr / 130, wo = rr % 130;
        int gw = w0 + wo - 1;
        float v = (gw >= 0 && gw < Wn) ? Lin[((size_t)(b*Cn + ci) * Fn + f0 + fi) * Wn + gw] : 0.f;
        sIn[ci][fi][wo] = v;
    }
    for (int t = tid; t < Cn * Cn * 3; t += 128) ks[t] = Kc[t];
    __syncthreads();

    int w = w0 + tid;
    float cs = 1.f, sn = 0.f;
    if (which < 2) {
        int j = p & 15;
        float invf = exp10f(-0.25f * (float)j);
        sincosf((float)w * invf, &sn, &cs);
    }
    int h  = p >> 4;
    int jj = p & 15;
#pragma unroll
    for (int co = 0; co < Cn; co++) {
        float acc0 = bias[co], acc1 = acc0;
#pragma unroll
        for (int ci = 0; ci < Cn; ci++) {
            float k0 = ks[co*24 + ci*3], k1 = ks[co*24 + ci*3 + 1], k2 = ks[co*24 + ci*3 + 2];
            acc0 += k0 * sIn[ci][0][tid] + k1 * sIn[ci][0][tid+1] + k2 * sIn[ci][0][tid+2];
            acc1 += k0 * sIn[ci][1][tid] + k1 * sIn[ci][1][tid+1] + k2 * sIn[ci][1][tid+2];
        }
        size_t head = (size_t)(b*Cn + co) * Hn + h;
        size_t idx = (head * Wn + w) * 16 + jj;
        if (which < 2) {
            float o0 = acc0 * cs - acc1 * sn;
            float o1 = acc1 * cs + acc0 * sn;
            uint32_t lo, hi = pack_split(o0, o1, lo);
            (which == 0 ? qI : kI)[pair * QS + idx] = make_uint2(hi, lo);
        } else {
            ((__nv_bfloat162*)vbf)[pair * (VS/2) + idx] = __floats2bfloat162_rn(acc0, acc1);
        }
    }
}

// ========== tensor-core flash attention (2-term QK), register-prefetched staging ==========
__global__ void __launch_bounds__(256, 1) attn_mma(const uint2* __restrict__ Qi,
                                                   const uint2* __restrict__ Ki,
                                                   const __nv_bfloat16* __restrict__ Vg,
                                                   __nv_bfloat16* __restrict__ AttH,
                                                   __nv_bfloat16* __restrict__ AttL) {
    __shared__ __nv_bfloat16 Kh[64][40];
    __shared__ __nv_bfloat16 Kl[64][40];
    __shared__ __nv_bfloat16 Vs[64][40];
    int pair = blockIdx.x >> 8, rest = blockIdx.x & 255;
    int head = rest >> 1, half = rest & 1;
    int tid = threadIdx.x, lane = tid & 31, wid = tid >> 5;
    int qb = half * 256 + wid * 32;
    size_t hbase = (size_t)head * Wn;
    Qi += pair * QS; Ki += pair * QS; Vg += pair * VS;
    AttH += pair * AS; AttL += pair * AS;

    uint32_t qh[2][2][4];
#pragma unroll
    for (int mi = 0; mi < 2; mi++) {
        int r0 = qb + mi * 16 + (lane >> 2);
#pragma unroll
        for (int kk = 0; kk < 2; kk++) {
            int jp = kk * 8 + (lane & 3);
            qh[mi][kk][0] = Qi[(hbase + r0) * 16 + jp].x;
            qh[mi][kk][1] = Qi[(hbase + r0 + 8) * 16 + jp].x;
            qh[mi][kk][2] = Qi[(hbase + r0) * 16 + jp + 4].x;
            qh[mi][kk][3] = Qi[(hbase + r0 + 8) * 16 + jp + 4].x;
        }
    }
    float m_[4] = {-1e30f, -1e30f, -1e30f, -1e30f};
    float l_[4] = {0.f, 0.f, 0.f, 0.f};
    float o[2][4][4] = {};
    uint32_t sbK = smem_u32(Kh), sbKl = smem_u32(Kl), sbV = smem_u32(Vs);
    int grp = lane >> 3, lr = lane & 7;
    int rowV = tid >> 2, qV = tid & 3;

    uint2 kreg[4];
    uint4 vreg;
#pragma unroll
    for (int it = 0; it < 4; it++) {
        int idx = tid + it * 256;
        kreg[it] = Ki[(hbase + (idx >> 4)) * 16 + (idx & 15)];
    }
    vreg = ((const uint4*)(Vg + (hbase + rowV) * HDn))[qV];

    for (int kt = 0; kt < 8; kt++) {
#pragma unroll
        for (int it = 0; it < 4; it++) {
            int idx = tid + it * 256;
            int row = idx >> 4, j = idx & 15;
            ((uint32_t*)&Kh[row][0])[j] = kreg[it].x;
            ((uint32_t*)&Kl[row][0])[j] = kreg[it].y;
        }
        *((uint4*)&Vs[rowV][qV * 8]) = vreg;
        __syncthreads();
        if (kt < 7) {
            int kb = (kt + 1) * 64;
#pragma unroll
            for (int it = 0; it < 4; it++) {
                int idx = tid + it * 256;
                kreg[it] = Ki[(hbase + kb + (idx >> 4)) * 16 + (idx & 15)];
            }
            vreg = ((const uint4*)(Vg + (hbase + kb + rowV) * HDn))[qV];
        }

        float s[2][8][4] = {};
#pragma unroll
        for (int kk = 0; kk < 2; kk++) {
#pragma unroll
            for (int nb = 0; nb < 4; nb++) {
                uint32_t kh4[4], kl4[4];
                uint32_t off = ((nb * 16 + (grp >> 1) * 8 + lr) * 40 + (grp & 1) * 8 + kk * 16) * 2;
                ldm_x4(kh4[0], kh4[1], kh4[2], kh4[3], sbK + off);
                ldm_x4(kl4[0], kl4[1], kl4[2], kl4[3], sbKl + off);
#pragma unroll
                for (int mi = 0; mi < 2; mi++) {
                    mma_bf16(s[mi][2*nb],   qh[mi][kk], &kh4[0]);
                    mma_bf16(s[mi][2*nb+1], qh[mi][kk], &kh4[2]);
                    mma_bf16(s[mi][2*nb],   qh[mi][kk], &kl4[0]);
                    mma_bf16(s[mi][2*nb+1], qh[mi][kk], &kl4[2]);
                }
            }
        }

        uint32_t pa[2][4][4];
#pragma unroll
        for (int mi = 0; mi < 2; mi++) {
            float mx0 = -1e30f, mx1 = -1e30f;
#pragma unroll
            for (int n = 0; n < 8; n++) {
#pragma unroll
                for (int q = 0; q < 4; q++) s[mi][n][q] *= 0.0625f;
                mx0 = fmaxf(mx0, fmaxf(s[mi][n][0], s[mi][n][1]));
                mx1 = fmaxf(mx1, fmaxf(s[mi][n][2], s[mi][n][3]));
            }
            mx0 = fmaxf(mx0, __shfl_xor_sync(0xffffffffu, mx0, 1));
            mx0 = fmaxf(mx0, __shfl_xor_sync(0xffffffffu, mx0, 2));
            mx1 = fmaxf(mx1, __shfl_xor_sync(0xffffffffu, mx1, 1));
            mx1 = fmaxf(mx1, __shfl_xor_sync(0xffffffffu, mx1, 2));
            int si = mi * 2;
            float mn0 = fmaxf(m_[si], mx0), mn1 = fmaxf(m_[si+1], mx1);
            float c0 = __expf(m_[si] - mn0), c1 = __expf(m_[si+1] - mn1);
            m_[si] = mn0; m_[si+1] = mn1;
            float ls0 = 0.f, ls1 = 0.f;
#pragma unroll
            for (int n = 0; n < 8; n++) {
                float p0 = __expf(s[mi][n][0] - mn0);
                float p1 = __expf(s[mi][n][1] - mn0);
                float p2 = __expf(s[mi][n][2] - mn1);
                float p3 = __expf(s[mi][n][3] - mn1);
                ls0 += p0 + p1; ls1 += p2 + p3;
                s[mi][n][0] = p0; s[mi][n][1] = p1; s[mi][n][2] = p2; s[mi][n][3] = p3;
            }
            ls0 += __shfl_xor_sync(0xffffffffu, ls0, 1);
            ls0 += __shfl_xor_sync(0xffffffffu, ls0, 2);
            ls1 += __shfl_xor_sync(0xffffffffu, ls1, 1);
            ls1 += __shfl_xor_sync(0xffffffffu, ls1, 2);
            l_[si]   = l_[si]   * c0 + ls0;
            l_[si+1] = l_[si+1] * c1 + ls1;
#pragma unroll
            for (int dn = 0; dn < 4; dn++) {
                o[mi][dn][0] *= c0; o[mi][dn][1] *= c0;
                o[mi][dn][2] *= c1; o[mi][dn][3] *= c1;
            }
#pragma unroll
            for (int t = 0; t < 4; t++) {
                pa[mi][t][0] = packbf(s[mi][2*t][0],   s[mi][2*t][1]);
                pa[mi][t][1] = packbf(s[mi][2*t][2],   s[mi][2*t][3]);
                pa[mi][t][2] = packbf(s[mi][2*t+1][0], s[mi][2*t+1][1]);
                pa[mi][t][3] = packbf(s[mi][2*t+1][2], s[mi][2*t+1][3]);
            }
        }

#pragma unroll
        for (int dn = 0; dn < 4; dn++) {
            uint32_t vb[4][2];
#pragma unroll
            for (int t = 0; t < 4; t++) {
                uint32_t off = ((t * 16 + (lane & 15)) * 40 + dn * 8) * 2;
                ldm_x2_trans(vb[t][0], vb[t][1], sbV + off);
            }
#pragma unroll
            for (int mi = 0; mi < 2; mi++)
#pragma unroll
                for (int t = 0; t < 4; t++)
                    mma_bf16(o[mi][dn], pa[mi][t], vb[t]);
        }
        __syncthreads();
    }

    int bc = head >> 3, hh = head & 7;
#pragma unroll
    for (int mi = 0; mi < 2; mi++) {
        int r0 = qb + mi * 16 + (lane >> 2);
        float i0 = 1.0f / l_[mi*2], i1 = 1.0f / l_[mi*2 + 1];
#pragma unroll
        for (int dn = 0; dn < 4; dn++) {
            int d0 = dn * 8 + (lane & 3) * 2;
            size_t a0 = ((size_t)bc * Wn + r0) * Fn + hh * HDn + d0;
            size_t a1 = ((size_t)bc * Wn + r0 + 8) * Fn + hh * HDn + d0;
            uint32_t lo0, hi0 = pack_split(o[mi][dn][0] * i0, o[mi][dn][1] * i0, lo0);
            uint32_t lo1, hi1 = pack_split(o[mi][dn][2] * i1, o[mi][dn][3] * i1, lo1);
            *(uint32_t*)(AttH + a0) = hi0;
            *(uint32_t*)(AttL + a0) = lo0;
            *(uint32_t*)(AttH + a1) = hi1;
            *(uint32_t*)(AttL + a1) = lo1;
        }
    }
}

// ============ fused LN + depthwise convs (k11 sq_relu + k7) — proven ============
__global__ void __launch_bounds__(256) lnconv_ab(const float* __restrict__ X,
                                                 const float* __restrict__ gam,
                                                 const float* __restrict__ bet,
                                                 const float* __restrict__ k11, const float* __restrict__ b11,
                                                 const float* __restrict__ k7,  const float* __restrict__ b7,
                                                 float* __restrict__ Yo) {
    extern __shared__ float sZ[];
    __shared__ float gs[Fn], bs[Fn], ps[4][64], ps2[4][64], mb[64], ib[64];
    int tid = threadIdx.x, w = tid & 63, fg = tid >> 6;
    int bc = blockIdx.y, c = bc & (Cn - 1);
    int w0 = blockIdx.x * 64;
    const float* xp = X + (size_t)bc * Fn * Wn + w0;
    for (int i = tid; i < Fn * 64; i += 256)
        sZ[i] = xp[(size_t)(i >> 6) * Wn + (i & 63)];
    for (int i = tid; i < Fn; i += 256) { gs[i] = gam[c * Fn + i]; bs[i] = bet[c * Fn + i]; }
    __syncthreads();
    float s = 0.f, s2 = 0.f;
#pragma unroll 4
    for (int f = fg * 64; f < fg * 64 + 64; f++) {
        float v = sZ[f * 64 + w];
        s += v; s2 += v * v;
    }
    ps[fg][w] = s; ps2[fg][w] = s2;
    __syncthreads();
    if (fg == 0) {
        float S  = ps[0][w]  + ps[1][w]  + ps[2][w]  + ps[3][w];
        float S2 = ps2[0][w] + ps2[1][w] + ps2[2][w] + ps2[3][w];
        float m = S * (1.0f / Fn);
        mb[w] = m;
        ib[w] = rsqrtf(S2 * (1.0f / Fn) - m * m + 1e-5f);
    }
    __syncthreads();
    float m = mb[w], inv = ib[w];
#pragma unroll 4
    for (int f = fg * 64; f < fg * 64 + 64; f++)
        sZ[f * 64 + w] = (sZ[f * 64 + w] - m) * inv * gs[f] + bs[f];
    __syncthreads();
    float wk11[11], wk7[7];
#pragma unroll
    for (int t = 0; t < 11; t++) wk11[t] = k11[c * 11 + t];
#pragma unroll
    for (int t = 0; t < 7; t++)  wk7[t]  = k7[c * 7 + t];
    float bb11 = b11[c], bb7 = b7[c];
    float* yo = Yo + (size_t)bc * Fn * Wn + w0 + w;
    for (int f = fg * 64; f < fg * 64 + 64; f++) {
        float a = bb11;
#pragma unroll
        for (int t = 0; t < 11; t++) {
            int ff = f - 5 + t;
            if (ff >= 0 && ff < Fn) a += sZ[ff * 64 + w] * wk11[t];
        }
        a = fmaxf(a, 0.f); a = a * a;
        float bo = bb7;
#pragma unroll
        for (int t = 0; t < 7; t++) {
            int ff = f - 3 + t;
            if (ff >= 0 && ff < Fn) bo += sZ[ff * 64 + w] * wk7[t];
        }
        yo[(size_t)f * Wn] = a + bo;
    }
}

// ============ fused LN + k7 conv + residual add into H — proven ============
__global__ void __launch_bounds__(256) lnconv2_add(const float* __restrict__ X,
                                                   const float* __restrict__ gam,
                                                   const float* __restrict__ bet,
                                                   const float* __restrict__ k7, const float* __restrict__ b7,
                                                   float* __restrict__ Hb) {
    extern __shared__ float sZ[];
    __shared__ float gs[Fn], bs[Fn], ps[4][64], ps2[4][64], mb[64], ib[64];
    int tid = threadIdx.x, w = tid & 63, fg = tid >> 6;
    int bc = blockIdx.y, c = bc & (Cn - 1);
    int w0 = blockIdx.x * 64;
    const float* xp = X + (size_t)bc * Fn * Wn + w0;
    for (int i = tid; i < Fn * 64; i += 256)
        sZ[i] = xp[(size_t)(i >> 6) * Wn + (i & 63)];
    for (int i = tid; i < Fn; i += 256) { gs[i] = gam[c * Fn + i]; bs[i] = bet[c * Fn + i]; }
    __syncthreads();
    float s = 0.f, s2 = 0.f;
#pragma unroll 4
    for (int f = fg * 64; f < fg * 64 + 64; f++) {
        float v = sZ[f * 64 + w];
        s += v; s2 += v * v;
    }
    ps[fg][w] = s; ps2[fg][w] = s2;
    __syncthreads();
    if (fg == 0) {
        float S  = ps[0][w]  + ps[1][w]  + ps[2][w]  + ps[3][w];
        float S2 = ps2[0][w] + ps2[1][w] + ps2[2][w] + ps2[3][w];
        float m = S * (1.0f / Fn);
        mb[w] = m;
        ib[w] = rsqrtf(S2 * (1.0f / Fn) - m * m + 1e-5f);
    }
    __syncthreads();
    float m = mb[w], inv = ib[w];
#pragma unroll 4
    for (int f = fg * 64; f < fg * 64 + 64; f++)
        sZ[f * 64 + w] = (sZ[f * 64 + w] - m) * inv * gs[f] + bs[f];
    __syncthreads();
    float wk7[7];
#pragma unroll
    for (int t = 0; t < 7; t++) wk7[t] = k7[c * 7 + t];
    float bb7 = b7[c];
    float* hb = Hb + (size_t)bc * Fn * Wn + w0 + w;
    for (int f = fg * 64; f < fg * 64 + 64; f++) {
        float v = bb7;
#pragma unroll
        for (int t = 0; t < 7; t++) {
            int ff = f - 3 + t;
            if (ff >= 0 && ff < Fn) v += sZ[ff * 64 + w] * wk7[t];
        }
        hb[(size_t)f * Wn] += v;
    }
}

// ============ fused LN + FFN first layer ============
__global__ void __launch_bounds__(256) ln_ffn3(const float* __restrict__ X,
                                               const float* __restrict__ gam,
                                               const float* __restrict__ bet,
                                               const float* __restrict__ w3,
                                               float* __restrict__ T) {
    extern __shared__ float sZ[];
    __shared__ float ws[En * Fn], gs[Fn], bs[Fn];
    __shared__ float ps[4][64], ps2[4][64], mb[64], ib[64];
    __shared__ float pacc[4][En][64];
    int tid = threadIdx.x, w = tid & 63, fg = tid >> 6;
    int bc = blockIdx.y, c = bc & (Cn - 1);
    int w0 = blockIdx.x * 64;
    const float* xp = X + (size_t)bc * Fn * Wn + w0;
    for (int i = tid; i < Fn * 64; i += 256)
        sZ[i] = xp[(size_t)(i >> 6) * Wn + (i & 63)];
    for (int i = tid; i < En * Fn; i += 256) ws[i] = w3[c * En * Fn + i];
    for (int i = tid; i < Fn; i += 256) { gs[i] = gam[c * Fn + i]; bs[i] = bet[c * Fn + i]; }
    __syncthreads();
    float s = 0.f, s2 = 0.f;
#pragma unroll 4
    for (int f = fg * 64; f < fg * 64 + 64; f++) {
        float v = sZ[f * 64 + w];
        s += v; s2 += v * v;
    }
    ps[fg][w] = s; ps2[fg][w] = s2;
    __syncthreads();
    if (fg == 0) {
        float S  = ps[0][w]  + ps[1][w]  + ps[2][w]  + ps[3][w];
        float S2 = ps2[0][w] + ps2[1][w] + ps2[2][w] + ps2[3][w];
        float m = S * (1.0f / Fn);
        mb[w] = m;
        ib[w] = rsqrtf(S2 * (1.0f / Fn) - m * m + 1e-5f);
    }
    __syncthreads();
    float m = mb[w], inv = ib[w];
    float acc[En] = {};
#pragma unroll 4
    for (int f = fg * 64; f < fg * 64 + 64; f++) {
        float zn = (sZ[f * 64 + w] - m) * inv * gs[f] + bs[f];
#pragma unroll
        for (int e = 0; e < En; e++) acc[e] += zn * ws[e * Fn + f];
    }
#pragma unroll
    for (int e = 0; e < En; e++) pacc[fg][e][w] = acc[e];
    __syncthreads();
    if (fg == 0) {
        float* tp = T + (size_t)bc * En * Wn + w0 + w;
#pragma unroll
        for (int e = 0; e < En; e++) {
            float v = pacc[0][e][w] + pacc[1][e][w] + pacc[2][e][w] + pacc[3][e][w];
            v = fmaxf(v, 0.f);
            tp[(size_t)e * Wn] = v * v;
        }
    }
}

// ============ fused FFN second layer + residual + concat output ============
__global__ void ffn4_write(const float* __restrict__ T, const float* __restrict__ w4,
                           const float* __restrict__ Hb, const float* __restrict__ X,
                           float* __restrict__ O) {
    int idx = blockIdx.x * 256 + threadIdx.x;
    int w  = idx & (Wn - 1);
    int f  = (idx >> 9) & (Fn - 1);
    int bc = idx >> 17;
    int c  = bc & (Cn - 1);
    const float* tp = T + (size_t)bc * En * Wn + w;
    const float* wp = w4 + ((size_t)c * Fn + f) * En;
    float v = tp[0] * wp[0] + tp[Wn] * wp[1] + tp[2 * Wn] * wp[2] + tp[3 * Wn] * wp[3];
    float h = Hb[idx] + v;
    int b = idx / (Cn * Fn * Wn);
    int r = idx - b * (Cn * Fn * Wn);
    O[(size_t)b * 2 * Cn * Fn * Wn + r] = X[idx];
    O[(size_t)b * 2 * Cn * Fn * Wn + Cn * Fn * Wn + r] = h;
}

// =====================================================================================

extern "C" void kernel_launch(void* const* d_in, const int* in_sizes, int n_in,
                              void* d_out, int out_size) {
    const float* x     = (const float*)d_in[0];
    const float* skip  = (const float*)d_in[1];
    const float* Wq    = (const float*)d_in[2];
    const float* Kq    = (const float*)d_in[3];
    const float* bq    = (const float*)d_in[4];
    const float* Wk    = (const float*)d_in[5];
    const float* Kk    = (const float*)d_in[6];
    const float* bk    = (const float*)d_in[7];
    const float* Wv    = (const float*)d_in[8];
    const float* Kv    = (const float*)d_in[9];
    const float* bv    = (const float*)d_in[10];
    const float* Wo    = (const float*)d_in[11];
    const float* ng    = (const float*)d_in[12];
    const float* nbet  = (const float*)d_in[13];
    const float* c1a_w = (const float*)d_in[14];
    const float* c1a_b = (const float*)d_in[15];
    const float* c1b_w = (const float*)d_in[16];
    const float* c1b_b = (const float*)d_in[17];
    const float* c2_w  = (const float*)d_in[18];
    const float* c2_b  = (const float*)d_in[19];
    const float* w3    = (const float*)d_in[20];
    const float* w4    = (const float*)d_in[21];
    float* out = (float*)d_out;

    float *hB, *lin6B, *t1B, *ffnB;
    cudaGetSymbolAddress((void**)&hB,    g_h);
    cudaGetSymbolAddress((void**)&lin6B, g_lin6);
    cudaGetSymbolAddress((void**)&t1B,   g_t1);
    cudaGetSymbolAddress((void**)&ffnB,  g_ffn);
    uint2 *qI, *kI;
    __nv_bfloat16 *vBf;
    cudaGetSymbolAddress((void**)&qI,  g_qI);
    cudaGetSymbolAddress((void**)&kI,  g_kI);
    cudaGetSymbolAddress((void**)&vBf, g_vbf);
    __nv_bfloat16 *zTh, *zTl, *skTh, *skTl, *atTh, *atTl;
    __nv_bfloat16 *WqH, *WkH, *WvH, *WoH;
    cudaGetSymbolAddress((void**)&zTh,  g_zTh);  cudaGetSymbolAddress((void**)&zTl,  g_zTl);
    cudaGetSymbolAddress((void**)&skTh, g_skTh); cudaGetSymbolAddress((void**)&skTl, g_skTl);
    cudaGetSymbolAddress((void**)&atTh, g_atTh); cudaGetSymbolAddress((void**)&atTl, g_atTl);
    cudaGetSymbolAddress((void**)&WqH, g_WqH);
    cudaGetSymbolAddress((void**)&WkH, g_WkH);
    cudaGetSymbolAddress((void**)&WvH, g_WvH);
    cudaGetSymbolAddress((void**)&WoH, g_WoH);

    const int TSM = Fn * 64 * 4;
    cudaFuncSetAttribute(gemm_qkv,    cudaFuncAttributeMaxDynamicSharedMemorySize, GSM);
    cudaFuncSetAttribute(gemm_woN<1>, cudaFuncAttributeMaxDynamicSharedMemorySize, GSM);
    cudaFuncSetAttribute(gemm_woN<2>, cudaFuncAttributeMaxDynamicSharedMemorySize, GSM);
    cudaFuncSetAttribute(lnconv_ab,   cudaFuncAttributeMaxDynamicSharedMemorySize, TSM);
    cudaFuncSetAttribute(lnconv2_add, cudaFuncAttributeMaxDynamicSharedMemorySize, TSM);
    cudaFuncSetAttribute(ln_ffn3,     cudaFuncAttributeMaxDynamicSharedMemorySize, TSM);

    const int nElemBlocks = NB / 256;
    const int wBlocks = (4 * WOFF) / 1024;
    const dim3 gLN(Wn / 16, Bn * Cn);
    const dim3 gT64(Wn / 64, Bn * Cn);

    wsplit_all<<<dim3(wBlocks, 4), 256>>>(Wq, Wk, Wv, Wo, WqH, WkH, WvH, WoH);
    tsplit_kernel<<<dim3(Wn/32, Fn/32, Bn*Cn), dim3(32, 8)>>>(skip, skTh, skTl);

    auto run_ln_t = [&](const float* X, int gi) {
        ln_t_v4<<<gLN, 256>>>(X, ng + gi * Cn * Fn, nbet + gi * Cn * Fn, zTh, zTl);
    };

    // --- att0 + att1 as one batched pair; h = x + both (seeded inside Wo GEMM) ---
    run_ln_t(x, 0);
    gemm_qkv<<<dim3(4, 2, 96), 256, GSM>>>(WqH, WkH, WvH,
                                           zTh, zTl, zTh, zTl, skTh, skTl, lin6B);
    conv_qkv<<<dim3(4, 128, 12), 128>>>(lin6B, Kq, bq, Kk, bk, Kv, bv, 0, qI, kI, vBf);
    attn_mma<<<512, 256>>>(qI, kI, vBf, atTh, atTl);
    gemm_woN<2><<<dim3(4, 2, 16), 256, GSM>>>(WoH, atTh, atTl, x, hB);

    // conv block (proven two-kernel form)
    lnconv_ab<<<gT64, 256, TSM>>>(hB, ng + 1 * Cn * Fn, nbet + 1 * Cn * Fn,
                                  c1a_w, c1a_b, c1b_w, c1b_b, t1B);
    lnconv2_add<<<gT64, 256, TSM>>>(t1B, ng + 2 * Cn * Fn, nbet + 2 * Cn * Fn,
                                    c2_w, c2_b, hB);

    // h += att2(LN3(h), same)
    run_ln_t(hB, 3);
    gemm_qkv<<<dim3(4, 2, 48), 256, GSM>>>(WqH + 2*(size_t)WOFF, WkH + 2*(size_t)WOFF,
                                           WvH + 2*(size_t)WOFF,
                                           zTh, zTl, zTh, zTl, zTh, zTl, lin6B);
    conv_qkv<<<dim3(4, 128, 6), 128>>>(lin6B, Kq, bq, Kk, bk, Kv, bv, 2, qI, kI, vBf);
    attn_mma<<<256, 256>>>(qI, kI, vBf, atTh, atTl);
    gemm_woN<1><<<dim3(4, 2, 16), 256, GSM>>>(WoH + 2*(size_t)WOFF, atTh, atTl, hB, hB);

    // h += att3(LN4(h), skip)
    run_ln_t(hB, 4);
    gemm_qkv<<<dim3(4, 2, 48), 256, GSM>>>(WqH + 3*(size_t)WOFF, WkH + 3*(size_t)WOFF,
                                           WvH + 3*(size_t)WOFF,
                                           zTh, zTl, skTh, skTl, skTh, skTl, lin6B);
    conv_qkv<<<dim3(4, 128, 6), 128>>>(lin6B, Kq, bq, Kk, bk, Kv, bv, 3, qI, kI, vBf);
    attn_mma<<<256, 256>>>(qI, kI, vBf, atTh, atTl);
    gemm_woN<1><<<dim3(4, 2, 16), 256, GSM>>>(WoH + 3*(size_t)WOFF, atTh, atTl, hB, hB);

    // FFN (LN5 fused into ffn3; ffn4 fused with concat output)
    ln_ffn3<<<gT64, 256, TSM>>>(hB, ng + 5 * Cn * Fn, nbet + 5 * Cn * Fn, w3, ffnB);
    ffn4_write<<<nElemBlocks, 256>>>(ffnB, w4, hB, x, out);
}